// round 8
// baseline (speedup 1.0000x reference)
#include <cuda_runtime.h>
#include <cuda_bf16.h>
#include <cstdint>
#include <math.h>

#define BB 2
#define SS 1024
#define DD 768
#define HH 12
#define DK 64
#define FF 3072
#define LL 4
#define VV 32000
#define MTOK (BB*SS)   /* 2048 */

typedef __nv_bfloat16 bf16;

// ---------------- scratch ----------------------------------------------------
__device__ float g_h  [MTOK*DD];
__device__ float g_p  [3*MTOK*DD];        // split-K partials
__device__ bf16 g_tok_hi[VV*DD],    g_tok_lo[VV*DD];
__device__ bf16 g_wq_hi [LL*DD*DD], g_wq_lo [LL*DD*DD];
__device__ bf16 g_wk_hi [LL*DD*DD], g_wk_lo [LL*DD*DD];
__device__ bf16 g_wv_hi [LL*DD*DD], g_wv_lo [LL*DD*DD];
__device__ bf16 g_wo_hi [LL*DD*DD], g_wo_lo [LL*DD*DD];
__device__ bf16 g_w1_hi [LL*FF*DD], g_w1_lo [LL*FF*DD];
__device__ bf16 g_w2_hi [LL*DD*FF], g_w2_lo [LL*DD*FF];
__device__ bf16 g_a_hi  [MTOK*DD],  g_a_lo  [MTOK*DD];
__device__ bf16 g_f_hi  [MTOK*FF],  g_f_lo  [MTOK*FF];
__device__ bf16 g_qh[MTOK*DD], g_ql[MTOK*DD];
__device__ bf16 g_kh[MTOK*DD], g_kl[MTOK*DD];
__device__ bf16 g_vh[MTOK*DD], g_vl[MTOK*DD];

// ---------------- helpers ----------------------------------------------------
__device__ __forceinline__ uint32_t smem_u32(const void* p) {
    uint32_t a;
    asm("{ .reg .u64 t; cvta.to.shared.u64 t, %1; cvt.u32.u64 %0, t; }" : "=r"(a) : "l"(p));
    return a;
}
__device__ __forceinline__ void cpasync16(uint32_t saddr, const void* gaddr) {
    asm volatile("cp.async.cg.shared.global [%0], [%1], 16;" :: "r"(saddr), "l"(gaddr));
}
#define CP_COMMIT() asm volatile("cp.async.commit_group;" ::: "memory")
#define CP_WAIT(N)  asm volatile("cp.async.wait_group %0;" :: "n"(N) : "memory")

__device__ __forceinline__ void ldsm4(uint32_t* r, uint32_t addr) {
    asm volatile("ldmatrix.sync.aligned.m8n8.x4.shared.b16 {%0,%1,%2,%3}, [%4];"
        : "=r"(r[0]), "=r"(r[1]), "=r"(r[2]), "=r"(r[3]) : "r"(addr));
}
__device__ __forceinline__ void ldsm4t(uint32_t* r, uint32_t addr) {
    asm volatile("ldmatrix.sync.aligned.m8n8.x4.trans.shared.b16 {%0,%1,%2,%3}, [%4];"
        : "=r"(r[0]), "=r"(r[1]), "=r"(r[2]), "=r"(r[3]) : "r"(addr));
}
__device__ __forceinline__ void mma16816(float* c, const uint32_t* a, const uint32_t* b) {
    asm volatile(
        "mma.sync.aligned.m16n8k16.row.col.f32.bf16.bf16.f32 "
        "{%0,%1,%2,%3}, {%4,%5,%6,%7}, {%8,%9}, {%0,%1,%2,%3};"
        : "+f"(c[0]), "+f"(c[1]), "+f"(c[2]), "+f"(c[3])
        : "r"(a[0]), "r"(a[1]), "r"(a[2]), "r"(a[3]), "r"(b[0]), "r"(b[1]));
}
__device__ __forceinline__ void split1(float v, bf16& h, bf16& l) {
    h = __float2bfloat16(v);
    l = __float2bfloat16(v - __bfloat162float(h));
}
__device__ __forceinline__ uint32_t packbf(float v0, float v1) {
    __nv_bfloat162 p(__float2bfloat16(v0), __float2bfloat16(v1));
    return *(uint32_t*)&p;
}

// ---------------- embed (with inline int64/int32 token detection) ------------
__global__ void embedcvt_kernel(const long long* __restrict__ x64,
                                const float* __restrict__ tok,
                                const float* __restrict__ pos) {
    __shared__ int is64s;
    if (threadIdx.x == 0) {
        int ok = 1;
        for (int i = 0; i < 16; i++) { long long t = x64[i]; if (t < 0 || t >= VV) ok = 0; }
        is64s = ok;
    }
    __syncthreads();
    int idx = blockIdx.x * blockDim.x + threadIdx.x;
    if (idx < MTOK * DD) {
        int d = idx % DD, t = idx / DD, s = t % SS;
        int tokid = is64s ? (int)x64[t] : ((const int*)x64)[t];
        g_h[idx] = tok[tokid * DD + d] + pos[s * DD + d];
    }
}

// ---------------- warp-per-row layernorm -> bf16 hi/lo -----------------------
// block 256 = 8 warps, warp handles one row of 768; grid = MTOK/8
__global__ __launch_bounds__(256)
void ln_kernel(const float* __restrict__ in, const float* __restrict__ g,
               const float* __restrict__ b,
               bf16* __restrict__ ohi, bf16* __restrict__ olo) {
    const int wid = threadIdx.x >> 5, lane = threadIdx.x & 31;
    const int row = blockIdx.x * 8 + wid;
    const float4* xr = (const float4*)(in + (size_t)row * DD);
    float4 v[6];
    float s1 = 0.f, s2 = 0.f;
#pragma unroll
    for (int i = 0; i < 6; i++) {
        v[i] = xr[lane + 32 * i];
        s1 += v[i].x + v[i].y + v[i].z + v[i].w;
        s2 += v[i].x*v[i].x + v[i].y*v[i].y + v[i].z*v[i].z + v[i].w*v[i].w;
    }
#pragma unroll
    for (int o = 16; o > 0; o >>= 1) {
        s1 += __shfl_xor_sync(0xffffffffu, s1, o);
        s2 += __shfl_xor_sync(0xffffffffu, s2, o);
    }
    float mu = s1 * (1.0f / DD);
    float inv = rsqrtf(s2 * (1.0f / DD) - mu * mu + 1e-5f);
    const float4* gg = (const float4*)g;
    const float4* bb = (const float4*)b;
#pragma unroll
    for (int i = 0; i < 6; i++) {
        int e4 = lane + 32 * i;
        float4 gv = gg[e4], bv = bb[e4];
        float o0 = (v[i].x - mu) * inv * gv.x + bv.x;
        float o1 = (v[i].y - mu) * inv * gv.y + bv.y;
        float o2 = (v[i].z - mu) * inv * gv.z + bv.z;
        float o3 = (v[i].w - mu) * inv * gv.w + bv.w;
        bf16 h0,l0,h1,l1,h2,l2,h3,l3;
        split1(o0,h0,l0); split1(o1,h1,l1); split1(o2,h2,l2); split1(o3,h3,l3);
        size_t base = (size_t)row * DD + e4 * 4;
        *(__nv_bfloat162*)&ohi[base]     = __nv_bfloat162(h0, h1);
        *(__nv_bfloat162*)&ohi[base + 2] = __nv_bfloat162(h2, h3);
        *(__nv_bfloat162*)&olo[base]     = __nv_bfloat162(l0, l1);
        *(__nv_bfloat162*)&olo[base + 2] = __nv_bfloat162(l2, l3);
    }
}

// fused: h += P0+P1+P2 (written back), then LN(h) -> bf16 hi/lo
__global__ __launch_bounds__(256)
void ln_res_kernel(float* __restrict__ h, const float* __restrict__ p,
                   const float* __restrict__ g, const float* __restrict__ b,
                   bf16* __restrict__ ohi, bf16* __restrict__ olo) {
    const int wid = threadIdx.x >> 5, lane = threadIdx.x & 31;
    const int row = blockIdx.x * 8 + wid;
    float4* hr = (float4*)(h + (size_t)row * DD);
    const float4* p0 = (const float4*)(p + (size_t)row * DD);
    const float4* p1 = (const float4*)(p + (size_t)MTOK * DD + (size_t)row * DD);
    const float4* p2 = (const float4*)(p + 2 * (size_t)MTOK * DD + (size_t)row * DD);
    float4 v[6];
    float s1 = 0.f, s2 = 0.f;
#pragma unroll
    for (int i = 0; i < 6; i++) {
        int e4 = lane + 32 * i;
        float4 hv = hr[e4], a0 = p0[e4], a1 = p1[e4], a2 = p2[e4];
        hv.x += a0.x + a1.x + a2.x;
        hv.y += a0.y + a1.y + a2.y;
        hv.z += a0.z + a1.z + a2.z;
        hv.w += a0.w + a1.w + a2.w;
        hr[e4] = hv;
        v[i] = hv;
        s1 += hv.x + hv.y + hv.z + hv.w;
        s2 += hv.x*hv.x + hv.y*hv.y + hv.z*hv.z + hv.w*hv.w;
    }
#pragma unroll
    for (int o = 16; o > 0; o >>= 1) {
        s1 += __shfl_xor_sync(0xffffffffu, s1, o);
        s2 += __shfl_xor_sync(0xffffffffu, s2, o);
    }
    float mu = s1 * (1.0f / DD);
    float inv = rsqrtf(s2 * (1.0f / DD) - mu * mu + 1e-5f);
    const float4* gg = (const float4*)g;
    const float4* bb = (const float4*)b;
#pragma unroll
    for (int i = 0; i < 6; i++) {
        int e4 = lane + 32 * i;
        float4 gv = gg[e4], bv = bb[e4];
        float o0 = (v[i].x - mu) * inv * gv.x + bv.x;
        float o1 = (v[i].y - mu) * inv * gv.y + bv.y;
        float o2 = (v[i].z - mu) * inv * gv.z + bv.z;
        float o3 = (v[i].w - mu) * inv * gv.w + bv.w;
        bf16 h0,l0,h1,l1,h2,l2,h3,l3;
        split1(o0,h0,l0); split1(o1,h1,l1); split1(o2,h2,l2); split1(o3,h3,l3);
        size_t base = (size_t)row * DD + e4 * 4;
        *(__nv_bfloat162*)&ohi[base]     = __nv_bfloat162(h0, h1);
        *(__nv_bfloat162*)&ohi[base + 2] = __nv_bfloat162(h2, h3);
        *(__nv_bfloat162*)&olo[base]     = __nv_bfloat162(l0, l1);
        *(__nv_bfloat162*)&olo[base + 2] = __nv_bfloat162(l2, l3);
    }
}

// ---------------- fp32 -> bf16 hi/lo splits ----------------------------------
__device__ __forceinline__ void split4_body(const float4* x, __nv_bfloat162* hi,
                                            __nv_bfloat162* lo, int i) {
    float4 v = x[i];
    bf16 hx, lx, hy, ly, hz, lz, hw, lw;
    split1(v.x, hx, lx); split1(v.y, hy, ly);
    split1(v.z, hz, lz); split1(v.w, hw, lw);
    hi[2*i]   = __nv_bfloat162(hx, hy);
    hi[2*i+1] = __nv_bfloat162(hz, hw);
    lo[2*i]   = __nv_bfloat162(lx, ly);
    lo[2*i+1] = __nv_bfloat162(lz, lw);
}

__global__ void split_kernel(const float4* __restrict__ x,
                             __nv_bfloat162* __restrict__ hi,
                             __nv_bfloat162* __restrict__ lo, int n4) {
    int i = blockIdx.x * blockDim.x + threadIdx.x;
    if (i < n4) split4_body(x, hi, lo, i);
}

__global__ void split_w_kernel(
        const float4* s0, __nv_bfloat162* h0, __nv_bfloat162* l0, int n0,
        const float4* s1, __nv_bfloat162* h1, __nv_bfloat162* l1, int n1,
        const float4* s2, __nv_bfloat162* h2, __nv_bfloat162* l2, int n2,
        const float4* s3, __nv_bfloat162* h3, __nv_bfloat162* l3, int n3,
        const float4* s4, __nv_bfloat162* h4, __nv_bfloat162* l4, int n4_,
        const float4* s5, __nv_bfloat162* h5, __nv_bfloat162* l5, int n5) {
    const float4* s; __nv_bfloat162* h; __nv_bfloat162* l; int n;
    switch (blockIdx.y) {
        case 0: s = s0; h = h0; l = l0; n = n0; break;
        case 1: s = s1; h = h1; l = l1; n = n1; break;
        case 2: s = s2; h = h2; l = l2; n = n2; break;
        case 3: s = s3; h = h3; l = l3; n = n3; break;
        case 4: s = s4; h = h4; l = l4; n = n4_; break;
        default: s = s5; h = h5; l = l5; n = n5; break;
    }
    int i = blockIdx.x * blockDim.x + threadIdx.x;
    if (i < n) split4_body(s, h, l, i);
}

// ---------------- split-bf16 mma.sync GEMM core ------------------------------
#define PADE   40
#define TILEB  (128*PADE*2)
#define STB128 (4*TILEB)
#define GSMEM128 (2*STB128)             /* 81920 */

// EPI: 0 f32+optional-bias, 2 bf16split+bias+relu, 3 f32, 4 bf16split+bias+scale
template<int EPI>
__device__ __forceinline__ void gemm_core(
        const bf16* Ahi, const bf16* Alo, const bf16* Bhi, const bf16* Blo,
        const float* bias, float sc,
        float* C, bf16* Chi, bf16* Clo,
        int m0, int n0, int N, int K, int ldk, uint32_t sb) {
    const int tid = threadIdx.x;
    const int wid = tid >> 5, lane = tid & 31;
    const int wm = (wid >> 2) * 64;
    const int wn = (wid & 3) * 32;

    float Cf[4][4][4];
#pragma unroll
    for (int i = 0; i < 4; i++)
#pragma unroll
        for (int j = 0; j < 4; j++)
#pragma unroll
            for (int x = 0; x < 4; x++) Cf[i][j][x] = 0.f;

    const int NS = K >> 5;
    const int a_row = (lane & 15);
    const int a_colsel = (lane >> 4) * 8;
    const int b_row = (lane & 7) + ((lane >> 4) & 1) * 8;
    const int b_colsel = ((lane >> 3) & 1) * 8;
    const int lr = tid >> 2;
    const int lc = tid & 3;

#define LOAD_STAGE(SB_, K0_)                                                    \
    do {                                                                        \
        uint32_t tb = (SB_);                                                    \
        _Pragma("unroll")                                                       \
        for (int hr = 0; hr < 2; hr++) {                                        \
            int row = lr + hr * 64;                                             \
            cpasync16(tb + row * (PADE*2) + lc * 16,                            \
                      Ahi + (size_t)(m0 + row) * ldk + (K0_) + lc * 8);         \
            cpasync16(tb + TILEB + row * (PADE*2) + lc * 16,                    \
                      Alo + (size_t)(m0 + row) * ldk + (K0_) + lc * 8);         \
            cpasync16(tb + 2*TILEB + row * (PADE*2) + lc * 16,                  \
                      Bhi + (size_t)(n0 + row) * ldk + (K0_) + lc * 8);         \
            cpasync16(tb + 3*TILEB + row * (PADE*2) + lc * 16,                  \
                      Blo + (size_t)(n0 + row) * ldk + (K0_) + lc * 8);         \
        }                                                                       \
    } while (0)

    LOAD_STAGE(sb, 0);
    CP_COMMIT();

    for (int s = 0; s < NS; s++) {
        if (s + 1 < NS) {
            LOAD_STAGE(sb + ((s + 1) & 1) * STB128, (s + 1) << 5);
            CP_COMMIT();
            CP_WAIT(1);
        } else {
            CP_WAIT(0);
        }
        __syncthreads();

        const uint32_t st = sb + (s & 1) * STB128;
        const uint32_t tAh = st;
        const uint32_t tAl = st + TILEB;
        const uint32_t tBh = st + 2 * TILEB;
        const uint32_t tBl = st + 3 * TILEB;

#pragma unroll
        for (int k16 = 0; k16 < 32; k16 += 16) {
            uint32_t Aany[4][4], Bh[2][4], Bl[2][4];
#pragma unroll
            for (int mf = 0; mf < 4; mf++)
                ldsm4(Aany[mf], tAh + (wm + mf * 16 + a_row) * (PADE*2) + (k16 + a_colsel) * 2);
#pragma unroll
            for (int p = 0; p < 2; p++) {
                ldsm4(Bh[p], tBh + (wn + p * 16 + b_row) * (PADE*2) + (k16 + b_colsel) * 2);
                ldsm4(Bl[p], tBl + (wn + p * 16 + b_row) * (PADE*2) + (k16 + b_colsel) * 2);
            }
#pragma unroll
            for (int mf = 0; mf < 4; mf++)
#pragma unroll
                for (int nf = 0; nf < 4; nf++)
                    mma16816(Cf[mf][nf], Aany[mf], &Bh[nf >> 1][(nf & 1) * 2]);
#pragma unroll
            for (int mf = 0; mf < 4; mf++)
#pragma unroll
                for (int nf = 0; nf < 4; nf++)
                    mma16816(Cf[mf][nf], Aany[mf], &Bl[nf >> 1][(nf & 1) * 2]);
#pragma unroll
            for (int mf = 0; mf < 4; mf++)
                ldsm4(Aany[mf], tAl + (wm + mf * 16 + a_row) * (PADE*2) + (k16 + a_colsel) * 2);
#pragma unroll
            for (int mf = 0; mf < 4; mf++)
#pragma unroll
                for (int nf = 0; nf < 4; nf++)
                    mma16816(Cf[mf][nf], Aany[mf], &Bh[nf >> 1][(nf & 1) * 2]);
        }
        __syncthreads();
    }
#undef LOAD_STAGE

    const int g = lane >> 2, t2 = (lane & 3) * 2;
#pragma unroll
    for (int mf = 0; mf < 4; mf++) {
#pragma unroll
        for (int nf = 0; nf < 4; nf++) {
            int n = n0 + wn + nf * 8 + t2;
#pragma unroll
            for (int hrow = 0; hrow < 2; hrow++) {
                int m = m0 + wm + mf * 16 + g + hrow * 8;
                float v0 = Cf[mf][nf][hrow * 2 + 0];
                float v1 = Cf[mf][nf][hrow * 2 + 1];
                if (EPI == 0) {
                    if (bias) { v0 += bias[n]; v1 += bias[n + 1]; }
                } else if (EPI != 3) {
                    v0 += bias[n]; v1 += bias[n + 1];
                }
                if (EPI == 2 || EPI == 4) {
                    if (EPI == 2) { v0 = fmaxf(v0, 0.f); v1 = fmaxf(v1, 0.f); }
                    else          { v0 *= sc; v1 *= sc; }
                    bf16 h0, l0, h1, l1;
                    split1(v0, h0, l0); split1(v1, h1, l1);
                    *(__nv_bfloat162*)&Chi[(size_t)m * N + n] = __nv_bfloat162(h0, h1);
                    *(__nv_bfloat162*)&Clo[(size_t)m * N + n] = __nv_bfloat162(l0, l1);
                } else {
                    *(float2*)&C[(size_t)m * N + n] = make_float2(v0, v1);
                }
            }
        }
    }
}

template<int EPI>
__global__ __launch_bounds__(256, 2)
void mm_gemm128(const bf16* __restrict__ Ahi, const bf16* __restrict__ Alo,
                const bf16* __restrict__ Bhi, const bf16* __restrict__ Blo,
                const float* __restrict__ bias,
                float* __restrict__ C, bf16* __restrict__ Chi, bf16* __restrict__ Clo,
                int N, int K) {
    extern __shared__ char smem_raw[];
    gemm_core<EPI>(Ahi, Alo, Bhi, Blo, bias, 1.0f, C, Chi, Clo,
                   blockIdx.y * 128, blockIdx.x * 128, N, K, K, smem_u32(smem_raw));
}

// split-K partial GEMM: grid.z = K-split index; writes fp32 partials, bias at z==0
__global__ __launch_bounds__(256, 2)
void mm_gemm_pk(const bf16* __restrict__ Ahi, const bf16* __restrict__ Alo,
                const bf16* __restrict__ Bhi, const bf16* __restrict__ Blo,
                const float* __restrict__ bias, float* __restrict__ P,
                int N, int Kfull, int Ks) {
    extern __shared__ char smem_raw[];
    const int z = blockIdx.z;
    const int k0 = z * Ks;
    gemm_core<0>(Ahi + k0, Alo + k0, Bhi + k0, Blo + k0,
                 z == 0 ? bias : nullptr, 1.0f,
                 P + (size_t)z * MTOK * N, nullptr, nullptr,
                 blockIdx.y * 128, blockIdx.x * 128, N, Ks, Kfull, smem_u32(smem_raw));
}

// fused QKV -> bf16 hi/lo outputs; q scaled by 1/8
__global__ __launch_bounds__(256, 2)
void qkv_gemm(const bf16* __restrict__ Ahi, const bf16* __restrict__ Alo,
              const bf16* __restrict__ wqh, const bf16* __restrict__ wql,
              const bf16* __restrict__ wkh, const bf16* __restrict__ wkl,
              const bf16* __restrict__ wvh, const bf16* __restrict__ wvl,
              const float* __restrict__ bq, const float* __restrict__ bk,
              const float* __restrict__ bv,
              bf16* __restrict__ qh, bf16* __restrict__ ql,
              bf16* __restrict__ kh, bf16* __restrict__ kl,
              bf16* __restrict__ vh, bf16* __restrict__ vl) {
    extern __shared__ char smem_raw[];
    const int which = blockIdx.x / 6, nb = blockIdx.x % 6;
    const bf16* Bh = (which == 0) ? wqh : (which == 1) ? wkh : wvh;
    const bf16* Bl = (which == 0) ? wql : (which == 1) ? wkl : wvl;
    const float* bias = (which == 0) ? bq : (which == 1) ? bk : bv;
    bf16* Ch = (which == 0) ? qh : (which == 1) ? kh : vh;
    bf16* Cl = (which == 0) ? ql : (which == 1) ? kl : vl;
    float sc = (which == 0) ? 0.125f : 1.0f;
    gemm_core<4>(Ahi, Alo, Bh, Bl, bias, sc, nullptr, Ch, Cl,
                 blockIdx.y * 128, nb * 128, DD, DD, DD, smem_u32(smem_raw));
}

// ---------------- MMA flash attention (128 q-rows per CTA, 8 warps) ----------
#define AST 144
#define QTILE (128*AST)                  /* 18432 */
#define KTILE (64*AST)                   /* 9216  */
#define ATT_SMEM (2*QTILE + 2*4*KTILE)   /* 110592 */

__device__ __forceinline__ void att_load_q(uint32_t dst, const bf16* src,
                                           size_t grow0, int hcol, int tid) {
    int r = tid >> 1, c0 = (tid & 1) * 4;      // 256 threads -> 128 rows
    const bf16* p = src + (grow0 + r) * DD + hcol + c0 * 8;
    uint32_t d = dst + r * AST + c0 * 16;
#pragma unroll
    for (int i = 0; i < 4; i++) cpasync16(d + i * 16, p + i * 8);
}
__device__ __forceinline__ void att_load_kv(uint32_t dst, const bf16* src,
                                            size_t grow0, int hcol, int tid) {
    int r = tid >> 2, q = tid & 3;             // 256 threads -> 64 rows
    const bf16* p = src + (grow0 + r) * DD + hcol + q * 16;
    uint32_t d = dst + r * AST + q * 32;
    cpasync16(d, p);
    cpasync16(d + 16, p + 8);
}

__global__ __launch_bounds__(256, 2)
void flash_attn(const bf16* __restrict__ qh, const bf16* __restrict__ ql,
                const bf16* __restrict__ kh, const bf16* __restrict__ kl,
                const bf16* __restrict__ vh, const bf16* __restrict__ vl,
                bf16* __restrict__ chi, bf16* __restrict__ clo) {
    const int qt = gridDim.x - 1 - blockIdx.x;   // heavy tiles first
    const int hd = blockIdx.y, b = blockIdx.z;
    extern __shared__ char smc[];
    const uint32_t sb = smem_u32(smc);
    const uint32_t Qh_s = sb, Ql_s = sb + QTILE;
    const uint32_t KV = sb + 2 * QTILE;

    const int tid = threadIdx.x, wid = tid >> 5, lane = tid & 31;
    const size_t qrow0 = (size_t)(b * SS + qt * 128);
    const int hcol = hd * DK;
    const int wrow = qt * 128 + wid * 16;        // warp's base q-row within seq

    att_load_q(Qh_s, qh, qrow0, hcol, tid);
    att_load_q(Ql_s, ql, qrow0, hcol, tid);
    {
        size_t kr = (size_t)(b * SS);
        att_load_kv(KV + 0 * KTILE, kh, kr, hcol, tid);
        att_load_kv(KV + 1 * KTILE, kl, kr, hcol, tid);
        att_load_kv(KV + 2 * KTILE, vh, kr, hcol, tid);
        att_load_kv(KV + 3 * KTILE, vl, kr, hcol, tid);
    }
    CP_COMMIT();

    float O[8][4];
    float mrow[2] = { -1e30f, -1e30f };
    float lrow[2] = { 0.f, 0.f };
#pragma unroll
    for (int nt = 0; nt < 8; nt++)
#pragma unroll
        for (int x = 0; x < 4; x++) O[nt][x] = 0.f;

    const int g = lane >> 2, t2q = (lane & 3) * 2;
    const int a_row = wid * 16 + (lane & 15);
    const uint32_t a_cs = ((lane >> 4) << 3) * 2;
    const int b_row = (lane & 7) + (((lane >> 4) & 1) << 3);
    const uint32_t b_cs = (((lane >> 3) & 1) << 3) * 2;
    const int v_row = (lane & 15);
    const uint32_t v_cs = ((lane >> 4) << 3) * 2;

    const int jmax = 2 * qt + 1;
    for (int jt = 0; jt <= jmax; jt++) {
        if (jt < jmax) {
            size_t kr = (size_t)(b * SS + (jt + 1) * 64);
            uint32_t nb = KV + ((jt + 1) & 1) * (4 * KTILE);
            att_load_kv(nb + 0 * KTILE, kh, kr, hcol, tid);
            att_load_kv(nb + 1 * KTILE, kl, kr, hcol, tid);
            att_load_kv(nb + 2 * KTILE, vh, kr, hcol, tid);
            att_load_kv(nb + 3 * KTILE, vl, kr, hcol, tid);
            CP_COMMIT();
            CP_WAIT(1);
        } else {
            CP_WAIT(0);
        }
        __syncthreads();

        const bool act = (jt * 64) <= (wrow + 15);        // warp has unmasked work
        const bool needmask = (jt * 64 + 63) > wrow;      // partial masking needed
        if (act) {
            const uint32_t Kh_s = KV + (jt & 1) * (4 * KTILE);
            const uint32_t Kl_s = Kh_s + KTILE;
            const uint32_t Vh_s = Kl_s + KTILE;
            const uint32_t Vl_s = Vh_s + KTILE;

            float S[8][4];
#pragma unroll
            for (int nt = 0; nt < 8; nt++)
#pragma unroll
                for (int x = 0; x < 4; x++) S[nt][x] = 0.f;

#pragma unroll
            for (int ks = 0; ks < 4; ks++) {
                uint32_t Ah[4], Al[4];
                ldsm4(Ah, Qh_s + a_row * AST + ks * 32 + a_cs);
                ldsm4(Al, Ql_s + a_row * AST + ks * 32 + a_cs);
#pragma unroll
                for (int p = 0; p < 4; p++) {
                    uint32_t Bh4[4], Bl4[4];
                    ldsm4(Bh4, Kh_s + (p * 16 + b_row) * AST + ks * 32 + b_cs);
                    ldsm4(Bl4, Kl_s + (p * 16 + b_row) * AST + ks * 32 + b_cs);
#pragma unroll
                    for (int q = 0; q < 2; q++) {
                        mma16816(S[p * 2 + q], Ah, &Bh4[q * 2]);
                        mma16816(S[p * 2 + q], Ah, &Bl4[q * 2]);
                        mma16816(S[p * 2 + q], Al, &Bh4[q * 2]);
                    }
                }
            }

#pragma unroll
            for (int half = 0; half < 2; half++) {
                const int rg = wrow + g + half * 8;       // seq row
                float mt = -1e30f;
#pragma unroll
                for (int nt = 0; nt < 8; nt++) {
                    float s0 = S[nt][half * 2], s1 = S[nt][half * 2 + 1];
                    if (needmask) {
                        int cg = jt * 64 + nt * 8 + t2q;
                        if (cg > rg)     s0 = -1e30f;
                        if (cg + 1 > rg) s1 = -1e30f;
                    }
                    S[nt][half * 2] = s0; S[nt][half * 2 + 1] = s1;
                    mt = fmaxf(mt, fmaxf(s0, s1));
                }
                mt = fmaxf(mt, __shfl_xor_sync(0xffffffffu, mt, 1));
                mt = fmaxf(mt, __shfl_xor_sync(0xffffffffu, mt, 2));
                float mn = fmaxf(mrow[half], mt);
                float f = __expf(mrow[half] - mn);
                mrow[half] = mn;
                float rs = 0.f;
#pragma unroll
                for (int nt = 0; nt < 8; nt++) {
                    float e0 = __expf(S[nt][half * 2] - mn);
                    float e1 = __expf(S[nt][half * 2 + 1] - mn);
                    S[nt][half * 2] = e0; S[nt][half * 2 + 1] = e1;
                    rs += e0 + e1;
                }
                rs += __shfl_xor_sync(0xffffffffu, rs, 1);
                rs += __shfl_xor_sync(0xffffffffu, rs, 2);
                lrow[half] = lrow[half] * f + rs;
#pragma unroll
                for (int nt = 0; nt < 8; nt++) {
                    O[nt][half * 2] *= f; O[nt][half * 2 + 1] *= f;
                }
            }

#pragma unroll
            for (int ks = 0; ks < 4; ks++) {
                uint32_t Ph[4], Pl[4];
#pragma unroll
                for (int q4 = 0; q4 < 4; q4++) {
                    int tile = 2 * ks + (q4 >> 1);
                    int o = (q4 & 1) * 2;
                    float v0 = S[tile][o], v1 = S[tile][o + 1];
                    bf16 h0 = __float2bfloat16(v0), h1 = __float2bfloat16(v1);
                    __nv_bfloat162 hh(h0, h1);
                    Ph[q4] = *(uint32_t*)&hh;
                    Pl[q4] = packbf(v0 - __bfloat162float(h0), v1 - __bfloat162float(h1));
                }
#pragma unroll
                for (int nt = 0; nt < 4; nt++) {
                    uint32_t Vh4[4], Vl4[4];
                    ldsm4t(Vh4, Vh_s + (ks * 16 + v_row) * AST + nt * 32 + v_cs);
                    ldsm4t(Vl4, Vl_s + (ks * 16 + v_row) * AST + nt * 32 + v_cs);
#pragma unroll
                    for (int q = 0; q < 2; q++) {
                        mma16816(O[nt * 2 + q], Ph, &Vh4[q * 2]);
                        mma16816(O[nt * 2 + q], Ph, &Vl4[q * 2]);
                        mma16816(O[nt * 2 + q], Pl, &Vh4[q * 2]);
                    }
                }
            }
        }
        __syncthreads();
    }

    float inv[2] = { 1.0f / lrow[0], 1.0f / lrow[1] };
#pragma unroll
    for (int nt = 0; nt < 8; nt++) {
#pragma unroll
        for (int half = 0; half < 2; half++) {
            size_t row = qrow0 + wid * 16 + g + half * 8;
            int col = hcol + nt * 8 + t2q;
            float v0 = O[nt][half * 2] * inv[half];
            float v1 = O[nt][half * 2 + 1] * inv[half];
            bf16 h0, l0, h1, l1;
            split1(v0, h0, l0); split1(v1, h1, l1);
            *(__nv_bfloat162*)&chi[row * DD + col] = __nv_bfloat162(h0, h1);
            *(__nv_bfloat162*)&clo[row * DD + col] = __nv_bfloat162(l0, l1);
        }
    }
}

// ---------------- driver -----------------------------------------------------
extern "C" void kernel_launch(void* const* d_in, const int* in_sizes, int n_in,
                              void* d_out, int out_size) {
    (void)in_sizes; (void)n_in; (void)out_size;
    const float* tok  = (const float*)d_in[1];
    const float* pos  = (const float*)d_in[2];
    const float* bq   = (const float*)d_in[4];
    const float* bk   = (const float*)d_in[6];
    const float* bv   = (const float*)d_in[8];
    const float* bo   = (const float*)d_in[10];
    const float* b1   = (const float*)d_in[12];
    const float* b2   = (const float*)d_in[14];
    const float* ln1g = (const float*)d_in[15];
    const float* ln1b = (const float*)d_in[16];
    const float* ln2g = (const float*)d_in[17];
    const float* ln2b = (const float*)d_in[18];
    const float* lnfg = (const float*)d_in[19];
    const float* lnfb = (const float*)d_in[20];
    float* out = (float*)d_out;

    float *h, *pp;
    cudaGetSymbolAddress((void**)&h,  g_h);
    cudaGetSymbolAddress((void**)&pp, g_p);

    bf16 *tokh, *tokl, *wqh, *wql, *wkh, *wkl, *wvh, *wvl, *woh, *wol;
    bf16 *w1h, *w1l, *w2h, *w2l, *ah, *al, *fh, *fl;
    bf16 *qh_, *ql_, *kh_, *kl_, *vh_, *vl_;
    cudaGetSymbolAddress((void**)&tokh, g_tok_hi); cudaGetSymbolAddress((void**)&tokl, g_tok_lo);
    cudaGetSymbolAddress((void**)&wqh,  g_wq_hi);  cudaGetSymbolAddress((void**)&wql,  g_wq_lo);
    cudaGetSymbolAddress((void**)&wkh,  g_wk_hi);  cudaGetSymbolAddress((void**)&wkl,  g_wk_lo);
    cudaGetSymbolAddress((void**)&wvh,  g_wv_hi);  cudaGetSymbolAddress((void**)&wvl,  g_wv_lo);
    cudaGetSymbolAddress((void**)&woh,  g_wo_hi);  cudaGetSymbolAddress((void**)&wol,  g_wo_lo);
    cudaGetSymbolAddress((void**)&w1h,  g_w1_hi);  cudaGetSymbolAddress((void**)&w1l,  g_w1_lo);
    cudaGetSymbolAddress((void**)&w2h,  g_w2_hi);  cudaGetSymbolAddress((void**)&w2l,  g_w2_lo);
    cudaGetSymbolAddress((void**)&ah,   g_a_hi);   cudaGetSymbolAddress((void**)&al,   g_a_lo);
    cudaGetSymbolAddress((void**)&fh,   g_f_hi);   cudaGetSymbolAddress((void**)&fl,   g_f_lo);
    cudaGetSymbolAddress((void**)&qh_,  g_qh);     cudaGetSymbolAddress((void**)&ql_,  g_ql);
    cudaGetSymbolAddress((void**)&kh_,  g_kh);     cudaGetSymbolAddress((void**)&kl_,  g_kl);
    cudaGetSymbolAddress((void**)&vh_,  g_vh);     cudaGetSymbolAddress((void**)&vl_,  g_vl);

    cudaFuncSetAttribute(mm_gemm128<2>, cudaFuncAttributeMaxDynamicSharedMemorySize, GSMEM128);
    cudaFuncSetAttribute(mm_gemm128<3>, cudaFuncAttributeMaxDynamicSharedMemorySize, GSMEM128);
    cudaFuncSetAttribute(mm_gemm_pk,    cudaFuncAttributeMaxDynamicSharedMemorySize, GSMEM128);
    cudaFuncSetAttribute(qkv_gemm,      cudaFuncAttributeMaxDynamicSharedMemorySize, GSMEM128);
    cudaFuncSetAttribute(flash_attn,    cudaFuncAttributeMaxDynamicSharedMemorySize, ATT_SMEM);

    // launch 0: embed (with inline token dtype detection)
    embedcvt_kernel<<<(MTOK * DD + 255) / 256, 256>>>((const long long*)d_in[0], tok, pos);
    // launch 1: all weight splits
    {
        const int nD4 = LL * DD * DD / 4;
        const int nF4 = LL * FF * DD / 4;
        dim3 gw((nF4 + 255) / 256, 6);
        split_w_kernel<<<gw, 256>>>(
            (const float4*)d_in[3],  (__nv_bfloat162*)wqh, (__nv_bfloat162*)wql, nD4,
            (const float4*)d_in[5],  (__nv_bfloat162*)wkh, (__nv_bfloat162*)wkl, nD4,
            (const float4*)d_in[7],  (__nv_bfloat162*)wvh, (__nv_bfloat162*)wvl, nD4,
            (const float4*)d_in[9],  (__nv_bfloat162*)woh, (__nv_bfloat162*)wol, nD4,
            (const float4*)d_in[11], (__nv_bfloat162*)w1h, (__nv_bfloat162*)w1l, nF4,
            (const float4*)d_in[13], (__nv_bfloat162*)w2h, (__nv_bfloat162*)w2l, nF4);
    }

    dim3 gQKV(18, MTOK / 128);           // (18, 16)
    dim3 gPK(DD / 128, MTOK / 128, 3);   // (6, 16, 3) — 288 CTAs
    dim3 gF(FF / 128, MTOK / 128);       // (24, 16)
    dim3 gV(VV / 128, MTOK / 128);       // (250, 16)
    dim3 gA(SS / 128, HH, BB);           // (8, 12, 2)
    const int gLN = MTOK / 8;            // 256 blocks, warp-per-row

    for (int l = 0; l < LL; l++) {
        const size_t wD = (size_t)l * DD * DD;
        if (l == 0)
            ln_kernel<<<gLN, 256>>>(h, ln1g, ln1b, ah, al);                 // launch 2
        else
            ln_res_kernel<<<gLN, 256>>>(h, pp, ln1g + l * DD, ln1b + l * DD, ah, al);
        qkv_gemm<<<gQKV, 256, GSMEM128>>>(ah, al, wqh + wD, wql + wD,       // launch 3 (l=0) — profiled
                                          wkh + wD, wkl + wD, wvh + wD, wvl + wD,
                                          bq + l * DD, bk + l * DD, bv + l * DD,
                                          qh_, ql_, kh_, kl_, vh_, vl_);
        flash_attn<<<gA, 256, ATT_SMEM>>>(qh_, ql_, kh_, kl_, vh_, vl_, ah, al);
        mm_gemm_pk<<<gPK, 256, GSMEM128>>>(ah, al, woh + wD, wol + wD,
                                           bo + l * DD, pp, DD, DD, DD / 3);
        ln_res_kernel<<<gLN, 256>>>(h, pp, ln2g + l * DD, ln2b + l * DD, ah, al);
        mm_gemm128<2><<<gF, 256, GSMEM128>>>(ah, al, w1h + (size_t)l * FF * DD,
                                             w1l + (size_t)l * FF * DD, b1 + l * FF,
                                             nullptr, fh, fl, FF, DD);
        mm_gemm_pk<<<gPK, 256, GSMEM128>>>(fh, fl, w2h + (size_t)l * DD * FF,
                                           w2l + (size_t)l * DD * FF, b2 + l * DD,
                                           pp, DD, FF, FF / 3);
    }

    // tok-emb split only needed by the LM head — keep it late
    {
        int n4 = VV * DD / 4;
        split_kernel<<<(n4 + 255) / 256, 256>>>((const float4*)tok,
            (__nv_bfloat162*)tokh, (__nv_bfloat162*)tokl, n4);
    }
    ln_res_kernel<<<gLN, 256>>>(h, pp, lnfg, lnfb, ah, al);
    mm_gemm128<3><<<gV, 256, GSMEM128>>>(ah, al, tokh, tokl, nullptr,
                                         out, nullptr, nullptr, VV, DD);
}

// round 9
// speedup vs baseline: 1.0226x; 1.0226x over previous
#include <cuda_runtime.h>
#include <cuda_bf16.h>
#include <cstdint>
#include <math.h>

#define BB 2
#define SS 1024
#define DD 768
#define HH 12
#define DK 64
#define FF 3072
#define LL 4
#define VV 32000
#define MTOK (BB*SS)   /* 2048 */

typedef __nv_bfloat16 bf16;

// ---------------- scratch ----------------------------------------------------
__device__ float g_h  [MTOK*DD];
__device__ float g_p  [3*MTOK*DD];        // split-K partials
__device__ bf16 g_tok_hi[VV*DD],    g_tok_lo[VV*DD];
__device__ bf16 g_wq_hi [LL*DD*DD], g_wq_lo [LL*DD*DD];
__device__ bf16 g_wk_hi [LL*DD*DD], g_wk_lo [LL*DD*DD];
__device__ bf16 g_wv_hi [LL*DD*DD], g_wv_lo [LL*DD*DD];
__device__ bf16 g_wo_hi [LL*DD*DD], g_wo_lo [LL*DD*DD];
__device__ bf16 g_w1_hi [LL*FF*DD], g_w1_lo [LL*FF*DD];
__device__ bf16 g_w2_hi [LL*DD*FF], g_w2_lo [LL*DD*FF];
__device__ bf16 g_a_hi  [MTOK*DD],  g_a_lo  [MTOK*DD];
__device__ bf16 g_f_hi  [MTOK*FF],  g_f_lo  [MTOK*FF];
__device__ bf16 g_qh[MTOK*DD], g_ql[MTOK*DD];
__device__ bf16 g_kh[MTOK*DD], g_kl[MTOK*DD];
__device__ bf16 g_vh[MTOK*DD], g_vl[MTOK*DD];

// ---------------- helpers ----------------------------------------------------
__device__ __forceinline__ uint32_t smem_u32(const void* p) {
    uint32_t a;
    asm("{ .reg .u64 t; cvta.to.shared.u64 t, %1; cvt.u32.u64 %0, t; }" : "=r"(a) : "l"(p));
    return a;
}
__device__ __forceinline__ void cpasync16(uint32_t saddr, const void* gaddr) {
    asm volatile("cp.async.cg.shared.global [%0], [%1], 16;" :: "r"(saddr), "l"(gaddr));
}
#define CP_COMMIT() asm volatile("cp.async.commit_group;" ::: "memory")
#define CP_WAIT(N)  asm volatile("cp.async.wait_group %0;" :: "n"(N) : "memory")

__device__ __forceinline__ void ldsm4(uint32_t* r, uint32_t addr) {
    asm volatile("ldmatrix.sync.aligned.m8n8.x4.shared.b16 {%0,%1,%2,%3}, [%4];"
        : "=r"(r[0]), "=r"(r[1]), "=r"(r[2]), "=r"(r[3]) : "r"(addr));
}
__device__ __forceinline__ void ldsm4t(uint32_t* r, uint32_t addr) {
    asm volatile("ldmatrix.sync.aligned.m8n8.x4.trans.shared.b16 {%0,%1,%2,%3}, [%4];"
        : "=r"(r[0]), "=r"(r[1]), "=r"(r[2]), "=r"(r[3]) : "r"(addr));
}
__device__ __forceinline__ void mma16816(float* c, const uint32_t* a, const uint32_t* b) {
    asm volatile(
        "mma.sync.aligned.m16n8k16.row.col.f32.bf16.bf16.f32 "
        "{%0,%1,%2,%3}, {%4,%5,%6,%7}, {%8,%9}, {%0,%1,%2,%3};"
        : "+f"(c[0]), "+f"(c[1]), "+f"(c[2]), "+f"(c[3])
        : "r"(a[0]), "r"(a[1]), "r"(a[2]), "r"(a[3]), "r"(b[0]), "r"(b[1]));
}
__device__ __forceinline__ void split1(float v, bf16& h, bf16& l) {
    h = __float2bfloat16(v);
    l = __float2bfloat16(v - __bfloat162float(h));
}
__device__ __forceinline__ uint32_t packbf(float v0, float v1) {
    __nv_bfloat162 p(__float2bfloat16(v0), __float2bfloat16(v1));
    return *(uint32_t*)&p;
}

// ---------------- embed (inline int64/int32 token detection) -----------------
__global__ void embedcvt_kernel(const long long* __restrict__ x64,
                                const float* __restrict__ tok,
                                const float* __restrict__ pos) {
    __shared__ int is64s;
    if (threadIdx.x == 0) {
        int ok = 1;
        for (int i = 0; i < 16; i++) { long long t = x64[i]; if (t < 0 || t >= VV) ok = 0; }
        is64s = ok;
    }
    __syncthreads();
    int idx = blockIdx.x * blockDim.x + threadIdx.x;
    if (idx < MTOK * DD) {
        int d = idx % DD, t = idx / DD, s = t % SS;
        int tokid = is64s ? (int)x64[t] : ((const int*)x64)[t];
        g_h[idx] = tok[tokid * DD + d] + pos[s * DD + d];
    }
}

// ---------------- warp-per-row layernorm -> bf16 hi/lo -----------------------
__global__ __launch_bounds__(256)
void ln_kernel(const float* __restrict__ in, const float* __restrict__ g,
               const float* __restrict__ b,
               bf16* __restrict__ ohi, bf16* __restrict__ olo) {
    const int wid = threadIdx.x >> 5, lane = threadIdx.x & 31;
    const int row = blockIdx.x * 8 + wid;
    const float4* xr = (const float4*)(in + (size_t)row * DD);
    float4 v[6];
    float s1 = 0.f, s2 = 0.f;
#pragma unroll
    for (int i = 0; i < 6; i++) {
        v[i] = xr[lane + 32 * i];
        s1 += v[i].x + v[i].y + v[i].z + v[i].w;
        s2 += v[i].x*v[i].x + v[i].y*v[i].y + v[i].z*v[i].z + v[i].w*v[i].w;
    }
#pragma unroll
    for (int o = 16; o > 0; o >>= 1) {
        s1 += __shfl_xor_sync(0xffffffffu, s1, o);
        s2 += __shfl_xor_sync(0xffffffffu, s2, o);
    }
    float mu = s1 * (1.0f / DD);
    float inv = rsqrtf(s2 * (1.0f / DD) - mu * mu + 1e-5f);
    const float4* gg = (const float4*)g;
    const float4* bb = (const float4*)b;
#pragma unroll
    for (int i = 0; i < 6; i++) {
        int e4 = lane + 32 * i;
        float4 gv = gg[e4], bv = bb[e4];
        float o0 = (v[i].x - mu) * inv * gv.x + bv.x;
        float o1 = (v[i].y - mu) * inv * gv.y + bv.y;
        float o2 = (v[i].z - mu) * inv * gv.z + bv.z;
        float o3 = (v[i].w - mu) * inv * gv.w + bv.w;
        bf16 h0,l0,h1,l1,h2,l2,h3,l3;
        split1(o0,h0,l0); split1(o1,h1,l1); split1(o2,h2,l2); split1(o3,h3,l3);
        size_t base = (size_t)row * DD + e4 * 4;
        *(__nv_bfloat162*)&ohi[base]     = __nv_bfloat162(h0, h1);
        *(__nv_bfloat162*)&ohi[base + 2] = __nv_bfloat162(h2, h3);
        *(__nv_bfloat162*)&olo[base]     = __nv_bfloat162(l0, l1);
        *(__nv_bfloat162*)&olo[base + 2] = __nv_bfloat162(l2, l3);
    }
}

__global__ __launch_bounds__(256)
void ln_res_kernel(float* __restrict__ h, const float* __restrict__ p,
                   const float* __restrict__ g, const float* __restrict__ b,
                   bf16* __restrict__ ohi, bf16* __restrict__ olo) {
    const int wid = threadIdx.x >> 5, lane = threadIdx.x & 31;
    const int row = blockIdx.x * 8 + wid;
    float4* hr = (float4*)(h + (size_t)row * DD);
    const float4* p0 = (const float4*)(p + (size_t)row * DD);
    const float4* p1 = (const float4*)(p + (size_t)MTOK * DD + (size_t)row * DD);
    const float4* p2 = (const float4*)(p + 2 * (size_t)MTOK * DD + (size_t)row * DD);
    float4 v[6];
    float s1 = 0.f, s2 = 0.f;
#pragma unroll
    for (int i = 0; i < 6; i++) {
        int e4 = lane + 32 * i;
        float4 hv = hr[e4], a0 = p0[e4], a1 = p1[e4], a2 = p2[e4];
        hv.x += a0.x + a1.x + a2.x;
        hv.y += a0.y + a1.y + a2.y;
        hv.z += a0.z + a1.z + a2.z;
        hv.w += a0.w + a1.w + a2.w;
        hr[e4] = hv;
        v[i] = hv;
        s1 += hv.x + hv.y + hv.z + hv.w;
        s2 += hv.x*hv.x + hv.y*hv.y + hv.z*hv.z + hv.w*hv.w;
    }
#pragma unroll
    for (int o = 16; o > 0; o >>= 1) {
        s1 += __shfl_xor_sync(0xffffffffu, s1, o);
        s2 += __shfl_xor_sync(0xffffffffu, s2, o);
    }
    float mu = s1 * (1.0f / DD);
    float inv = rsqrtf(s2 * (1.0f / DD) - mu * mu + 1e-5f);
    const float4* gg = (const float4*)g;
    const float4* bb = (const float4*)b;
#pragma unroll
    for (int i = 0; i < 6; i++) {
        int e4 = lane + 32 * i;
        float4 gv = gg[e4], bv = bb[e4];
        float o0 = (v[i].x - mu) * inv * gv.x + bv.x;
        float o1 = (v[i].y - mu) * inv * gv.y + bv.y;
        float o2 = (v[i].z - mu) * inv * gv.z + bv.z;
        float o3 = (v[i].w - mu) * inv * gv.w + bv.w;
        bf16 h0,l0,h1,l1,h2,l2,h3,l3;
        split1(o0,h0,l0); split1(o1,h1,l1); split1(o2,h2,l2); split1(o3,h3,l3);
        size_t base = (size_t)row * DD + e4 * 4;
        *(__nv_bfloat162*)&ohi[base]     = __nv_bfloat162(h0, h1);
        *(__nv_bfloat162*)&ohi[base + 2] = __nv_bfloat162(h2, h3);
        *(__nv_bfloat162*)&olo[base]     = __nv_bfloat162(l0, l1);
        *(__nv_bfloat162*)&olo[base + 2] = __nv_bfloat162(l2, l3);
    }
}

// ---------------- fp32 -> bf16 hi/lo splits ----------------------------------
__device__ __forceinline__ void split4_body(const float4* x, __nv_bfloat162* hi,
                                            __nv_bfloat162* lo, int i) {
    float4 v = x[i];
    bf16 hx, lx, hy, ly, hz, lz, hw, lw;
    split1(v.x, hx, lx); split1(v.y, hy, ly);
    split1(v.z, hz, lz); split1(v.w, hw, lw);
    hi[2*i]   = __nv_bfloat162(hx, hy);
    hi[2*i+1] = __nv_bfloat162(hz, hw);
    lo[2*i]   = __nv_bfloat162(lx, ly);
    lo[2*i+1] = __nv_bfloat162(lz, lw);
}

__global__ void split_kernel(const float4* __restrict__ x,
                             __nv_bfloat162* __restrict__ hi,
                             __nv_bfloat162* __restrict__ lo, int n4) {
    int i = blockIdx.x * blockDim.x + threadIdx.x;
    if (i < n4) split4_body(x, hi, lo, i);
}

__global__ void split_w_kernel(
        const float4* s0, __nv_bfloat162* h0, __nv_bfloat162* l0, int n0,
        const float4* s1, __nv_bfloat162* h1, __nv_bfloat162* l1, int n1,
        const float4* s2, __nv_bfloat162* h2, __nv_bfloat162* l2, int n2,
        const float4* s3, __nv_bfloat162* h3, __nv_bfloat162* l3, int n3,
        const float4* s4, __nv_bfloat162* h4, __nv_bfloat162* l4, int n4_,
        const float4* s5, __nv_bfloat162* h5, __nv_bfloat162* l5, int n5) {
    const float4* s; __nv_bfloat162* h; __nv_bfloat162* l; int n;
    switch (blockIdx.y) {
        case 0: s = s0; h = h0; l = l0; n = n0; break;
        case 1: s = s1; h = h1; l = l1; n = n1; break;
        case 2: s = s2; h = h2; l = l2; n = n2; break;
        case 3: s = s3; h = h3; l = l3; n = n3; break;
        case 4: s = s4; h = h4; l = l4; n = n4_; break;
        default: s = s5; h = h5; l = l5; n = n5; break;
    }
    int i = blockIdx.x * blockDim.x + threadIdx.x;
    if (i < n) split4_body(s, h, l, i);
}

// ---------------- split-bf16 mma.sync GEMM core ------------------------------
// 4-stage K16 pipeline, ONE __syncthreads per stage (CUTLASS multistage order).
#define RB     48                        /* 24 bf16 row stride (16 data + 8 pad) */
#define TILE16 (128*RB)                  /* 6144 B  */
#define STG16  (4*TILE16)                /* 24576 B : Ahi|Alo|Bhi|Blo */
#define NSTG   4
#define GSMEM16 (NSTG*STG16)             /* 98304 B */

// EPI: 0 f32+optional-bias, 2 bf16split+bias+relu, 3 f32, 4 bf16split+bias+scale
template<int EPI>
__device__ __forceinline__ void gemm_core(
        const bf16* Ahi, const bf16* Alo, const bf16* Bhi, const bf16* Blo,
        const float* bias, float sc,
        float* C, bf16* Chi, bf16* Clo,
        int m0, int n0, int N, int K, int ldk, uint32_t sb) {
    const int tid = threadIdx.x;
    const int wid = tid >> 5, lane = tid & 31;
    const int wm = (wid >> 2) * 64;
    const int wn = (wid & 3) * 32;

    float Cf[4][4][4];
#pragma unroll
    for (int i = 0; i < 4; i++)
#pragma unroll
        for (int j = 0; j < 4; j++)
#pragma unroll
            for (int x = 0; x < 4; x++) Cf[i][j][x] = 0.f;

    const int NS = K >> 4;               // K16 stages
    const int a_row = (lane & 15);
    const int a_cs = ((lane >> 4) * 8) * 2;          // byte offset 0/16
    const int b_row = (lane & 7) + ((lane >> 4) & 1) * 8;
    const int b_cs = (((lane >> 3) & 1) * 8) * 2;
    const int lr = tid >> 1;             // 0..127
    const int lc = tid & 1;              // 16B chunk

#define LOAD_STG(S_)                                                            \
    do {                                                                        \
        const int k0_ = (S_) << 4;                                              \
        uint32_t tb = sb + ((S_) & (NSTG - 1)) * STG16 + lr * RB + lc * 16;     \
        const int ac_ = k0_ + lc * 8;                                           \
        cpasync16(tb,              Ahi + (size_t)(m0 + lr) * ldk + ac_);        \
        cpasync16(tb + TILE16,     Alo + (size_t)(m0 + lr) * ldk + ac_);        \
        cpasync16(tb + 2 * TILE16, Bhi + (size_t)(n0 + lr) * ldk + ac_);        \
        cpasync16(tb + 3 * TILE16, Blo + (size_t)(n0 + lr) * ldk + ac_);        \
    } while (0)

    // prologue: 3 stages in flight
#pragma unroll
    for (int s = 0; s < NSTG - 1; s++) { LOAD_STG(s); CP_COMMIT(); }

    for (int s = 0; s < NS; s++) {
        CP_WAIT(NSTG - 2);               // stage s resident
        __syncthreads();                 // visible to all; prior readers done

        const uint32_t st = sb + (s & (NSTG - 1)) * STG16;
        const uint32_t tAh = st;
        const uint32_t tAl = st + TILE16;
        const uint32_t tBh = st + 2 * TILE16;
        const uint32_t tBl = st + 3 * TILE16;

        uint32_t Aany[4][4], Bh[2][4], Bl[2][4];
#pragma unroll
        for (int mf = 0; mf < 4; mf++)
            ldsm4(Aany[mf], tAh + (wm + mf * 16 + a_row) * RB + a_cs);
#pragma unroll
        for (int p = 0; p < 2; p++) {
            ldsm4(Bh[p], tBh + (wn + p * 16 + b_row) * RB + b_cs);
            ldsm4(Bl[p], tBl + (wn + p * 16 + b_row) * RB + b_cs);
        }
#pragma unroll
        for (int mf = 0; mf < 4; mf++)
#pragma unroll
            for (int nf = 0; nf < 4; nf++)
                mma16816(Cf[mf][nf], Aany[mf], &Bh[nf >> 1][(nf & 1) * 2]);
#pragma unroll
        for (int mf = 0; mf < 4; mf++)
#pragma unroll
            for (int nf = 0; nf < 4; nf++)
                mma16816(Cf[mf][nf], Aany[mf], &Bl[nf >> 1][(nf & 1) * 2]);
#pragma unroll
        for (int mf = 0; mf < 4; mf++)
            ldsm4(Aany[mf], tAl + (wm + mf * 16 + a_row) * RB + a_cs);
#pragma unroll
        for (int mf = 0; mf < 4; mf++)
#pragma unroll
            for (int nf = 0; nf < 4; nf++)
                mma16816(Cf[mf][nf], Aany[mf], &Bh[nf >> 1][(nf & 1) * 2]);

        if (s + NSTG - 1 < NS) LOAD_STG(s + NSTG - 1);
        CP_COMMIT();                     // always commit (keeps group numbering)
    }
#undef LOAD_STG

    const int g = lane >> 2, t2 = (lane & 3) * 2;
#pragma unroll
    for (int mf = 0; mf < 4; mf++) {
#pragma unroll
        for (int nf = 0; nf < 4; nf++) {
            int n = n0 + wn + nf * 8 + t2;
#pragma unroll
            for (int hrow = 0; hrow < 2; hrow++) {
                int m = m0 + wm + mf * 16 + g + hrow * 8;
                float v0 = Cf[mf][nf][hrow * 2 + 0];
                float v1 = Cf[mf][nf][hrow * 2 + 1];
                if (EPI == 0) {
                    if (bias) { v0 += bias[n]; v1 += bias[n + 1]; }
                } else if (EPI != 3) {
                    v0 += bias[n]; v1 += bias[n + 1];
                }
                if (EPI == 2 || EPI == 4) {
                    if (EPI == 2) { v0 = fmaxf(v0, 0.f); v1 = fmaxf(v1, 0.f); }
                    else          { v0 *= sc; v1 *= sc; }
                    bf16 h0, l0, h1, l1;
                    split1(v0, h0, l0); split1(v1, h1, l1);
                    *(__nv_bfloat162*)&Chi[(size_t)m * N + n] = __nv_bfloat162(h0, h1);
                    *(__nv_bfloat162*)&Clo[(size_t)m * N + n] = __nv_bfloat162(l0, l1);
                } else {
                    *(float2*)&C[(size_t)m * N + n] = make_float2(v0, v1);
                }
            }
        }
    }
}

template<int EPI>
__global__ __launch_bounds__(256, 2)
void mm_gemm128(const bf16* __restrict__ Ahi, const bf16* __restrict__ Alo,
                const bf16* __restrict__ Bhi, const bf16* __restrict__ Blo,
                const float* __restrict__ bias,
                float* __restrict__ C, bf16* __restrict__ Chi, bf16* __restrict__ Clo,
                int N, int K) {
    extern __shared__ char smem_raw[];
    gemm_core<EPI>(Ahi, Alo, Bhi, Blo, bias, 1.0f, C, Chi, Clo,
                   blockIdx.y * 128, blockIdx.x * 128, N, K, K, smem_u32(smem_raw));
}

__global__ __launch_bounds__(256, 2)
void mm_gemm_pk(const bf16* __restrict__ Ahi, const bf16* __restrict__ Alo,
                const bf16* __restrict__ Bhi, const bf16* __restrict__ Blo,
                const float* __restrict__ bias, float* __restrict__ P,
                int N, int Kfull, int Ks) {
    extern __shared__ char smem_raw[];
    const int z = blockIdx.z;
    const int k0 = z * Ks;
    gemm_core<0>(Ahi + k0, Alo + k0, Bhi + k0, Blo + k0,
                 z == 0 ? bias : nullptr, 1.0f,
                 P + (size_t)z * MTOK * N, nullptr, nullptr,
                 blockIdx.y * 128, blockIdx.x * 128, N, Ks, Kfull, smem_u32(smem_raw));
}

__global__ __launch_bounds__(256, 2)
void qkv_gemm(const bf16* __restrict__ Ahi, const bf16* __restrict__ Alo,
              const bf16* __restrict__ wqh, const bf16* __restrict__ wql,
              const bf16* __restrict__ wkh, const bf16* __restrict__ wkl,
              const bf16* __restrict__ wvh, const bf16* __restrict__ wvl,
              const float* __restrict__ bq, const float* __restrict__ bk,
              const float* __restrict__ bv,
              bf16* __restrict__ qh, bf16* __restrict__ ql,
              bf16* __restrict__ kh, bf16* __restrict__ kl,
              bf16* __restrict__ vh, bf16* __restrict__ vl) {
    extern __shared__ char smem_raw[];
    const int which = blockIdx.x / 6, nb = blockIdx.x % 6;
    const bf16* Bh = (which == 0) ? wqh : (which == 1) ? wkh : wvh;
    const bf16* Bl = (which == 0) ? wql : (which == 1) ? wkl : wvl;
    const float* bias = (which == 0) ? bq : (which == 1) ? bk : bv;
    bf16* Ch = (which == 0) ? qh : (which == 1) ? kh : vh;
    bf16* Cl = (which == 0) ? ql : (which == 1) ? kl : vl;
    float sc = (which == 0) ? 0.125f : 1.0f;
    gemm_core<4>(Ahi, Alo, Bh, Bl, bias, sc, nullptr, Ch, Cl,
                 blockIdx.y * 128, nb * 128, DD, DD, DD, smem_u32(smem_raw));
}

// ---------------- MMA flash attention (R7 64-query version) ------------------
#define AST 144
#define ATILE (64*AST)
#define ATT_SMEM (2*ATILE + 2*4*ATILE)   /* 92160 */

__device__ __forceinline__ void att_load4(uint32_t dst, const bf16* src,
                                          size_t grow0, int hcol, int tid) {
    int r = tid >> 1, c0 = (tid & 1) * 4;
    const bf16* p = src + (grow0 + r) * DD + hcol + c0 * 8;
    uint32_t d = dst + r * AST + c0 * 16;
#pragma unroll
    for (int i = 0; i < 4; i++) cpasync16(d + i * 16, p + i * 8);
}

__global__ __launch_bounds__(128)
void flash_attn(const bf16* __restrict__ qh, const bf16* __restrict__ ql,
                const bf16* __restrict__ kh, const bf16* __restrict__ kl,
                const bf16* __restrict__ vh, const bf16* __restrict__ vl,
                bf16* __restrict__ chi, bf16* __restrict__ clo) {
    const int qt = gridDim.x - 1 - blockIdx.x;
    const int hd = blockIdx.y, b = blockIdx.z;
    extern __shared__ char smc[];
    const uint32_t sb = smem_u32(smc);
    const uint32_t Qh_s = sb, Ql_s = sb + ATILE;
    const uint32_t KV = sb + 2 * ATILE;

    const int tid = threadIdx.x, wid = tid >> 5, lane = tid & 31;
    const size_t qrow0 = (size_t)(b * SS + qt * 64);
    const int hcol = hd * DK;

    att_load4(Qh_s, qh, qrow0, hcol, tid);
    att_load4(Ql_s, ql, qrow0, hcol, tid);
    {
        size_t kr = (size_t)(b * SS);
        att_load4(KV + 0 * ATILE, kh, kr, hcol, tid);
        att_load4(KV + 1 * ATILE, kl, kr, hcol, tid);
        att_load4(KV + 2 * ATILE, vh, kr, hcol, tid);
        att_load4(KV + 3 * ATILE, vl, kr, hcol, tid);
    }
    CP_COMMIT();

    float O[8][4];
    float mrow[2] = { -1e30f, -1e30f };
    float lrow[2] = { 0.f, 0.f };
#pragma unroll
    for (int nt = 0; nt < 8; nt++)
#pragma unroll
        for (int x = 0; x < 4; x++) O[nt][x] = 0.f;

    const int g = lane >> 2, t2q = (lane & 3) * 2;
    const int a_row = wid * 16 + (lane & 15);
    const uint32_t a_cs = ((lane >> 4) << 3) * 2;
    const int b_row = (lane & 7) + (((lane >> 4) & 1) << 3);
    const uint32_t b_cs = (((lane >> 3) & 1) << 3) * 2;
    const int v_row = (lane & 15);
    const uint32_t v_cs = ((lane >> 4) << 3) * 2;

    for (int jt = 0; jt <= qt; jt++) {
        if (jt < qt) {
            size_t kr = (size_t)(b * SS + (jt + 1) * 64);
            uint32_t nb = KV + ((jt + 1) & 1) * (4 * ATILE);
            att_load4(nb + 0 * ATILE, kh, kr, hcol, tid);
            att_load4(nb + 1 * ATILE, kl, kr, hcol, tid);
            att_load4(nb + 2 * ATILE, vh, kr, hcol, tid);
            att_load4(nb + 3 * ATILE, vl, kr, hcol, tid);
            CP_COMMIT();
            CP_WAIT(1);
        } else {
            CP_WAIT(0);
        }
        __syncthreads();

        const uint32_t Kh_s = KV + (jt & 1) * (4 * ATILE);
        const uint32_t Kl_s = Kh_s + ATILE;
        const uint32_t Vh_s = Kl_s + ATILE;
        const uint32_t Vl_s = Vh_s + ATILE;

        float S[8][4];
#pragma unroll
        for (int nt = 0; nt < 8; nt++)
#pragma unroll
            for (int x = 0; x < 4; x++) S[nt][x] = 0.f;

#pragma unroll
        for (int ks = 0; ks < 4; ks++) {
            uint32_t Ah[4], Al[4];
            ldsm4(Ah, Qh_s + a_row * AST + ks * 32 + a_cs);
            ldsm4(Al, Ql_s + a_row * AST + ks * 32 + a_cs);
#pragma unroll
            for (int p = 0; p < 2; p++) {
                uint32_t Bh4[4], Bl4[4];
                ldsm4(Bh4, Kh_s + (p * 16 + b_row) * AST + ks * 32 + b_cs);
                ldsm4(Bl4, Kl_s + (p * 16 + b_row) * AST + ks * 32 + b_cs);
#pragma unroll
                for (int q = 0; q < 2; q++) {
                    mma16816(S[p * 2 + q], Ah, &Bh4[q * 2]);
                    mma16816(S[p * 2 + q], Ah, &Bl4[q * 2]);
                    mma16816(S[p * 2 + q], Al, &Bh4[q * 2]);
                }
                uint32_t Bh4b[4], Bl4b[4];
                ldsm4(Bh4b, Kh_s + ((p + 2) * 16 + b_row) * AST + ks * 32 + b_cs);
                ldsm4(Bl4b, Kl_s + ((p + 2) * 16 + b_row) * AST + ks * 32 + b_cs);
#pragma unroll
                for (int q = 0; q < 2; q++) {
                    mma16816(S[(p + 2) * 2 + q], Ah, &Bh4b[q * 2]);
                    mma16816(S[(p + 2) * 2 + q], Ah, &Bl4b[q * 2]);
                    mma16816(S[(p + 2) * 2 + q], Al, &Bh4b[q * 2]);
                }
            }
        }

        const bool diag = (jt == qt);
#pragma unroll
        for (int half = 0; half < 2; half++) {
            const int rloc = wid * 16 + g + half * 8;
            float mt = -1e30f;
#pragma unroll
            for (int nt = 0; nt < 8; nt++) {
                float s0 = S[nt][half * 2], s1 = S[nt][half * 2 + 1];
                if (diag) {
                    if (nt * 8 + t2q > rloc)     s0 = -1e30f;
                    if (nt * 8 + t2q + 1 > rloc) s1 = -1e30f;
                }
                S[nt][half * 2] = s0; S[nt][half * 2 + 1] = s1;
                mt = fmaxf(mt, fmaxf(s0, s1));
            }
            mt = fmaxf(mt, __shfl_xor_sync(0xffffffffu, mt, 1));
            mt = fmaxf(mt, __shfl_xor_sync(0xffffffffu, mt, 2));
            float mn = fmaxf(mrow[half], mt);
            float f = __expf(mrow[half] - mn);
            mrow[half] = mn;
            float rs = 0.f;
#pragma unroll
            for (int nt = 0; nt < 8; nt++) {
                float e0 = __expf(S[nt][half * 2] - mn);
                float e1 = __expf(S[nt][half * 2 + 1] - mn);
                S[nt][half * 2] = e0; S[nt][half * 2 + 1] = e1;
                rs += e0 + e1;
            }
            rs += __shfl_xor_sync(0xffffffffu, rs, 1);
            rs += __shfl_xor_sync(0xffffffffu, rs, 2);
            lrow[half] = lrow[half] * f + rs;
#pragma unroll
            for (int nt = 0; nt < 8; nt++) {
                O[nt][half * 2] *= f; O[nt][half * 2 + 1] *= f;
            }
        }

#pragma unroll
        for (int ks = 0; ks < 4; ks++) {
            uint32_t Ph[4], Pl[4];
#pragma unroll
            for (int q4 = 0; q4 < 4; q4++) {
                int tile = 2 * ks + (q4 >> 1);
                int o = (q4 & 1) * 2;
                float v0 = S[tile][o], v1 = S[tile][o + 1];
                bf16 h0 = __float2bfloat16(v0), h1 = __float2bfloat16(v1);
                __nv_bfloat162 hh(h0, h1);
                Ph[q4] = *(uint32_t*)&hh;
                Pl[q4] = packbf(v0 - __bfloat162float(h0), v1 - __bfloat162float(h1));
            }
#pragma unroll
            for (int nt = 0; nt < 4; nt++) {
                uint32_t Vh4[4], Vl4[4];
                ldsm4t(Vh4, Vh_s + (ks * 16 + v_row) * AST + nt * 32 + v_cs);
                ldsm4t(Vl4, Vl_s + (ks * 16 + v_row) * AST + nt * 32 + v_cs);
#pragma unroll
                for (int q = 0; q < 2; q++) {
                    mma16816(O[nt * 2 + q], Ph, &Vh4[q * 2]);
                    mma16816(O[nt * 2 + q], Ph, &Vl4[q * 2]);
                    mma16816(O[nt * 2 + q], Pl, &Vh4[q * 2]);
                }
            }
        }
        __syncthreads();
    }

    float inv[2] = { 1.0f / lrow[0], 1.0f / lrow[1] };
#pragma unroll
    for (int nt = 0; nt < 8; nt++) {
#pragma unroll
        for (int half = 0; half < 2; half++) {
            size_t row = qrow0 + wid * 16 + g + half * 8;
            int col = hcol + nt * 8 + t2q;
            float v0 = O[nt][half * 2] * inv[half];
            float v1 = O[nt][half * 2 + 1] * inv[half];
            bf16 h0, l0, h1, l1;
            split1(v0, h0, l0); split1(v1, h1, l1);
            *(__nv_bfloat162*)&chi[row * DD + col] = __nv_bfloat162(h0, h1);
            *(__nv_bfloat162*)&clo[row * DD + col] = __nv_bfloat162(l0, l1);
        }
    }
}

// ---------------- driver -----------------------------------------------------
extern "C" void kernel_launch(void* const* d_in, const int* in_sizes, int n_in,
                              void* d_out, int out_size) {
    (void)in_sizes; (void)n_in; (void)out_size;
    const float* tok  = (const float*)d_in[1];
    const float* pos  = (const float*)d_in[2];
    const float* bq   = (const float*)d_in[4];
    const float* bk   = (const float*)d_in[6];
    const float* bv   = (const float*)d_in[8];
    const float* bo   = (const float*)d_in[10];
    const float* b1   = (const float*)d_in[12];
    const float* b2   = (const float*)d_in[14];
    const float* ln1g = (const float*)d_in[15];
    const float* ln1b = (const float*)d_in[16];
    const float* ln2g = (const float*)d_in[17];
    const float* ln2b = (const float*)d_in[18];
    const float* lnfg = (const float*)d_in[19];
    const float* lnfb = (const float*)d_in[20];
    float* out = (float*)d_out;

    float *h, *pp;
    cudaGetSymbolAddress((void**)&h,  g_h);
    cudaGetSymbolAddress((void**)&pp, g_p);

    bf16 *tokh, *tokl, *wqh, *wql, *wkh, *wkl, *wvh, *wvl, *woh, *wol;
    bf16 *w1h, *w1l, *w2h, *w2l, *ah, *al, *fh, *fl;
    bf16 *qh_, *ql_, *kh_, *kl_, *vh_, *vl_;
    cudaGetSymbolAddress((void**)&tokh, g_tok_hi); cudaGetSymbolAddress((void**)&tokl, g_tok_lo);
    cudaGetSymbolAddress((void**)&wqh,  g_wq_hi);  cudaGetSymbolAddress((void**)&wql,  g_wq_lo);
    cudaGetSymbolAddress((void**)&wkh,  g_wk_hi);  cudaGetSymbolAddress((void**)&wkl,  g_wk_lo);
    cudaGetSymbolAddress((void**)&wvh,  g_wv_hi);  cudaGetSymbolAddress((void**)&wvl,  g_wv_lo);
    cudaGetSymbolAddress((void**)&woh,  g_wo_hi);  cudaGetSymbolAddress((void**)&wol,  g_wo_lo);
    cudaGetSymbolAddress((void**)&w1h,  g_w1_hi);  cudaGetSymbolAddress((void**)&w1l,  g_w1_lo);
    cudaGetSymbolAddress((void**)&w2h,  g_w2_hi);  cudaGetSymbolAddress((void**)&w2l,  g_w2_lo);
    cudaGetSymbolAddress((void**)&ah,   g_a_hi);   cudaGetSymbolAddress((void**)&al,   g_a_lo);
    cudaGetSymbolAddress((void**)&fh,   g_f_hi);   cudaGetSymbolAddress((void**)&fl,   g_f_lo);
    cudaGetSymbolAddress((void**)&qh_,  g_qh);     cudaGetSymbolAddress((void**)&ql_,  g_ql);
    cudaGetSymbolAddress((void**)&kh_,  g_kh);     cudaGetSymbolAddress((void**)&kl_,  g_kl);
    cudaGetSymbolAddress((void**)&vh_,  g_vh);     cudaGetSymbolAddress((void**)&vl_,  g_vl);

    cudaFuncSetAttribute(mm_gemm128<2>, cudaFuncAttributeMaxDynamicSharedMemorySize, GSMEM16);
    cudaFuncSetAttribute(mm_gemm128<3>, cudaFuncAttributeMaxDynamicSharedMemorySize, GSMEM16);
    cudaFuncSetAttribute(mm_gemm_pk,    cudaFuncAttributeMaxDynamicSharedMemorySize, GSMEM16);
    cudaFuncSetAttribute(qkv_gemm,      cudaFuncAttributeMaxDynamicSharedMemorySize, GSMEM16);
    cudaFuncSetAttribute(flash_attn,    cudaFuncAttributeMaxDynamicSharedMemorySize, ATT_SMEM);

    // launch 0: embed
    embedcvt_kernel<<<(MTOK * DD + 255) / 256, 256>>>((const long long*)d_in[0], tok, pos);
    // launch 1: all weight splits
    {
        const int nD4 = LL * DD * DD / 4;
        const int nF4 = LL * FF * DD / 4;
        dim3 gw((nF4 + 255) / 256, 6);
        split_w_kernel<<<gw, 256>>>(
            (const float4*)d_in[3],  (__nv_bfloat162*)wqh, (__nv_bfloat162*)wql, nD4,
            (const float4*)d_in[5],  (__nv_bfloat162*)wkh, (__nv_bfloat162*)wkl, nD4,
            (const float4*)d_in[7],  (__nv_bfloat162*)wvh, (__nv_bfloat162*)wvl, nD4,
            (const float4*)d_in[9],  (__nv_bfloat162*)woh, (__nv_bfloat162*)wol, nD4,
            (const float4*)d_in[11], (__nv_bfloat162*)w1h, (__nv_bfloat162*)w1l, nF4,
            (const float4*)d_in[13], (__nv_bfloat162*)w2h, (__nv_bfloat162*)w2l, nF4);
    }

    dim3 gQKV(18, MTOK / 128);           // (18, 16)
    dim3 gPK(DD / 128, MTOK / 128, 3);   // (6, 16, 3)
    dim3 gF(FF / 128, MTOK / 128);       // (24, 16)
    dim3 gV(VV / 128, MTOK / 128);       // (250, 16)
    dim3 gA(SS / 64, HH, BB);            // (16, 12, 2)
    const int gLN = MTOK / 8;

    for (int l = 0; l < LL; l++) {
        const size_t wD = (size_t)l * DD * DD;
        if (l == 0)
            ln_kernel<<<gLN, 256>>>(h, ln1g, ln1b, ah, al);                 // launch 2
        else
            ln_res_kernel<<<gLN, 256>>>(h, pp, ln1g + l * DD, ln1b + l * DD, ah, al);
        qkv_gemm<<<gQKV, 256, GSMEM16>>>(ah, al, wqh + wD, wql + wD,        // launch 3 (l=0) — profiled
                                         wkh + wD, wkl + wD, wvh + wD, wvl + wD,
                                         bq + l * DD, bk + l * DD, bv + l * DD,
                                         qh_, ql_, kh_, kl_, vh_, vl_);
        flash_attn<<<gA, 128, ATT_SMEM>>>(qh_, ql_, kh_, kl_, vh_, vl_, ah, al);
        mm_gemm_pk<<<gPK, 256, GSMEM16>>>(ah, al, woh + wD, wol + wD,
                                          bo + l * DD, pp, DD, DD, DD / 3);
        ln_res_kernel<<<gLN, 256>>>(h, pp, ln2g + l * DD, ln2b + l * DD, ah, al);
        mm_gemm128<2><<<gF, 256, GSMEM16>>>(ah, al, w1h + (size_t)l * FF * DD,
                                            w1l + (size_t)l * FF * DD, b1 + l * FF,
                                            nullptr, fh, fl, FF, DD);
        mm_gemm_pk<<<gPK, 256, GSMEM16>>>(fh, fl, w2h + (size_t)l * DD * FF,
                                          w2l + (size_t)l * DD * FF, b2 + l * DD,
                                          pp, DD, FF, FF / 3);
    }

    {
        int n4 = VV * DD / 4;
        split_kernel<<<(n4 + 255) / 256, 256>>>((const float4*)tok,
            (__nv_bfloat162*)tokh, (__nv_bfloat162*)tokl, n4);
    }
    ln_res_kernel<<<gLN, 256>>>(h, pp, lnfg, lnfb, ah, al);
    mm_gemm128<3><<<gV, 256, GSMEM16>>>(ah, al, tokh, tokl, nullptr,
                                        out, nullptr, nullptr, VV, DD);
}

// round 10
// speedup vs baseline: 1.1183x; 1.0935x over previous
#include <cuda_runtime.h>
#include <cuda_bf16.h>
#include <cuda_fp16.h>
#include <cstdint>
#include <math.h>

#define BB 2
#define SS 1024
#define DD 768
#define HH 12
#define DK 64
#define FF 3072
#define LL 4
#define VV 32000
#define MTOK (BB*SS)   /* 2048 */

typedef __nv_bfloat16 bf16;

// ---------------- scratch ----------------------------------------------------
__device__ float g_h  [MTOK*DD];
__device__ float g_p  [3*MTOK*DD];        // split-K partials
__device__ __half g_t16 [VV*DD];          // tok_emb fp16 (LM head B)
__device__ __half g_e16h[MTOK*DD], g_e16l[MTOK*DD];   // final LN fp16 hi/lo
__device__ bf16 g_wq_hi [LL*DD*DD], g_wq_lo [LL*DD*DD];
__device__ bf16 g_wk_hi [LL*DD*DD], g_wk_lo [LL*DD*DD];
__device__ bf16 g_wv_hi [LL*DD*DD], g_wv_lo [LL*DD*DD];
__device__ bf16 g_wo_hi [LL*DD*DD], g_wo_lo [LL*DD*DD];
__device__ bf16 g_w1_hi [LL*FF*DD], g_w1_lo [LL*FF*DD];
__device__ bf16 g_w2_hi [LL*DD*FF], g_w2_lo [LL*DD*FF];
__device__ bf16 g_a_hi  [MTOK*DD],  g_a_lo  [MTOK*DD];
__device__ bf16 g_f_hi  [MTOK*FF],  g_f_lo  [MTOK*FF];
__device__ bf16 g_qh[MTOK*DD], g_ql[MTOK*DD];
__device__ bf16 g_kh[MTOK*DD], g_kl[MTOK*DD];
__device__ bf16 g_vh[MTOK*DD], g_vl[MTOK*DD];

// ---------------- helpers ----------------------------------------------------
__device__ __forceinline__ uint32_t smem_u32(const void* p) {
    uint32_t a;
    asm("{ .reg .u64 t; cvta.to.shared.u64 t, %1; cvt.u32.u64 %0, t; }" : "=r"(a) : "l"(p));
    return a;
}
__device__ __forceinline__ void cpasync16(uint32_t saddr, const void* gaddr) {
    asm volatile("cp.async.cg.shared.global [%0], [%1], 16;" :: "r"(saddr), "l"(gaddr));
}
#define CP_COMMIT() asm volatile("cp.async.commit_group;" ::: "memory")
#define CP_WAIT(N)  asm volatile("cp.async.wait_group %0;" :: "n"(N) : "memory")

__device__ __forceinline__ void ldsm4(uint32_t* r, uint32_t addr) {
    asm volatile("ldmatrix.sync.aligned.m8n8.x4.shared.b16 {%0,%1,%2,%3}, [%4];"
        : "=r"(r[0]), "=r"(r[1]), "=r"(r[2]), "=r"(r[3]) : "r"(addr));
}
__device__ __forceinline__ void ldsm4t(uint32_t* r, uint32_t addr) {
    asm volatile("ldmatrix.sync.aligned.m8n8.x4.trans.shared.b16 {%0,%1,%2,%3}, [%4];"
        : "=r"(r[0]), "=r"(r[1]), "=r"(r[2]), "=r"(r[3]) : "r"(addr));
}
__device__ __forceinline__ void mma16816(float* c, const uint32_t* a, const uint32_t* b) {
    asm volatile(
        "mma.sync.aligned.m16n8k16.row.col.f32.bf16.bf16.f32 "
        "{%0,%1,%2,%3}, {%4,%5,%6,%7}, {%8,%9}, {%0,%1,%2,%3};"
        : "+f"(c[0]), "+f"(c[1]), "+f"(c[2]), "+f"(c[3])
        : "r"(a[0]), "r"(a[1]), "r"(a[2]), "r"(a[3]), "r"(b[0]), "r"(b[1]));
}
__device__ __forceinline__ void mma16816h(float* c, const uint32_t* a, const uint32_t* b) {
    asm volatile(
        "mma.sync.aligned.m16n8k16.row.col.f32.f16.f16.f32 "
        "{%0,%1,%2,%3}, {%4,%5,%6,%7}, {%8,%9}, {%0,%1,%2,%3};"
        : "+f"(c[0]), "+f"(c[1]), "+f"(c[2]), "+f"(c[3])
        : "r"(a[0]), "r"(a[1]), "r"(a[2]), "r"(a[3]), "r"(b[0]), "r"(b[1]));
}
__device__ __forceinline__ void split1(float v, bf16& h, bf16& l) {
    h = __float2bfloat16(v);
    l = __float2bfloat16(v - __bfloat162float(h));
}
__device__ __forceinline__ void split1h(float v, __half& h, __half& l) {
    h = __float2half(v);
    l = __float2half(v - __half2float(h));
}
__device__ __forceinline__ uint32_t packbf(float v0, float v1) {
    __nv_bfloat162 p(__float2bfloat16(v0), __float2bfloat16(v1));
    return *(uint32_t*)&p;
}

// ---------------- embed (inline int64/int32 token detection) -----------------
__global__ void embedcvt_kernel(const long long* __restrict__ x64,
                                const float* __restrict__ tok,
                                const float* __restrict__ pos) {
    __shared__ int is64s;
    if (threadIdx.x == 0) {
        int ok = 1;
        for (int i = 0; i < 16; i++) { long long t = x64[i]; if (t < 0 || t >= VV) ok = 0; }
        is64s = ok;
    }
    __syncthreads();
    int idx = blockIdx.x * blockDim.x + threadIdx.x;
    if (idx < MTOK * DD) {
        int d = idx % DD, t = idx / DD, s = t % SS;
        int tokid = is64s ? (int)x64[t] : ((const int*)x64)[t];
        g_h[idx] = tok[tokid * DD + d] + pos[s * DD + d];
    }
}

// ---------------- warp-per-row layernorm -> bf16 hi/lo -----------------------
__global__ __launch_bounds__(256)
void ln_kernel(const float* __restrict__ in, const float* __restrict__ g,
               const float* __restrict__ b,
               bf16* __restrict__ ohi, bf16* __restrict__ olo) {
    const int wid = threadIdx.x >> 5, lane = threadIdx.x & 31;
    const int row = blockIdx.x * 8 + wid;
    const float4* xr = (const float4*)(in + (size_t)row * DD);
    float4 v[6];
    float s1 = 0.f, s2 = 0.f;
#pragma unroll
    for (int i = 0; i < 6; i++) {
        v[i] = xr[lane + 32 * i];
        s1 += v[i].x + v[i].y + v[i].z + v[i].w;
        s2 += v[i].x*v[i].x + v[i].y*v[i].y + v[i].z*v[i].z + v[i].w*v[i].w;
    }
#pragma unroll
    for (int o = 16; o > 0; o >>= 1) {
        s1 += __shfl_xor_sync(0xffffffffu, s1, o);
        s2 += __shfl_xor_sync(0xffffffffu, s2, o);
    }
    float mu = s1 * (1.0f / DD);
    float inv = rsqrtf(s2 * (1.0f / DD) - mu * mu + 1e-5f);
    const float4* gg = (const float4*)g;
    const float4* bb = (const float4*)b;
#pragma unroll
    for (int i = 0; i < 6; i++) {
        int e4 = lane + 32 * i;
        float4 gv = gg[e4], bv = bb[e4];
        float o0 = (v[i].x - mu) * inv * gv.x + bv.x;
        float o1 = (v[i].y - mu) * inv * gv.y + bv.y;
        float o2 = (v[i].z - mu) * inv * gv.z + bv.z;
        float o3 = (v[i].w - mu) * inv * gv.w + bv.w;
        bf16 h0,l0,h1,l1,h2,l2,h3,l3;
        split1(o0,h0,l0); split1(o1,h1,l1); split1(o2,h2,l2); split1(o3,h3,l3);
        size_t base = (size_t)row * DD + e4 * 4;
        *(__nv_bfloat162*)&ohi[base]     = __nv_bfloat162(h0, h1);
        *(__nv_bfloat162*)&ohi[base + 2] = __nv_bfloat162(h2, h3);
        *(__nv_bfloat162*)&olo[base]     = __nv_bfloat162(l0, l1);
        *(__nv_bfloat162*)&olo[base + 2] = __nv_bfloat162(l2, l3);
    }
}

__global__ __launch_bounds__(256)
void ln_res_kernel(float* __restrict__ h, const float* __restrict__ p,
                   const float* __restrict__ g, const float* __restrict__ b,
                   bf16* __restrict__ ohi, bf16* __restrict__ olo) {
    const int wid = threadIdx.x >> 5, lane = threadIdx.x & 31;
    const int row = blockIdx.x * 8 + wid;
    float4* hr = (float4*)(h + (size_t)row * DD);
    const float4* p0 = (const float4*)(p + (size_t)row * DD);
    const float4* p1 = (const float4*)(p + (size_t)MTOK * DD + (size_t)row * DD);
    const float4* p2 = (const float4*)(p + 2 * (size_t)MTOK * DD + (size_t)row * DD);
    float4 v[6];
    float s1 = 0.f, s2 = 0.f;
#pragma unroll
    for (int i = 0; i < 6; i++) {
        int e4 = lane + 32 * i;
        float4 hv = hr[e4], a0 = p0[e4], a1 = p1[e4], a2 = p2[e4];
        hv.x += a0.x + a1.x + a2.x;
        hv.y += a0.y + a1.y + a2.y;
        hv.z += a0.z + a1.z + a2.z;
        hv.w += a0.w + a1.w + a2.w;
        hr[e4] = hv;
        v[i] = hv;
        s1 += hv.x + hv.y + hv.z + hv.w;
        s2 += hv.x*hv.x + hv.y*hv.y + hv.z*hv.z + hv.w*hv.w;
    }
#pragma unroll
    for (int o = 16; o > 0; o >>= 1) {
        s1 += __shfl_xor_sync(0xffffffffu, s1, o);
        s2 += __shfl_xor_sync(0xffffffffu, s2, o);
    }
    float mu = s1 * (1.0f / DD);
    float inv = rsqrtf(s2 * (1.0f / DD) - mu * mu + 1e-5f);
    const float4* gg = (const float4*)g;
    const float4* bb = (const float4*)b;
#pragma unroll
    for (int i = 0; i < 6; i++) {
        int e4 = lane + 32 * i;
        float4 gv = gg[e4], bv = bb[e4];
        float o0 = (v[i].x - mu) * inv * gv.x + bv.x;
        float o1 = (v[i].y - mu) * inv * gv.y + bv.y;
        float o2 = (v[i].z - mu) * inv * gv.z + bv.z;
        float o3 = (v[i].w - mu) * inv * gv.w + bv.w;
        bf16 h0,l0,h1,l1,h2,l2,h3,l3;
        split1(o0,h0,l0); split1(o1,h1,l1); split1(o2,h2,l2); split1(o3,h3,l3);
        size_t base = (size_t)row * DD + e4 * 4;
        *(__nv_bfloat162*)&ohi[base]     = __nv_bfloat162(h0, h1);
        *(__nv_bfloat162*)&ohi[base + 2] = __nv_bfloat162(h2, h3);
        *(__nv_bfloat162*)&olo[base]     = __nv_bfloat162(l0, l1);
        *(__nv_bfloat162*)&olo[base + 2] = __nv_bfloat162(l2, l3);
    }
}

// final LN: h += partials, LN -> fp16 hi/lo (for fp16 LM head)
__global__ __launch_bounds__(256)
void ln_res16_kernel(float* __restrict__ h, const float* __restrict__ p,
                     const float* __restrict__ g, const float* __restrict__ b,
                     __half* __restrict__ ohi, __half* __restrict__ olo) {
    const int wid = threadIdx.x >> 5, lane = threadIdx.x & 31;
    const int row = blockIdx.x * 8 + wid;
    float4* hr = (float4*)(h + (size_t)row * DD);
    const float4* p0 = (const float4*)(p + (size_t)row * DD);
    const float4* p1 = (const float4*)(p + (size_t)MTOK * DD + (size_t)row * DD);
    const float4* p2 = (const float4*)(p + 2 * (size_t)MTOK * DD + (size_t)row * DD);
    float4 v[6];
    float s1 = 0.f, s2 = 0.f;
#pragma unroll
    for (int i = 0; i < 6; i++) {
        int e4 = lane + 32 * i;
        float4 hv = hr[e4], a0 = p0[e4], a1 = p1[e4], a2 = p2[e4];
        hv.x += a0.x + a1.x + a2.x;
        hv.y += a0.y + a1.y + a2.y;
        hv.z += a0.z + a1.z + a2.z;
        hv.w += a0.w + a1.w + a2.w;
        v[i] = hv;
        s1 += hv.x + hv.y + hv.z + hv.w;
        s2 += hv.x*hv.x + hv.y*hv.y + hv.z*hv.z + hv.w*hv.w;
    }
#pragma unroll
    for (int o = 16; o > 0; o >>= 1) {
        s1 += __shfl_xor_sync(0xffffffffu, s1, o);
        s2 += __shfl_xor_sync(0xffffffffu, s2, o);
    }
    float mu = s1 * (1.0f / DD);
    float inv = rsqrtf(s2 * (1.0f / DD) - mu * mu + 1e-5f);
    const float4* gg = (const float4*)g;
    const float4* bb = (const float4*)b;
#pragma unroll
    for (int i = 0; i < 6; i++) {
        int e4 = lane + 32 * i;
        float4 gv = gg[e4], bv = bb[e4];
        float o0 = (v[i].x - mu) * inv * gv.x + bv.x;
        float o1 = (v[i].y - mu) * inv * gv.y + bv.y;
        float o2 = (v[i].z - mu) * inv * gv.z + bv.z;
        float o3 = (v[i].w - mu) * inv * gv.w + bv.w;
        __half h0,l0,h1,l1,h2,l2,h3,l3;
        split1h(o0,h0,l0); split1h(o1,h1,l1); split1h(o2,h2,l2); split1h(o3,h3,l3);
        size_t base = (size_t)row * DD + e4 * 4;
        *(__half2*)&ohi[base]     = __half2(h0, h1);
        *(__half2*)&ohi[base + 2] = __half2(h2, h3);
        *(__half2*)&olo[base]     = __half2(l0, l1);
        *(__half2*)&olo[base + 2] = __half2(l2, l3);
    }
}

// ---------------- fp32 -> bf16 hi/lo splits ----------------------------------
__device__ __forceinline__ void split4_body(const float4* x, __nv_bfloat162* hi,
                                            __nv_bfloat162* lo, int i) {
    float4 v = x[i];
    bf16 hx, lx, hy, ly, hz, lz, hw, lw;
    split1(v.x, hx, lx); split1(v.y, hy, ly);
    split1(v.z, hz, lz); split1(v.w, hw, lw);
    hi[2*i]   = __nv_bfloat162(hx, hy);
    hi[2*i+1] = __nv_bfloat162(hz, hw);
    lo[2*i]   = __nv_bfloat162(lx, ly);
    lo[2*i+1] = __nv_bfloat162(lz, lw);
}

// fp32 -> fp16 plain convert (tok_emb for LM head)
__global__ void cvt16_kernel(const float4* __restrict__ x, __half2* __restrict__ o, int n4) {
    int i = blockIdx.x * blockDim.x + threadIdx.x;
    if (i < n4) {
        float4 v = x[i];
        o[2*i]   = __floats2half2_rn(v.x, v.y);
        o[2*i+1] = __floats2half2_rn(v.z, v.w);
    }
}

__global__ void split_w_kernel(
        const float4* s0, __nv_bfloat162* h0, __nv_bfloat162* l0, int n0,
        const float4* s1, __nv_bfloat162* h1, __nv_bfloat162* l1, int n1,
        const float4* s2, __nv_bfloat162* h2, __nv_bfloat162* l2, int n2,
        const float4* s3, __nv_bfloat162* h3, __nv_bfloat162* l3, int n3,
        const float4* s4, __nv_bfloat162* h4, __nv_bfloat162* l4, int n4_,
        const float4* s5, __nv_bfloat162* h5, __nv_bfloat162* l5, int n5) {
    const float4* s; __nv_bfloat162* h; __nv_bfloat162* l; int n;
    switch (blockIdx.y) {
        case 0: s = s0; h = h0; l = l0; n = n0; break;
        case 1: s = s1; h = h1; l = l1; n = n1; break;
        case 2: s = s2; h = h2; l = l2; n = n2; break;
        case 3: s = s3; h = h3; l = l3; n = n3; break;
        case 4: s = s4; h = h4; l = l4; n = n4_; break;
        default: s = s5; h = h5; l = l5; n = n5; break;
    }
    int i = blockIdx.x * blockDim.x + threadIdx.x;
    if (i < n) split4_body(s, h, l, i);
}

// ---------------- split-bf16 mma.sync GEMM core ------------------------------
#define RB     48
#define TILE16 (128*RB)                  /* 6144 B  */
#define STG16  (4*TILE16)                /* 24576 B */
#define NSTG   4
#define GSMEM16 (NSTG*STG16)             /* 98304 B */

template<int EPI>
__device__ __forceinline__ void gemm_core(
        const bf16* Ahi, const bf16* Alo, const bf16* Bhi, const bf16* Blo,
        const float* bias, float sc,
        float* C, bf16* Chi, bf16* Clo,
        int m0, int n0, int N, int K, int ldk, uint32_t sb) {
    const int tid = threadIdx.x;
    const int wid = tid >> 5, lane = tid & 31;
    const int wm = (wid >> 2) * 64;
    const int wn = (wid & 3) * 32;

    float Cf[4][4][4];
#pragma unroll
    for (int i = 0; i < 4; i++)
#pragma unroll
        for (int j = 0; j < 4; j++)
#pragma unroll
            for (int x = 0; x < 4; x++) Cf[i][j][x] = 0.f;

    const int NS = K >> 4;
    const int a_row = (lane & 15);
    const int a_cs = ((lane >> 4) * 8) * 2;
    const int b_row = (lane & 7) + ((lane >> 4) & 1) * 8;
    const int b_cs = (((lane >> 3) & 1) * 8) * 2;
    const int lr = tid >> 1;
    const int lc = tid & 1;

#define LOAD_STG(S_)                                                            \
    do {                                                                        \
        const int k0_ = (S_) << 4;                                              \
        uint32_t tb = sb + ((S_) & (NSTG - 1)) * STG16 + lr * RB + lc * 16;     \
        const int ac_ = k0_ + lc * 8;                                           \
        cpasync16(tb,              Ahi + (size_t)(m0 + lr) * ldk + ac_);        \
        cpasync16(tb + TILE16,     Alo + (size_t)(m0 + lr) * ldk + ac_);        \
        cpasync16(tb + 2 * TILE16, Bhi + (size_t)(n0 + lr) * ldk + ac_);        \
        cpasync16(tb + 3 * TILE16, Blo + (size_t)(n0 + lr) * ldk + ac_);        \
    } while (0)

#pragma unroll
    for (int s = 0; s < NSTG - 1; s++) { LOAD_STG(s); CP_COMMIT(); }

    for (int s = 0; s < NS; s++) {
        CP_WAIT(NSTG - 2);
        __syncthreads();

        const uint32_t st = sb + (s & (NSTG - 1)) * STG16;
        const uint32_t tAh = st;
        const uint32_t tAl = st + TILE16;
        const uint32_t tBh = st + 2 * TILE16;
        const uint32_t tBl = st + 3 * TILE16;

        uint32_t Aany[4][4], Bh[2][4], Bl[2][4];
#pragma unroll
        for (int mf = 0; mf < 4; mf++)
            ldsm4(Aany[mf], tAh + (wm + mf * 16 + a_row) * RB + a_cs);
#pragma unroll
        for (int p = 0; p < 2; p++) {
            ldsm4(Bh[p], tBh + (wn + p * 16 + b_row) * RB + b_cs);
            ldsm4(Bl[p], tBl + (wn + p * 16 + b_row) * RB + b_cs);
        }
#pragma unroll
        for (int mf = 0; mf < 4; mf++)
#pragma unroll
            for (int nf = 0; nf < 4; nf++)
                mma16816(Cf[mf][nf], Aany[mf], &Bh[nf >> 1][(nf & 1) * 2]);
#pragma unroll
        for (int mf = 0; mf < 4; mf++)
#pragma unroll
            for (int nf = 0; nf < 4; nf++)
                mma16816(Cf[mf][nf], Aany[mf], &Bl[nf >> 1][(nf & 1) * 2]);
#pragma unroll
        for (int mf = 0; mf < 4; mf++)
            ldsm4(Aany[mf], tAl + (wm + mf * 16 + a_row) * RB + a_cs);
#pragma unroll
        for (int mf = 0; mf < 4; mf++)
#pragma unroll
            for (int nf = 0; nf < 4; nf++)
                mma16816(Cf[mf][nf], Aany[mf], &Bh[nf >> 1][(nf & 1) * 2]);

        if (s + NSTG - 1 < NS) LOAD_STG(s + NSTG - 1);
        CP_COMMIT();
    }
#undef LOAD_STG

    const int g = lane >> 2, t2 = (lane & 3) * 2;
#pragma unroll
    for (int mf = 0; mf < 4; mf++) {
#pragma unroll
        for (int nf = 0; nf < 4; nf++) {
            int n = n0 + wn + nf * 8 + t2;
#pragma unroll
            for (int hrow = 0; hrow < 2; hrow++) {
                int m = m0 + wm + mf * 16 + g + hrow * 8;
                float v0 = Cf[mf][nf][hrow * 2 + 0];
                float v1 = Cf[mf][nf][hrow * 2 + 1];
                if (EPI == 0) {
                    if (bias) { v0 += bias[n]; v1 += bias[n + 1]; }
                } else {
                    v0 += bias[n]; v1 += bias[n + 1];
                }
                if (EPI == 2 || EPI == 4) {
                    if (EPI == 2) { v0 = fmaxf(v0, 0.f); v1 = fmaxf(v1, 0.f); }
                    else          { v0 *= sc; v1 *= sc; }
                    bf16 h0, l0, h1, l1;
                    split1(v0, h0, l0); split1(v1, h1, l1);
                    *(__nv_bfloat162*)&Chi[(size_t)m * N + n] = __nv_bfloat162(h0, h1);
                    *(__nv_bfloat162*)&Clo[(size_t)m * N + n] = __nv_bfloat162(l0, l1);
                } else {
                    *(float2*)&C[(size_t)m * N + n] = make_float2(v0, v1);
                }
            }
        }
    }
}

template<int EPI>
__global__ __launch_bounds__(256, 2)
void mm_gemm128(const bf16* __restrict__ Ahi, const bf16* __restrict__ Alo,
                const bf16* __restrict__ Bhi, const bf16* __restrict__ Blo,
                const float* __restrict__ bias,
                float* __restrict__ C, bf16* __restrict__ Chi, bf16* __restrict__ Clo,
                int N, int K) {
    extern __shared__ char smem_raw[];
    gemm_core<EPI>(Ahi, Alo, Bhi, Blo, bias, 1.0f, C, Chi, Clo,
                   blockIdx.y * 128, blockIdx.x * 128, N, K, K, smem_u32(smem_raw));
}

__global__ __launch_bounds__(256, 2)
void mm_gemm_pk(const bf16* __restrict__ Ahi, const bf16* __restrict__ Alo,
                const bf16* __restrict__ Bhi, const bf16* __restrict__ Blo,
                const float* __restrict__ bias, float* __restrict__ P,
                int N, int Kfull, int Ks) {
    extern __shared__ char smem_raw[];
    const int z = blockIdx.z;
    const int k0 = z * Ks;
    gemm_core<0>(Ahi + k0, Alo + k0, Bhi + k0, Blo + k0,
                 z == 0 ? bias : nullptr, 1.0f,
                 P + (size_t)z * MTOK * N, nullptr, nullptr,
                 blockIdx.y * 128, blockIdx.x * 128, N, Ks, Kfull, smem_u32(smem_raw));
}

__global__ __launch_bounds__(256, 2)
void qkv_gemm(const bf16* __restrict__ Ahi, const bf16* __restrict__ Alo,
              const bf16* __restrict__ wqh, const bf16* __restrict__ wql,
              const bf16* __restrict__ wkh, const bf16* __restrict__ wkl,
              const bf16* __restrict__ wvh, const bf16* __restrict__ wvl,
              const float* __restrict__ bq, const float* __restrict__ bk,
              const float* __restrict__ bv,
              bf16* __restrict__ qh, bf16* __restrict__ ql,
              bf16* __restrict__ kh, bf16* __restrict__ kl,
              bf16* __restrict__ vh, bf16* __restrict__ vl) {
    extern __shared__ char smem_raw[];
    const int which = blockIdx.x / 6, nb = blockIdx.x % 6;
    const bf16* Bh = (which == 0) ? wqh : (which == 1) ? wkh : wvh;
    const bf16* Bl = (which == 0) ? wql : (which == 1) ? wkl : wvl;
    const float* bias = (which == 0) ? bq : (which == 1) ? bk : bv;
    bf16* Ch = (which == 0) ? qh : (which == 1) ? kh : vh;
    bf16* Cl = (which == 0) ? ql : (which == 1) ? kl : vl;
    float sc = (which == 0) ? 0.125f : 1.0f;
    gemm_core<4>(Ahi, Alo, Bh, Bl, bias, sc, nullptr, Ch, Cl,
                 blockIdx.y * 128, nb * 128, DD, DD, DD, smem_u32(smem_raw));
}

// ---------------- fp16 2-pass LM head GEMM -----------------------------------
// C = (Ah+Al) @ Bh^T : A exact fp16 split, B fp16-rounded. 3 tiles/stage.
#define LSTG   (3*TILE16)                /* 18432 */
#define GSMEM_LM (NSTG*LSTG)             /* 73728 */

__global__ __launch_bounds__(256, 2)
void lm_gemm(const __half* __restrict__ Ah, const __half* __restrict__ Al,
             const __half* __restrict__ Bh, float* __restrict__ C,
             int N, int K) {
    extern __shared__ char smem_raw[];
    const uint32_t sb = smem_u32(smem_raw);
    const int tid = threadIdx.x;
    const int wid = tid >> 5, lane = tid & 31;
    const int m0 = blockIdx.y * 128, n0 = blockIdx.x * 128;
    const int wm = (wid >> 2) * 64;
    const int wn = (wid & 3) * 32;

    float Cf[4][4][4];
#pragma unroll
    for (int i = 0; i < 4; i++)
#pragma unroll
        for (int j = 0; j < 4; j++)
#pragma unroll
            for (int x = 0; x < 4; x++) Cf[i][j][x] = 0.f;

    const int NS = K >> 4;
    const int a_row = (lane & 15);
    const int a_cs = ((lane >> 4) * 8) * 2;
    const int b_row = (lane & 7) + ((lane >> 4) & 1) * 8;
    const int b_cs = (((lane >> 3) & 1) * 8) * 2;
    const int lr = tid >> 1;
    const int lc = tid & 1;

#define LOAD_LM(S_)                                                             \
    do {                                                                        \
        const int k0_ = (S_) << 4;                                              \
        uint32_t tb = sb + ((S_) & (NSTG - 1)) * LSTG + lr * RB + lc * 16;      \
        const int ac_ = k0_ + lc * 8;                                           \
        cpasync16(tb,              Ah + (size_t)(m0 + lr) * K + ac_);           \
        cpasync16(tb + TILE16,     Al + (size_t)(m0 + lr) * K + ac_);           \
        cpasync16(tb + 2 * TILE16, Bh + (size_t)(n0 + lr) * K + ac_);           \
    } while (0)

#pragma unroll
    for (int s = 0; s < NSTG - 1; s++) { LOAD_LM(s); CP_COMMIT(); }

    for (int s = 0; s < NS; s++) {
        CP_WAIT(NSTG - 2);
        __syncthreads();

        const uint32_t st = sb + (s & (NSTG - 1)) * LSTG;
        const uint32_t tAh = st;
        const uint32_t tAl = st + TILE16;
        const uint32_t tBh = st + 2 * TILE16;

        uint32_t Af[4][4], Bf[2][4];
#pragma unroll
        for (int mf = 0; mf < 4; mf++)
            ldsm4(Af[mf], tAh + (wm + mf * 16 + a_row) * RB + a_cs);
#pragma unroll
        for (int p = 0; p < 2; p++)
            ldsm4(Bf[p], tBh + (wn + p * 16 + b_row) * RB + b_cs);
#pragma unroll
        for (int mf = 0; mf < 4; mf++)
#pragma unroll
            for (int nf = 0; nf < 4; nf++)
                mma16816h(Cf[mf][nf], Af[mf], &Bf[nf >> 1][(nf & 1) * 2]);
#pragma unroll
        for (int mf = 0; mf < 4; mf++)
            ldsm4(Af[mf], tAl + (wm + mf * 16 + a_row) * RB + a_cs);
#pragma unroll
        for (int mf = 0; mf < 4; mf++)
#pragma unroll
            for (int nf = 0; nf < 4; nf++)
                mma16816h(Cf[mf][nf], Af[mf], &Bf[nf >> 1][(nf & 1) * 2]);

        if (s + NSTG - 1 < NS) LOAD_LM(s + NSTG - 1);
        CP_COMMIT();
    }
#undef LOAD_LM

    const int g = lane >> 2, t2 = (lane & 3) * 2;
#pragma unroll
    for (int mf = 0; mf < 4; mf++) {
#pragma unroll
        for (int nf = 0; nf < 4; nf++) {
            int n = n0 + wn + nf * 8 + t2;
#pragma unroll
            for (int hrow = 0; hrow < 2; hrow++) {
                int m = m0 + wm + mf * 16 + g + hrow * 8;
                *(float2*)&C[(size_t)m * N + n] =
                    make_float2(Cf[mf][nf][hrow * 2], Cf[mf][nf][hrow * 2 + 1]);
            }
        }
    }
}

// ---------------- MMA flash attention (64-query, 128 threads) ----------------
#define AST 144
#define ATILE (64*AST)
#define ATT_SMEM (2*ATILE + 2*4*ATILE)   /* 92160 */

__device__ __forceinline__ void att_load4(uint32_t dst, const bf16* src,
                                          size_t grow0, int hcol, int tid) {
    int r = tid >> 1, c0 = (tid & 1) * 4;
    const bf16* p = src + (grow0 + r) * DD + hcol + c0 * 8;
    uint32_t d = dst + r * AST + c0 * 16;
#pragma unroll
    for (int i = 0; i < 4; i++) cpasync16(d + i * 16, p + i * 8);
}

__global__ __launch_bounds__(128)
void flash_attn(const bf16* __restrict__ qh, const bf16* __restrict__ ql,
                const bf16* __restrict__ kh, const bf16* __restrict__ kl,
                const bf16* __restrict__ vh, const bf16* __restrict__ vl,
                bf16* __restrict__ chi, bf16* __restrict__ clo) {
    const int qt = gridDim.x - 1 - blockIdx.x;
    const int hd = blockIdx.y, b = blockIdx.z;
    extern __shared__ char smc[];
    const uint32_t sb = smem_u32(smc);
    const uint32_t Qh_s = sb, Ql_s = sb + ATILE;
    const uint32_t KV = sb + 2 * ATILE;

    const int tid = threadIdx.x, wid = tid >> 5, lane = tid & 31;
    const size_t qrow0 = (size_t)(b * SS + qt * 64);
    const int hcol = hd * DK;

    att_load4(Qh_s, qh, qrow0, hcol, tid);
    att_load4(Ql_s, ql, qrow0, hcol, tid);
    {
        size_t kr = (size_t)(b * SS);
        att_load4(KV + 0 * ATILE, kh, kr, hcol, tid);
        att_load4(KV + 1 * ATILE, kl, kr, hcol, tid);
        att_load4(KV + 2 * ATILE, vh, kr, hcol, tid);
        att_load4(KV + 3 * ATILE, vl, kr, hcol, tid);
    }
    CP_COMMIT();

    float O[8][4];
    float mrow[2] = { -1e30f, -1e30f };
    float lrow[2] = { 0.f, 0.f };
#pragma unroll
    for (int nt = 0; nt < 8; nt++)
#pragma unroll
        for (int x = 0; x < 4; x++) O[nt][x] = 0.f;

    const int g = lane >> 2, t2q = (lane & 3) * 2;
    const int a_row = wid * 16 + (lane & 15);
    const uint32_t a_cs = ((lane >> 4) << 3) * 2;
    const int b_row = (lane & 7) + (((lane >> 4) & 1) << 3);
    const uint32_t b_cs = (((lane >> 3) & 1) << 3) * 2;
    const int v_row = (lane & 15);
    const uint32_t v_cs = ((lane >> 4) << 3) * 2;

    for (int jt = 0; jt <= qt; jt++) {
        if (jt < qt) {
            size_t kr = (size_t)(b * SS + (jt + 1) * 64);
            uint32_t nb = KV + ((jt + 1) & 1) * (4 * ATILE);
            att_load4(nb + 0 * ATILE, kh, kr, hcol, tid);
            att_load4(nb + 1 * ATILE, kl, kr, hcol, tid);
            att_load4(nb + 2 * ATILE, vh, kr, hcol, tid);
            att_load4(nb + 3 * ATILE, vl, kr, hcol, tid);
            CP_COMMIT();
            CP_WAIT(1);
        } else {
            CP_WAIT(0);
        }
        __syncthreads();

        const uint32_t Kh_s = KV + (jt & 1) * (4 * ATILE);
        const uint32_t Kl_s = Kh_s + ATILE;
        const uint32_t Vh_s = Kl_s + ATILE;
        const uint32_t Vl_s = Vh_s + ATILE;

        float S[8][4];
#pragma unroll
        for (int nt = 0; nt < 8; nt++)
#pragma unroll
            for (int x = 0; x < 4; x++) S[nt][x] = 0.f;

#pragma unroll
        for (int ks = 0; ks < 4; ks++) {
            uint32_t Ahh[4], All[4];
            ldsm4(Ahh, Qh_s + a_row * AST + ks * 32 + a_cs);
            ldsm4(All, Ql_s + a_row * AST + ks * 32 + a_cs);
#pragma unroll
            for (int p = 0; p < 2; p++) {
                uint32_t Bh4[4], Bl4[4];
                ldsm4(Bh4, Kh_s + (p * 16 + b_row) * AST + ks * 32 + b_cs);
                ldsm4(Bl4, Kl_s + (p * 16 + b_row) * AST + ks * 32 + b_cs);
#pragma unroll
                for (int q = 0; q < 2; q++) {
                    mma16816(S[p * 2 + q], Ahh, &Bh4[q * 2]);
                    mma16816(S[p * 2 + q], Ahh, &Bl4[q * 2]);
                    mma16816(S[p * 2 + q], All, &Bh4[q * 2]);
                }
                uint32_t Bh4b[4], Bl4b[4];
                ldsm4(Bh4b, Kh_s + ((p + 2) * 16 + b_row) * AST + ks * 32 + b_cs);
                ldsm4(Bl4b, Kl_s + ((p + 2) * 16 + b_row) * AST + ks * 32 + b_cs);
#pragma unroll
                for (int q = 0; q < 2; q++) {
                    mma16816(S[(p + 2) * 2 + q], Ahh, &Bh4b[q * 2]);
                    mma16816(S[(p + 2) * 2 + q], Ahh, &Bl4b[q * 2]);
                    mma16816(S[(p + 2) * 2 + q], All, &Bh4b[q * 2]);
                }
            }
        }

        const bool diag = (jt == qt);
#pragma unroll
        for (int half = 0; half < 2; half++) {
            const int rloc = wid * 16 + g + half * 8;
            float mt = -1e30f;
#pragma unroll
            for (int nt = 0; nt < 8; nt++) {
                float s0 = S[nt][half * 2], s1 = S[nt][half * 2 + 1];
                if (diag) {
                    if (nt * 8 + t2q > rloc)     s0 = -1e30f;
                    if (nt * 8 + t2q + 1 > rloc) s1 = -1e30f;
                }
                S[nt][half * 2] = s0; S[nt][half * 2 + 1] = s1;
                mt = fmaxf(mt, fmaxf(s0, s1));
            }
            mt = fmaxf(mt, __shfl_xor_sync(0xffffffffu, mt, 1));
            mt = fmaxf(mt, __shfl_xor_sync(0xffffffffu, mt, 2));
            float mn = fmaxf(mrow[half], mt);
            float f = __expf(mrow[half] - mn);
            mrow[half] = mn;
            float rs = 0.f;
#pragma unroll
            for (int nt = 0; nt < 8; nt++) {
                float e0 = __expf(S[nt][half * 2] - mn);
                float e1 = __expf(S[nt][half * 2 + 1] - mn);
                S[nt][half * 2] = e0; S[nt][half * 2 + 1] = e1;
                rs += e0 + e1;
            }
            rs += __shfl_xor_sync(0xffffffffu, rs, 1);
            rs += __shfl_xor_sync(0xffffffffu, rs, 2);
            lrow[half] = lrow[half] * f + rs;
#pragma unroll
            for (int nt = 0; nt < 8; nt++) {
                O[nt][half * 2] *= f; O[nt][half * 2 + 1] *= f;
            }
        }

#pragma unroll
        for (int ks = 0; ks < 4; ks++) {
            uint32_t Ph[4], Pl[4];
#pragma unroll
            for (int q4 = 0; q4 < 4; q4++) {
                int tile = 2 * ks + (q4 >> 1);
                int o = (q4 & 1) * 2;
                float v0 = S[tile][o], v1 = S[tile][o + 1];
                bf16 h0 = __float2bfloat16(v0), h1 = __float2bfloat16(v1);
                __nv_bfloat162 hh(h0, h1);
                Ph[q4] = *(uint32_t*)&hh;
                Pl[q4] = packbf(v0 - __bfloat162float(h0), v1 - __bfloat162float(h1));
            }
#pragma unroll
            for (int nt = 0; nt < 4; nt++) {
                uint32_t Vh4[4], Vl4[4];
                ldsm4t(Vh4, Vh_s + (ks * 16 + v_row) * AST + nt * 32 + v_cs);
                ldsm4t(Vl4, Vl_s + (ks * 16 + v_row) * AST + nt * 32 + v_cs);
#pragma unroll
                for (int q = 0; q < 2; q++) {
                    mma16816(O[nt * 2 + q], Ph, &Vh4[q * 2]);
                    mma16816(O[nt * 2 + q], Ph, &Vl4[q * 2]);
                    mma16816(O[nt * 2 + q], Pl, &Vh4[q * 2]);
                }
            }
        }
        __syncthreads();
    }

    float inv[2] = { 1.0f / lrow[0], 1.0f / lrow[1] };
#pragma unroll
    for (int nt = 0; nt < 8; nt++) {
#pragma unroll
        for (int half = 0; half < 2; half++) {
            size_t row = qrow0 + wid * 16 + g + half * 8;
            int col = hcol + nt * 8 + t2q;
            float v0 = O[nt][half * 2] * inv[half];
            float v1 = O[nt][half * 2 + 1] * inv[half];
            bf16 h0, l0, h1, l1;
            split1(v0, h0, l0); split1(v1, h1, l1);
            *(__nv_bfloat162*)&chi[row * DD + col] = __nv_bfloat162(h0, h1);
            *(__nv_bfloat162*)&clo[row * DD + col] = __nv_bfloat162(l0, l1);
        }
    }
}

// ---------------- driver -----------------------------------------------------
extern "C" void kernel_launch(void* const* d_in, const int* in_sizes, int n_in,
                              void* d_out, int out_size) {
    (void)in_sizes; (void)n_in; (void)out_size;
    const float* tok  = (const float*)d_in[1];
    const float* pos  = (const float*)d_in[2];
    const float* bq   = (const float*)d_in[4];
    const float* bk   = (const float*)d_in[6];
    const float* bv   = (const float*)d_in[8];
    const float* bo   = (const float*)d_in[10];
    const float* b1   = (const float*)d_in[12];
    const float* b2   = (const float*)d_in[14];
    const float* ln1g = (const float*)d_in[15];
    const float* ln1b = (const float*)d_in[16];
    const float* ln2g = (const float*)d_in[17];
    const float* ln2b = (const float*)d_in[18];
    const float* lnfg = (const float*)d_in[19];
    const float* lnfb = (const float*)d_in[20];
    float* out = (float*)d_out;

    float *h, *pp;
    cudaGetSymbolAddress((void**)&h,  g_h);
    cudaGetSymbolAddress((void**)&pp, g_p);

    __half *t16, *e16h, *e16l;
    cudaGetSymbolAddress((void**)&t16,  g_t16);
    cudaGetSymbolAddress((void**)&e16h, g_e16h);
    cudaGetSymbolAddress((void**)&e16l, g_e16l);

    bf16 *wqh, *wql, *wkh, *wkl, *wvh, *wvl, *woh, *wol;
    bf16 *w1h, *w1l, *w2h, *w2l, *ah, *al, *fh, *fl;
    bf16 *qh_, *ql_, *kh_, *kl_, *vh_, *vl_;
    cudaGetSymbolAddress((void**)&wqh,  g_wq_hi);  cudaGetSymbolAddress((void**)&wql,  g_wq_lo);
    cudaGetSymbolAddress((void**)&wkh,  g_wk_hi);  cudaGetSymbolAddress((void**)&wkl,  g_wk_lo);
    cudaGetSymbolAddress((void**)&wvh,  g_wv_hi);  cudaGetSymbolAddress((void**)&wvl,  g_wv_lo);
    cudaGetSymbolAddress((void**)&woh,  g_wo_hi);  cudaGetSymbolAddress((void**)&wol,  g_wo_lo);
    cudaGetSymbolAddress((void**)&w1h,  g_w1_hi);  cudaGetSymbolAddress((void**)&w1l,  g_w1_lo);
    cudaGetSymbolAddress((void**)&w2h,  g_w2_hi);  cudaGetSymbolAddress((void**)&w2l,  g_w2_lo);
    cudaGetSymbolAddress((void**)&ah,   g_a_hi);   cudaGetSymbolAddress((void**)&al,   g_a_lo);
    cudaGetSymbolAddress((void**)&fh,   g_f_hi);   cudaGetSymbolAddress((void**)&fl,   g_f_lo);
    cudaGetSymbolAddress((void**)&qh_,  g_qh);     cudaGetSymbolAddress((void**)&ql_,  g_ql);
    cudaGetSymbolAddress((void**)&kh_,  g_kh);     cudaGetSymbolAddress((void**)&kl_,  g_kl);
    cudaGetSymbolAddress((void**)&vh_,  g_vh);     cudaGetSymbolAddress((void**)&vl_,  g_vl);

    cudaFuncSetAttribute(mm_gemm128<2>, cudaFuncAttributeMaxDynamicSharedMemorySize, GSMEM16);
    cudaFuncSetAttribute(mm_gemm_pk,    cudaFuncAttributeMaxDynamicSharedMemorySize, GSMEM16);
    cudaFuncSetAttribute(qkv_gemm,      cudaFuncAttributeMaxDynamicSharedMemorySize, GSMEM16);
    cudaFuncSetAttribute(lm_gemm,       cudaFuncAttributeMaxDynamicSharedMemorySize, GSMEM_LM);
    cudaFuncSetAttribute(flash_attn,    cudaFuncAttributeMaxDynamicSharedMemorySize, ATT_SMEM);

    // launch 0: embed
    embedcvt_kernel<<<(MTOK * DD + 255) / 256, 256>>>((const long long*)d_in[0], tok, pos);
    // launch 1: all weight splits
    {
        const int nD4 = LL * DD * DD / 4;
        const int nF4 = LL * FF * DD / 4;
        dim3 gw((nF4 + 255) / 256, 6);
        split_w_kernel<<<gw, 256>>>(
            (const float4*)d_in[3],  (__nv_bfloat162*)wqh, (__nv_bfloat162*)wql, nD4,
            (const float4*)d_in[5],  (__nv_bfloat162*)wkh, (__nv_bfloat162*)wkl, nD4,
            (const float4*)d_in[7],  (__nv_bfloat162*)wvh, (__nv_bfloat162*)wvl, nD4,
            (const float4*)d_in[9],  (__nv_bfloat162*)woh, (__nv_bfloat162*)wol, nD4,
            (const float4*)d_in[11], (__nv_bfloat162*)w1h, (__nv_bfloat162*)w1l, nF4,
            (const float4*)d_in[13], (__nv_bfloat162*)w2h, (__nv_bfloat162*)w2l, nF4);
    }

    dim3 gQKV(18, MTOK / 128);           // (18, 16)
    dim3 gPK(DD / 128, MTOK / 128, 3);   // (6, 16, 3)
    dim3 gF(FF / 128, MTOK / 128);       // (24, 16)
    dim3 gV(VV / 128, MTOK / 128);       // (250, 16)
    dim3 gA(SS / 64, HH, BB);            // (16, 12, 2)
    const int gLN = MTOK / 8;

    for (int l = 0; l < LL; l++) {
        const size_t wD = (size_t)l * DD * DD;
        if (l == 0)
            ln_kernel<<<gLN, 256>>>(h, ln1g, ln1b, ah, al);                 // launch 2
        else
            ln_res_kernel<<<gLN, 256>>>(h, pp, ln1g + l * DD, ln1b + l * DD, ah, al);
        qkv_gemm<<<gQKV, 256, GSMEM16>>>(ah, al, wqh + wD, wql + wD,        // launch 3 (l=0) — profiled
                                         wkh + wD, wkl + wD, wvh + wD, wvl + wD,
                                         bq + l * DD, bk + l * DD, bv + l * DD,
                                         qh_, ql_, kh_, kl_, vh_, vl_);
        flash_attn<<<gA, 128, ATT_SMEM>>>(qh_, ql_, kh_, kl_, vh_, vl_, ah, al);
        mm_gemm_pk<<<gPK, 256, GSMEM16>>>(ah, al, woh + wD, wol + wD,
                                          bo + l * DD, pp, DD, DD, DD / 3);
        ln_res_kernel<<<gLN, 256>>>(h, pp, ln2g + l * DD, ln2b + l * DD, ah, al);
        mm_gemm128<2><<<gF, 256, GSMEM16>>>(ah, al, w1h + (size_t)l * FF * DD,
                                            w1l + (size_t)l * FF * DD, b1 + l * FF,
                                            nullptr, fh, fl, FF, DD);
        mm_gemm_pk<<<gPK, 256, GSMEM16>>>(fh, fl, w2h + (size_t)l * DD * FF,
                                          w2l + (size_t)l * DD * FF, b2 + l * DD,
                                          pp, DD, FF, FF / 3);
    }

    // LM head: fp16 convert of tok_emb + fp16 split final LN + 2-pass GEMM
    {
        int n4 = VV * DD / 4;
        cvt16_kernel<<<(n4 + 255) / 256, 256>>>((const float4*)tok, (__half2*)t16, n4);
    }
    ln_res16_kernel<<<gLN, 256>>>(h, pp, lnfg, lnfb, e16h, e16l);
    lm_gemm<<<gV, 256, GSMEM_LM>>>(e16h, e16l, t16, out, VV, DD);
}

// round 11
// speedup vs baseline: 1.2189x; 1.0900x over previous
#include <cuda_runtime.h>
#include <cuda_bf16.h>
#include <cuda_fp16.h>
#include <cstdint>
#include <math.h>

#define BB 2
#define SS 1024
#define DD 768
#define HH 12
#define DK 64
#define FF 3072
#define LL 4
#define VV 32000
#define MTOK (BB*SS)   /* 2048 */

typedef __nv_bfloat16 bf16;

// ---------------- scratch ----------------------------------------------------
__device__ float g_h  [MTOK*DD];
__device__ float g_p  [3*MTOK*DD];        // split-K partials
__device__ __half g_t16 [VV*DD];          // tok_emb fp16 (LM head B)
__device__ __half g_e16h[MTOK*DD], g_e16l[MTOK*DD];   // fp16 LN outputs (ln1 + final)
__device__ __half g_w16q[LL*DD*DD], g_w16k[LL*DD*DD], g_w16v[LL*DD*DD];
__device__ __half g_q16h[MTOK*DD], g_q16l[MTOK*DD];
__device__ __half g_k16 [MTOK*DD], g_v16 [MTOK*DD];
__device__ bf16 g_wo_hi [LL*DD*DD], g_wo_lo [LL*DD*DD];
__device__ bf16 g_w1_hi [LL*FF*DD], g_w1_lo [LL*FF*DD];
__device__ bf16 g_w2_hi [LL*DD*FF], g_w2_lo [LL*DD*FF];
__device__ bf16 g_a_hi  [MTOK*DD],  g_a_lo  [MTOK*DD];   // ctx / ln2 outputs
__device__ bf16 g_f_hi  [MTOK*FF],  g_f_lo  [MTOK*FF];

// ---------------- helpers ----------------------------------------------------
__device__ __forceinline__ uint32_t smem_u32(const void* p) {
    uint32_t a;
    asm("{ .reg .u64 t; cvta.to.shared.u64 t, %1; cvt.u32.u64 %0, t; }" : "=r"(a) : "l"(p));
    return a;
}
__device__ __forceinline__ void cpasync16(uint32_t saddr, const void* gaddr) {
    asm volatile("cp.async.cg.shared.global [%0], [%1], 16;" :: "r"(saddr), "l"(gaddr));
}
#define CP_COMMIT() asm volatile("cp.async.commit_group;" ::: "memory")
#define CP_WAIT(N)  asm volatile("cp.async.wait_group %0;" :: "n"(N) : "memory")

__device__ __forceinline__ void ldsm4(uint32_t* r, uint32_t addr) {
    asm volatile("ldmatrix.sync.aligned.m8n8.x4.shared.b16 {%0,%1,%2,%3}, [%4];"
        : "=r"(r[0]), "=r"(r[1]), "=r"(r[2]), "=r"(r[3]) : "r"(addr));
}
__device__ __forceinline__ void ldsm4t(uint32_t* r, uint32_t addr) {
    asm volatile("ldmatrix.sync.aligned.m8n8.x4.trans.shared.b16 {%0,%1,%2,%3}, [%4];"
        : "=r"(r[0]), "=r"(r[1]), "=r"(r[2]), "=r"(r[3]) : "r"(addr));
}
__device__ __forceinline__ void mma16816(float* c, const uint32_t* a, const uint32_t* b) {
    asm volatile(
        "mma.sync.aligned.m16n8k16.row.col.f32.bf16.bf16.f32 "
        "{%0,%1,%2,%3}, {%4,%5,%6,%7}, {%8,%9}, {%0,%1,%2,%3};"
        : "+f"(c[0]), "+f"(c[1]), "+f"(c[2]), "+f"(c[3])
        : "r"(a[0]), "r"(a[1]), "r"(a[2]), "r"(a[3]), "r"(b[0]), "r"(b[1]));
}
__device__ __forceinline__ void mma16816h(float* c, const uint32_t* a, const uint32_t* b) {
    asm volatile(
        "mma.sync.aligned.m16n8k16.row.col.f32.f16.f16.f32 "
        "{%0,%1,%2,%3}, {%4,%5,%6,%7}, {%8,%9}, {%0,%1,%2,%3};"
        : "+f"(c[0]), "+f"(c[1]), "+f"(c[2]), "+f"(c[3])
        : "r"(a[0]), "r"(a[1]), "r"(a[2]), "r"(a[3]), "r"(b[0]), "r"(b[1]));
}
__device__ __forceinline__ void split1(float v, bf16& h, bf16& l) {
    h = __float2bfloat16(v);
    l = __float2bfloat16(v - __bfloat162float(h));
}
__device__ __forceinline__ void split1h(float v, __half& h, __half& l) {
    h = __float2half(v);
    l = __float2half(v - __half2float(h));
}
__device__ __forceinline__ uint32_t packh(float v0, float v1) {
    __half2 p(__float2half(v0), __float2half(v1));
    return *(uint32_t*)&p;
}

// ---------------- embed ------------------------------------------------------
__global__ void embedcvt_kernel(const long long* __restrict__ x64,
                                const float* __restrict__ tok,
                                const float* __restrict__ pos) {
    __shared__ int is64s;
    if (threadIdx.x == 0) {
        int ok = 1;
        for (int i = 0; i < 16; i++) { long long t = x64[i]; if (t < 0 || t >= VV) ok = 0; }
        is64s = ok;
    }
    __syncthreads();
    int idx = blockIdx.x * blockDim.x + threadIdx.x;
    if (idx < MTOK * DD) {
        int d = idx % DD, t = idx / DD, s = t % SS;
        int tokid = is64s ? (int)x64[t] : ((const int*)x64)[t];
        g_h[idx] = tok[tokid * DD + d] + pos[s * DD + d];
    }
}

// ---------------- warp-per-row layernorms ------------------------------------
// -> bf16 hi/lo (ln2)
__global__ __launch_bounds__(256)
void ln_res_kernel(float* __restrict__ h, const float* __restrict__ p,
                   const float* __restrict__ g, const float* __restrict__ b,
                   bf16* __restrict__ ohi, bf16* __restrict__ olo) {
    const int wid = threadIdx.x >> 5, lane = threadIdx.x & 31;
    const int row = blockIdx.x * 8 + wid;
    float4* hr = (float4*)(h + (size_t)row * DD);
    const float4* p0 = (const float4*)(p + (size_t)row * DD);
    const float4* p1 = (const float4*)(p + (size_t)MTOK * DD + (size_t)row * DD);
    const float4* p2 = (const float4*)(p + 2 * (size_t)MTOK * DD + (size_t)row * DD);
    float4 v[6];
    float s1 = 0.f, s2 = 0.f;
#pragma unroll
    for (int i = 0; i < 6; i++) {
        int e4 = lane + 32 * i;
        float4 hv = hr[e4], a0 = p0[e4], a1 = p1[e4], a2 = p2[e4];
        hv.x += a0.x + a1.x + a2.x;
        hv.y += a0.y + a1.y + a2.y;
        hv.z += a0.z + a1.z + a2.z;
        hv.w += a0.w + a1.w + a2.w;
        hr[e4] = hv;
        v[i] = hv;
        s1 += hv.x + hv.y + hv.z + hv.w;
        s2 += hv.x*hv.x + hv.y*hv.y + hv.z*hv.z + hv.w*hv.w;
    }
#pragma unroll
    for (int o = 16; o > 0; o >>= 1) {
        s1 += __shfl_xor_sync(0xffffffffu, s1, o);
        s2 += __shfl_xor_sync(0xffffffffu, s2, o);
    }
    float mu = s1 * (1.0f / DD);
    float inv = rsqrtf(s2 * (1.0f / DD) - mu * mu + 1e-5f);
    const float4* gg = (const float4*)g;
    const float4* bb = (const float4*)b;
#pragma unroll
    for (int i = 0; i < 6; i++) {
        int e4 = lane + 32 * i;
        float4 gv = gg[e4], bv = bb[e4];
        float o0 = (v[i].x - mu) * inv * gv.x + bv.x;
        float o1 = (v[i].y - mu) * inv * gv.y + bv.y;
        float o2 = (v[i].z - mu) * inv * gv.z + bv.z;
        float o3 = (v[i].w - mu) * inv * gv.w + bv.w;
        bf16 h0,l0,h1,l1,h2,l2,h3,l3;
        split1(o0,h0,l0); split1(o1,h1,l1); split1(o2,h2,l2); split1(o3,h3,l3);
        size_t base = (size_t)row * DD + e4 * 4;
        *(__nv_bfloat162*)&ohi[base]     = __nv_bfloat162(h0, h1);
        *(__nv_bfloat162*)&ohi[base + 2] = __nv_bfloat162(h2, h3);
        *(__nv_bfloat162*)&olo[base]     = __nv_bfloat162(l0, l1);
        *(__nv_bfloat162*)&olo[base + 2] = __nv_bfloat162(l2, l3);
    }
}

// -> fp16 hi/lo, no partials (ln1 of layer 0)
__global__ __launch_bounds__(256)
void ln16_kernel(const float* __restrict__ in, const float* __restrict__ g,
                 const float* __restrict__ b,
                 __half* __restrict__ ohi, __half* __restrict__ olo) {
    const int wid = threadIdx.x >> 5, lane = threadIdx.x & 31;
    const int row = blockIdx.x * 8 + wid;
    const float4* xr = (const float4*)(in + (size_t)row * DD);
    float4 v[6];
    float s1 = 0.f, s2 = 0.f;
#pragma unroll
    for (int i = 0; i < 6; i++) {
        v[i] = xr[lane + 32 * i];
        s1 += v[i].x + v[i].y + v[i].z + v[i].w;
        s2 += v[i].x*v[i].x + v[i].y*v[i].y + v[i].z*v[i].z + v[i].w*v[i].w;
    }
#pragma unroll
    for (int o = 16; o > 0; o >>= 1) {
        s1 += __shfl_xor_sync(0xffffffffu, s1, o);
        s2 += __shfl_xor_sync(0xffffffffu, s2, o);
    }
    float mu = s1 * (1.0f / DD);
    float inv = rsqrtf(s2 * (1.0f / DD) - mu * mu + 1e-5f);
    const float4* gg = (const float4*)g;
    const float4* bb = (const float4*)b;
#pragma unroll
    for (int i = 0; i < 6; i++) {
        int e4 = lane + 32 * i;
        float4 gv = gg[e4], bv = bb[e4];
        float o0 = (v[i].x - mu) * inv * gv.x + bv.x;
        float o1 = (v[i].y - mu) * inv * gv.y + bv.y;
        float o2 = (v[i].z - mu) * inv * gv.z + bv.z;
        float o3 = (v[i].w - mu) * inv * gv.w + bv.w;
        __half h0,l0,h1,l1,h2,l2,h3,l3;
        split1h(o0,h0,l0); split1h(o1,h1,l1); split1h(o2,h2,l2); split1h(o3,h3,l3);
        size_t base = (size_t)row * DD + e4 * 4;
        *(__half2*)&ohi[base]     = __half2(h0, h1);
        *(__half2*)&ohi[base + 2] = __half2(h2, h3);
        *(__half2*)&olo[base]     = __half2(l0, l1);
        *(__half2*)&olo[base + 2] = __half2(l2, l3);
    }
}

// h += partials (written back), LN -> fp16 hi/lo (ln1 of l>0 + final LN)
__global__ __launch_bounds__(256)
void ln_res16_kernel(float* __restrict__ h, const float* __restrict__ p,
                     const float* __restrict__ g, const float* __restrict__ b,
                     __half* __restrict__ ohi, __half* __restrict__ olo) {
    const int wid = threadIdx.x >> 5, lane = threadIdx.x & 31;
    const int row = blockIdx.x * 8 + wid;
    float4* hr = (float4*)(h + (size_t)row * DD);
    const float4* p0 = (const float4*)(p + (size_t)row * DD);
    const float4* p1 = (const float4*)(p + (size_t)MTOK * DD + (size_t)row * DD);
    const float4* p2 = (const float4*)(p + 2 * (size_t)MTOK * DD + (size_t)row * DD);
    float4 v[6];
    float s1 = 0.f, s2 = 0.f;
#pragma unroll
    for (int i = 0; i < 6; i++) {
        int e4 = lane + 32 * i;
        float4 hv = hr[e4], a0 = p0[e4], a1 = p1[e4], a2 = p2[e4];
        hv.x += a0.x + a1.x + a2.x;
        hv.y += a0.y + a1.y + a2.y;
        hv.z += a0.z + a1.z + a2.z;
        hv.w += a0.w + a1.w + a2.w;
        hr[e4] = hv;
        v[i] = hv;
        s1 += hv.x + hv.y + hv.z + hv.w;
        s2 += hv.x*hv.x + hv.y*hv.y + hv.z*hv.z + hv.w*hv.w;
    }
#pragma unroll
    for (int o = 16; o > 0; o >>= 1) {
        s1 += __shfl_xor_sync(0xffffffffu, s1, o);
        s2 += __shfl_xor_sync(0xffffffffu, s2, o);
    }
    float mu = s1 * (1.0f / DD);
    float inv = rsqrtf(s2 * (1.0f / DD) - mu * mu + 1e-5f);
    const float4* gg = (const float4*)g;
    const float4* bb = (const float4*)b;
#pragma unroll
    for (int i = 0; i < 6; i++) {
        int e4 = lane + 32 * i;
        float4 gv = gg[e4], bv = bb[e4];
        float o0 = (v[i].x - mu) * inv * gv.x + bv.x;
        float o1 = (v[i].y - mu) * inv * gv.y + bv.y;
        float o2 = (v[i].z - mu) * inv * gv.z + bv.z;
        float o3 = (v[i].w - mu) * inv * gv.w + bv.w;
        __half h0,l0,h1,l1,h2,l2,h3,l3;
        split1h(o0,h0,l0); split1h(o1,h1,l1); split1h(o2,h2,l2); split1h(o3,h3,l3);
        size_t base = (size_t)row * DD + e4 * 4;
        *(__half2*)&ohi[base]     = __half2(h0, h1);
        *(__half2*)&ohi[base + 2] = __half2(h2, h3);
        *(__half2*)&olo[base]     = __half2(l0, l1);
        *(__half2*)&olo[base + 2] = __half2(l2, l3);
    }
}

// ---------------- converts/splits --------------------------------------------
__device__ __forceinline__ void split4_body(const float4* x, __nv_bfloat162* hi,
                                            __nv_bfloat162* lo, int i) {
    float4 v = x[i];
    bf16 hx, lx, hy, ly, hz, lz, hw, lw;
    split1(v.x, hx, lx); split1(v.y, hy, ly);
    split1(v.z, hz, lz); split1(v.w, hw, lw);
    hi[2*i]   = __nv_bfloat162(hx, hy);
    hi[2*i+1] = __nv_bfloat162(hz, hw);
    lo[2*i]   = __nv_bfloat162(lx, ly);
    lo[2*i+1] = __nv_bfloat162(lz, lw);
}

__global__ void cvt16_kernel(const float4* __restrict__ x, __half2* __restrict__ o, int n4) {
    int i = blockIdx.x * blockDim.x + threadIdx.x;
    if (i < n4) {
        float4 v = x[i];
        o[2*i]   = __floats2half2_rn(v.x, v.y);
        o[2*i+1] = __floats2half2_rn(v.z, v.w);
    }
}

// wq,wk,wv -> fp16 (grid.y selects)
__global__ void cvtw16_kernel(const float4* s0, __half2* o0,
                              const float4* s1, __half2* o1,
                              const float4* s2, __half2* o2, int n4) {
    const float4* s = (blockIdx.y == 0) ? s0 : (blockIdx.y == 1) ? s1 : s2;
    __half2*      o = (blockIdx.y == 0) ? o0 : (blockIdx.y == 1) ? o1 : o2;
    int i = blockIdx.x * blockDim.x + threadIdx.x;
    if (i < n4) {
        float4 v = s[i];
        o[2*i]   = __floats2half2_rn(v.x, v.y);
        o[2*i+1] = __floats2half2_rn(v.z, v.w);
    }
}

// wo,w1,w2 -> bf16 hi/lo (grid.y selects)
__global__ void split_w_kernel(
        const float4* s0, __nv_bfloat162* h0, __nv_bfloat162* l0, int n0,
        const float4* s1, __nv_bfloat162* h1, __nv_bfloat162* l1, int n1,
        const float4* s2, __nv_bfloat162* h2, __nv_bfloat162* l2, int n2) {
    const float4* s; __nv_bfloat162* h; __nv_bfloat162* l; int n;
    switch (blockIdx.y) {
        case 0: s = s0; h = h0; l = l0; n = n0; break;
        case 1: s = s1; h = h1; l = l1; n = n1; break;
        default: s = s2; h = h2; l = l2; n = n2; break;
    }
    int i = blockIdx.x * blockDim.x + threadIdx.x;
    if (i < n) split4_body(s, h, l, i);
}

// ---------------- bf16 3-pass GEMM core (O-proj, W1, W2) ----------------------
#define RB     48
#define TILE16 (128*RB)                  /* 6144 B  */
#define STG16  (4*TILE16)
#define NSTG   4
#define GSMEM16 (NSTG*STG16)             /* 98304 B */

template<int EPI>   // 0 f32 (+opt bias), 2 bf16split+bias+relu
__device__ __forceinline__ void gemm_core(
        const bf16* Ahi, const bf16* Alo, const bf16* Bhi, const bf16* Blo,
        const float* bias,
        float* C, bf16* Chi, bf16* Clo,
        int m0, int n0, int N, int K, int ldk, uint32_t sb) {
    const int tid = threadIdx.x;
    const int wid = tid >> 5, lane = tid & 31;
    const int wm = (wid >> 2) * 64;
    const int wn = (wid & 3) * 32;

    float Cf[4][4][4];
#pragma unroll
    for (int i = 0; i < 4; i++)
#pragma unroll
        for (int j = 0; j < 4; j++)
#pragma unroll
            for (int x = 0; x < 4; x++) Cf[i][j][x] = 0.f;

    const int NS = K >> 4;
    const int a_row = (lane & 15);
    const int a_cs = ((lane >> 4) * 8) * 2;
    const int b_row = (lane & 7) + ((lane >> 4) & 1) * 8;
    const int b_cs = (((lane >> 3) & 1) * 8) * 2;
    const int lr = tid >> 1;
    const int lc = tid & 1;

#define LOAD_STG(S_)                                                            \
    do {                                                                        \
        const int k0_ = (S_) << 4;                                              \
        uint32_t tb = sb + ((S_) & (NSTG - 1)) * STG16 + lr * RB + lc * 16;     \
        const int ac_ = k0_ + lc * 8;                                           \
        cpasync16(tb,              Ahi + (size_t)(m0 + lr) * ldk + ac_);        \
        cpasync16(tb + TILE16,     Alo + (size_t)(m0 + lr) * ldk + ac_);        \
        cpasync16(tb + 2 * TILE16, Bhi + (size_t)(n0 + lr) * ldk + ac_);        \
        cpasync16(tb + 3 * TILE16, Blo + (size_t)(n0 + lr) * ldk + ac_);        \
    } while (0)

#pragma unroll
    for (int s = 0; s < NSTG - 1; s++) { LOAD_STG(s); CP_COMMIT(); }

    for (int s = 0; s < NS; s++) {
        CP_WAIT(NSTG - 2);
        __syncthreads();

        const uint32_t st = sb + (s & (NSTG - 1)) * STG16;
        uint32_t Aany[4][4], Bh[2][4], Bl[2][4];
#pragma unroll
        for (int mf = 0; mf < 4; mf++)
            ldsm4(Aany[mf], st + (wm + mf * 16 + a_row) * RB + a_cs);
#pragma unroll
        for (int p = 0; p < 2; p++) {
            ldsm4(Bh[p], st + 2 * TILE16 + (wn + p * 16 + b_row) * RB + b_cs);
            ldsm4(Bl[p], st + 3 * TILE16 + (wn + p * 16 + b_row) * RB + b_cs);
        }
#pragma unroll
        for (int mf = 0; mf < 4; mf++)
#pragma unroll
            for (int nf = 0; nf < 4; nf++)
                mma16816(Cf[mf][nf], Aany[mf], &Bh[nf >> 1][(nf & 1) * 2]);
#pragma unroll
        for (int mf = 0; mf < 4; mf++)
#pragma unroll
            for (int nf = 0; nf < 4; nf++)
                mma16816(Cf[mf][nf], Aany[mf], &Bl[nf >> 1][(nf & 1) * 2]);
#pragma unroll
        for (int mf = 0; mf < 4; mf++)
            ldsm4(Aany[mf], st + TILE16 + (wm + mf * 16 + a_row) * RB + a_cs);
#pragma unroll
        for (int mf = 0; mf < 4; mf++)
#pragma unroll
            for (int nf = 0; nf < 4; nf++)
                mma16816(Cf[mf][nf], Aany[mf], &Bh[nf >> 1][(nf & 1) * 2]);

        if (s + NSTG - 1 < NS) LOAD_STG(s + NSTG - 1);
        CP_COMMIT();
    }
#undef LOAD_STG

    const int g = lane >> 2, t2 = (lane & 3) * 2;
#pragma unroll
    for (int mf = 0; mf < 4; mf++) {
#pragma unroll
        for (int nf = 0; nf < 4; nf++) {
            int n = n0 + wn + nf * 8 + t2;
#pragma unroll
            for (int hrow = 0; hrow < 2; hrow++) {
                int m = m0 + wm + mf * 16 + g + hrow * 8;
                float v0 = Cf[mf][nf][hrow * 2 + 0];
                float v1 = Cf[mf][nf][hrow * 2 + 1];
                if (EPI == 0) {
                    if (bias) { v0 += bias[n]; v1 += bias[n + 1]; }
                    *(float2*)&C[(size_t)m * N + n] = make_float2(v0, v1);
                } else {
                    v0 = fmaxf(v0 + bias[n], 0.f);
                    v1 = fmaxf(v1 + bias[n + 1], 0.f);
                    bf16 h0, l0, h1, l1;
                    split1(v0, h0, l0); split1(v1, h1, l1);
                    *(__nv_bfloat162*)&Chi[(size_t)m * N + n] = __nv_bfloat162(h0, h1);
                    *(__nv_bfloat162*)&Clo[(size_t)m * N + n] = __nv_bfloat162(l0, l1);
                }
            }
        }
    }
}

template<int EPI>
__global__ __launch_bounds__(256, 2)
void mm_gemm128(const bf16* __restrict__ Ahi, const bf16* __restrict__ Alo,
                const bf16* __restrict__ Bhi, const bf16* __restrict__ Blo,
                const float* __restrict__ bias,
                float* __restrict__ C, bf16* __restrict__ Chi, bf16* __restrict__ Clo,
                int N, int K) {
    extern __shared__ char smem_raw[];
    gemm_core<EPI>(Ahi, Alo, Bhi, Blo, bias, C, Chi, Clo,
                   blockIdx.y * 128, blockIdx.x * 128, N, K, K, smem_u32(smem_raw));
}

__global__ __launch_bounds__(256, 2)
void mm_gemm_pk(const bf16* __restrict__ Ahi, const bf16* __restrict__ Alo,
                const bf16* __restrict__ Bhi, const bf16* __restrict__ Blo,
                const float* __restrict__ bias, float* __restrict__ P,
                int N, int Kfull, int Ks) {
    extern __shared__ char smem_raw[];
    const int z = blockIdx.z;
    const int k0 = z * Ks;
    gemm_core<0>(Ahi + k0, Alo + k0, Bhi + k0, Blo + k0,
                 z == 0 ? bias : nullptr,
                 P + (size_t)z * MTOK * N, nullptr, nullptr,
                 blockIdx.y * 128, blockIdx.x * 128, N, Ks, Kfull, smem_u32(smem_raw));
}

// ---------------- fp16 2-pass GEMM core (QKV + LM head) ----------------------
#define LSTG   (3*TILE16)                /* 18432 */
#define GSMEM_LM (NSTG*LSTG)             /* 73728 */

template<int EPI>   // 3 f32 no-bias (LM), 5 fp16 out + bias + scale (+opt lo)
__device__ __forceinline__ void hgemm_core(
        const __half* Ah, const __half* Al, const __half* Bh,
        const float* bias, float sc,
        float* C, __half* Chi, __half* Clo,
        int m0, int n0, int N, int K, uint32_t sb) {
    const int tid = threadIdx.x;
    const int wid = tid >> 5, lane = tid & 31;
    const int wm = (wid >> 2) * 64;
    const int wn = (wid & 3) * 32;

    float Cf[4][4][4];
#pragma unroll
    for (int i = 0; i < 4; i++)
#pragma unroll
        for (int j = 0; j < 4; j++)
#pragma unroll
            for (int x = 0; x < 4; x++) Cf[i][j][x] = 0.f;

    const int NS = K >> 4;
    const int a_row = (lane & 15);
    const int a_cs = ((lane >> 4) * 8) * 2;
    const int b_row = (lane & 7) + ((lane >> 4) & 1) * 8;
    const int b_cs = (((lane >> 3) & 1) * 8) * 2;
    const int lr = tid >> 1;
    const int lc = tid & 1;

#define LOAD_LM(S_)                                                             \
    do {                                                                        \
        const int k0_ = (S_) << 4;                                              \
        uint32_t tb = sb + ((S_) & (NSTG - 1)) * LSTG + lr * RB + lc * 16;      \
        const int ac_ = k0_ + lc * 8;                                           \
        cpasync16(tb,              Ah + (size_t)(m0 + lr) * K + ac_);           \
        cpasync16(tb + TILE16,     Al + (size_t)(m0 + lr) * K + ac_);           \
        cpasync16(tb + 2 * TILE16, Bh + (size_t)(n0 + lr) * K + ac_);           \
    } while (0)

#pragma unroll
    for (int s = 0; s < NSTG - 1; s++) { LOAD_LM(s); CP_COMMIT(); }

    for (int s = 0; s < NS; s++) {
        CP_WAIT(NSTG - 2);
        __syncthreads();

        const uint32_t st = sb + (s & (NSTG - 1)) * LSTG;
        uint32_t Af[4][4], Bf[2][4];
#pragma unroll
        for (int mf = 0; mf < 4; mf++)
            ldsm4(Af[mf], st + (wm + mf * 16 + a_row) * RB + a_cs);
#pragma unroll
        for (int p = 0; p < 2; p++)
            ldsm4(Bf[p], st + 2 * TILE16 + (wn + p * 16 + b_row) * RB + b_cs);
#pragma unroll
        for (int mf = 0; mf < 4; mf++)
#pragma unroll
            for (int nf = 0; nf < 4; nf++)
                mma16816h(Cf[mf][nf], Af[mf], &Bf[nf >> 1][(nf & 1) * 2]);
#pragma unroll
        for (int mf = 0; mf < 4; mf++)
            ldsm4(Af[mf], st + TILE16 + (wm + mf * 16 + a_row) * RB + a_cs);
#pragma unroll
        for (int mf = 0; mf < 4; mf++)
#pragma unroll
            for (int nf = 0; nf < 4; nf++)
                mma16816h(Cf[mf][nf], Af[mf], &Bf[nf >> 1][(nf & 1) * 2]);

        if (s + NSTG - 1 < NS) LOAD_LM(s + NSTG - 1);
        CP_COMMIT();
    }
#undef LOAD_LM

    const int g = lane >> 2, t2 = (lane & 3) * 2;
#pragma unroll
    for (int mf = 0; mf < 4; mf++) {
#pragma unroll
        for (int nf = 0; nf < 4; nf++) {
            int n = n0 + wn + nf * 8 + t2;
#pragma unroll
            for (int hrow = 0; hrow < 2; hrow++) {
                int m = m0 + wm + mf * 16 + g + hrow * 8;
                float v0 = Cf[mf][nf][hrow * 2 + 0];
                float v1 = Cf[mf][nf][hrow * 2 + 1];
                if (EPI == 3) {
                    *(float2*)&C[(size_t)m * N + n] = make_float2(v0, v1);
                } else {
                    v0 = (v0 + bias[n]) * sc;
                    v1 = (v1 + bias[n + 1]) * sc;
                    __half h0, l0, h1, l1;
                    split1h(v0, h0, l0); split1h(v1, h1, l1);
                    *(__half2*)&Chi[(size_t)m * N + n] = __half2(h0, h1);
                    if (Clo)
                        *(__half2*)&Clo[(size_t)m * N + n] = __half2(l0, l1);
                }
            }
        }
    }
}

__global__ __launch_bounds__(256, 2)
void lm_gemm(const __half* __restrict__ Ah, const __half* __restrict__ Al,
             const __half* __restrict__ Bh, float* __restrict__ C, int N, int K) {
    extern __shared__ char smem_raw[];
    hgemm_core<3>(Ah, Al, Bh, nullptr, 1.0f, C, nullptr, nullptr,
                  blockIdx.y * 128, blockIdx.x * 128, N, K, smem_u32(smem_raw));
}

__global__ __launch_bounds__(256, 2)
void qkv16_gemm(const __half* __restrict__ Ah, const __half* __restrict__ Al,
                const __half* __restrict__ wq, const __half* __restrict__ wk,
                const __half* __restrict__ wv,
                const float* __restrict__ bq, const float* __restrict__ bk,
                const float* __restrict__ bv,
                __half* __restrict__ qh, __half* __restrict__ ql,
                __half* __restrict__ k16, __half* __restrict__ v16) {
    extern __shared__ char smem_raw[];
    const int which = blockIdx.x / 6, nb = blockIdx.x % 6;
    const __half* B = (which == 0) ? wq : (which == 1) ? wk : wv;
    const float* bias = (which == 0) ? bq : (which == 1) ? bk : bv;
    __half* Ch = (which == 0) ? qh : (which == 1) ? k16 : v16;
    __half* Cl = (which == 0) ? ql : nullptr;
    float sc = (which == 0) ? 0.125f : 1.0f;
    hgemm_core<5>(Ah, Al, B, bias, sc, nullptr, Ch, Cl,
                  blockIdx.y * 128, nb * 128, DD, DD, smem_u32(smem_raw));
}

// ---------------- fp16 2-pass MMA flash attention ----------------------------
#define AST 144
#define ATILE (64*AST)
#define ATT_SMEM16 (2*ATILE + 2*2*ATILE)   /* 55296 */

__device__ __forceinline__ void att_load4(uint32_t dst, const void* src,
                                          size_t grow0, int hcol, int tid) {
    int r = tid >> 1, c0 = (tid & 1) * 4;
    const char* p = (const char*)src + ((grow0 + r) * DD + hcol + c0 * 8) * 2;
    uint32_t d = dst + r * AST + c0 * 16;
#pragma unroll
    for (int i = 0; i < 4; i++) cpasync16(d + i * 16, p + i * 16);
}

__global__ __launch_bounds__(128)
void flash_attn(const __half* __restrict__ qh, const __half* __restrict__ ql,
                const __half* __restrict__ k16, const __half* __restrict__ v16,
                bf16* __restrict__ chi, bf16* __restrict__ clo) {
    const int qt = gridDim.x - 1 - blockIdx.x;
    const int hd = blockIdx.y, b = blockIdx.z;
    extern __shared__ char smc[];
    const uint32_t sb = smem_u32(smc);
    const uint32_t Qh_s = sb, Ql_s = sb + ATILE;
    const uint32_t KV = sb + 2 * ATILE;

    const int tid = threadIdx.x, wid = tid >> 5, lane = tid & 31;
    const size_t qrow0 = (size_t)(b * SS + qt * 64);
    const int hcol = hd * DK;

    att_load4(Qh_s, qh, qrow0, hcol, tid);
    att_load4(Ql_s, ql, qrow0, hcol, tid);
    {
        size_t kr = (size_t)(b * SS);
        att_load4(KV,         k16, kr, hcol, tid);
        att_load4(KV + ATILE, v16, kr, hcol, tid);
    }
    CP_COMMIT();

    float O[8][4];
    float mrow[2] = { -1e30f, -1e30f };
    float lrow[2] = { 0.f, 0.f };
#pragma unroll
    for (int nt = 0; nt < 8; nt++)
#pragma unroll
        for (int x = 0; x < 4; x++) O[nt][x] = 0.f;

    const int g = lane >> 2, t2q = (lane & 3) * 2;
    const int a_row = wid * 16 + (lane & 15);
    const uint32_t a_cs = ((lane >> 4) << 3) * 2;
    const int b_row = (lane & 7) + (((lane >> 4) & 1) << 3);
    const uint32_t b_cs = (((lane >> 3) & 1) << 3) * 2;
    const int v_row = (lane & 15);
    const uint32_t v_cs = ((lane >> 4) << 3) * 2;

    for (int jt = 0; jt <= qt; jt++) {
        if (jt < qt) {
            size_t kr = (size_t)(b * SS + (jt + 1) * 64);
            uint32_t nb = KV + ((jt + 1) & 1) * (2 * ATILE);
            att_load4(nb,         k16, kr, hcol, tid);
            att_load4(nb + ATILE, v16, kr, hcol, tid);
            CP_COMMIT();
            CP_WAIT(1);
        } else {
            CP_WAIT(0);
        }
        __syncthreads();

        const uint32_t Kh_s = KV + (jt & 1) * (2 * ATILE);
        const uint32_t Vh_s = Kh_s + ATILE;

        float S[8][4];
#pragma unroll
        for (int nt = 0; nt < 8; nt++)
#pragma unroll
            for (int x = 0; x < 4; x++) S[nt][x] = 0.f;

#pragma unroll
        for (int ks = 0; ks < 4; ks++) {
            uint32_t Qhf[4], Qlf[4];
            ldsm4(Qhf, Qh_s + a_row * AST + ks * 32 + a_cs);
            ldsm4(Qlf, Ql_s + a_row * AST + ks * 32 + a_cs);
#pragma unroll
            for (int p = 0; p < 4; p++) {
                uint32_t Kf[4];
                ldsm4(Kf, Kh_s + (p * 16 + b_row) * AST + ks * 32 + b_cs);
#pragma unroll
                for (int q = 0; q < 2; q++) {
                    mma16816h(S[p * 2 + q], Qhf, &Kf[q * 2]);
                    mma16816h(S[p * 2 + q], Qlf, &Kf[q * 2]);
                }
            }
        }

        const bool diag = (jt == qt);
#pragma unroll
        for (int half = 0; half < 2; half++) {
            const int rloc = wid * 16 + g + half * 8;
            float mt = -1e30f;
#pragma unroll
            for (int nt = 0; nt < 8; nt++) {
                float s0 = S[nt][half * 2], s1 = S[nt][half * 2 + 1];
                if (diag) {
                    if (nt * 8 + t2q > rloc)     s0 = -1e30f;
                    if (nt * 8 + t2q + 1 > rloc) s1 = -1e30f;
                }
                S[nt][half * 2] = s0; S[nt][half * 2 + 1] = s1;
                mt = fmaxf(mt, fmaxf(s0, s1));
            }
            mt = fmaxf(mt, __shfl_xor_sync(0xffffffffu, mt, 1));
            mt = fmaxf(mt, __shfl_xor_sync(0xffffffffu, mt, 2));
            float mn = fmaxf(mrow[half], mt);
            float f = __expf(mrow[half] - mn);
            mrow[half] = mn;
            float rs = 0.f;
#pragma unroll
            for (int nt = 0; nt < 8; nt++) {
                float e0 = __expf(S[nt][half * 2] - mn);
                float e1 = __expf(S[nt][half * 2 + 1] - mn);
                S[nt][half * 2] = e0; S[nt][half * 2 + 1] = e1;
                rs += e0 + e1;
            }
            rs += __shfl_xor_sync(0xffffffffu, rs, 1);
            rs += __shfl_xor_sync(0xffffffffu, rs, 2);
            lrow[half] = lrow[half] * f + rs;
#pragma unroll
            for (int nt = 0; nt < 8; nt++) {
                O[nt][half * 2] *= f; O[nt][half * 2 + 1] *= f;
            }
        }

#pragma unroll
        for (int ks = 0; ks < 4; ks++) {
            uint32_t Ph[4], Pl[4];
#pragma unroll
            for (int q4 = 0; q4 < 4; q4++) {
                int tile = 2 * ks + (q4 >> 1);
                int o = (q4 & 1) * 2;
                float v0 = S[tile][o], v1 = S[tile][o + 1];
                __half h0 = __float2half(v0), h1 = __float2half(v1);
                __half2 hh(h0, h1);
                Ph[q4] = *(uint32_t*)&hh;
                Pl[q4] = packh(v0 - __half2float(h0), v1 - __half2float(h1));
            }
#pragma unroll
            for (int nt = 0; nt < 4; nt++) {
                uint32_t Vf[4];
                ldsm4t(Vf, Vh_s + (ks * 16 + v_row) * AST + nt * 32 + v_cs);
#pragma unroll
                for (int q = 0; q < 2; q++) {
                    mma16816h(O[nt * 2 + q], Ph, &Vf[q * 2]);
                    mma16816h(O[nt * 2 + q], Pl, &Vf[q * 2]);
                }
            }
        }
        __syncthreads();
    }

    float inv[2] = { 1.0f / lrow[0], 1.0f / lrow[1] };
#pragma unroll
    for (int nt = 0; nt < 8; nt++) {
#pragma unroll
        for (int half = 0; half < 2; half++) {
            size_t row = qrow0 + wid * 16 + g + half * 8;
            int col = hcol + nt * 8 + t2q;
            float v0 = O[nt][half * 2] * inv[half];
            float v1 = O[nt][half * 2 + 1] * inv[half];
            bf16 h0, l0, h1, l1;
            split1(v0, h0, l0); split1(v1, h1, l1);
            *(__nv_bfloat162*)&chi[row * DD + col] = __nv_bfloat162(h0, h1);
            *(__nv_bfloat162*)&clo[row * DD + col] = __nv_bfloat162(l0, l1);
        }
    }
}

// ---------------- driver -----------------------------------------------------
extern "C" void kernel_launch(void* const* d_in, const int* in_sizes, int n_in,
                              void* d_out, int out_size) {
    (void)in_sizes; (void)n_in; (void)out_size;
    const float* tok  = (const float*)d_in[1];
    const float* pos  = (const float*)d_in[2];
    const float* bq   = (const float*)d_in[4];
    const float* bk   = (const float*)d_in[6];
    const float* bv   = (const float*)d_in[8];
    const float* bo   = (const float*)d_in[10];
    const float* b1   = (const float*)d_in[12];
    const float* b2   = (const float*)d_in[14];
    const float* ln1g = (const float*)d_in[15];
    const float* ln1b = (const float*)d_in[16];
    const float* ln2g = (const float*)d_in[17];
    const float* ln2b = (const float*)d_in[18];
    const float* lnfg = (const float*)d_in[19];
    const float* lnfb = (const float*)d_in[20];
    float* out = (float*)d_out;

    float *h, *pp;
    cudaGetSymbolAddress((void**)&h,  g_h);
    cudaGetSymbolAddress((void**)&pp, g_p);

    __half *t16, *e16h, *e16l, *w16q, *w16k, *w16v, *q16h, *q16l, *k16, *v16;
    cudaGetSymbolAddress((void**)&t16,  g_t16);
    cudaGetSymbolAddress((void**)&e16h, g_e16h);
    cudaGetSymbolAddress((void**)&e16l, g_e16l);
    cudaGetSymbolAddress((void**)&w16q, g_w16q);
    cudaGetSymbolAddress((void**)&w16k, g_w16k);
    cudaGetSymbolAddress((void**)&w16v, g_w16v);
    cudaGetSymbolAddress((void**)&q16h, g_q16h);
    cudaGetSymbolAddress((void**)&q16l, g_q16l);
    cudaGetSymbolAddress((void**)&k16,  g_k16);
    cudaGetSymbolAddress((void**)&v16,  g_v16);

    bf16 *woh, *wol, *w1h, *w1l, *w2h, *w2l, *ah, *al, *fh, *fl;
    cudaGetSymbolAddress((void**)&woh,  g_wo_hi);  cudaGetSymbolAddress((void**)&wol,  g_wo_lo);
    cudaGetSymbolAddress((void**)&w1h,  g_w1_hi);  cudaGetSymbolAddress((void**)&w1l,  g_w1_lo);
    cudaGetSymbolAddress((void**)&w2h,  g_w2_hi);  cudaGetSymbolAddress((void**)&w2l,  g_w2_lo);
    cudaGetSymbolAddress((void**)&ah,   g_a_hi);   cudaGetSymbolAddress((void**)&al,   g_a_lo);
    cudaGetSymbolAddress((void**)&fh,   g_f_hi);   cudaGetSymbolAddress((void**)&fl,   g_f_lo);

    cudaFuncSetAttribute(mm_gemm128<2>, cudaFuncAttributeMaxDynamicSharedMemorySize, GSMEM16);
    cudaFuncSetAttribute(mm_gemm_pk,    cudaFuncAttributeMaxDynamicSharedMemorySize, GSMEM16);
    cudaFuncSetAttribute(qkv16_gemm,    cudaFuncAttributeMaxDynamicSharedMemorySize, GSMEM_LM);
    cudaFuncSetAttribute(lm_gemm,       cudaFuncAttributeMaxDynamicSharedMemorySize, GSMEM_LM);
    cudaFuncSetAttribute(flash_attn,    cudaFuncAttributeMaxDynamicSharedMemorySize, ATT_SMEM16);

    // launch 0: embed
    embedcvt_kernel<<<(MTOK * DD + 255) / 256, 256>>>((const long long*)d_in[0], tok, pos);
    // launch 1: wq/wk/wv -> fp16
    {
        const int nD4 = LL * DD * DD / 4;
        dim3 gw((nD4 + 255) / 256, 3);
        cvtw16_kernel<<<gw, 256>>>(
            (const float4*)d_in[3], (__half2*)w16q,
            (const float4*)d_in[5], (__half2*)w16k,
            (const float4*)d_in[7], (__half2*)w16v, nD4);
    }

    dim3 gQKV(18, MTOK / 128);           // (18, 16)
    dim3 gPK(DD / 128, MTOK / 128, 3);   // (6, 16, 3)
    dim3 gF(FF / 128, MTOK / 128);       // (24, 16)
    dim3 gV(VV / 128, MTOK / 128);       // (250, 16)
    dim3 gA(SS / 64, HH, BB);            // (16, 12, 2)
    const int gLN = MTOK / 8;

    for (int l = 0; l < LL; l++) {
        const size_t wD = (size_t)l * DD * DD;
        if (l == 0)
            ln16_kernel<<<gLN, 256>>>(h, ln1g, ln1b, e16h, e16l);          // launch 2
        else
            ln_res16_kernel<<<gLN, 256>>>(h, pp, ln1g + l * DD, ln1b + l * DD, e16h, e16l);
        qkv16_gemm<<<gQKV, 256, GSMEM_LM>>>(e16h, e16l,                    // launch 3 (l=0) — profiled
                                            w16q + wD, w16k + wD, w16v + wD,
                                            bq + l * DD, bk + l * DD, bv + l * DD,
                                            q16h, q16l, k16, v16);
        if (l == 0) {   // launch 4: wo/w1/w2 bf16 splits (needed from O-proj on)
            const int nD4 = LL * DD * DD / 4;
            const int nF4 = LL * FF * DD / 4;
            dim3 gw((nF4 + 255) / 256, 3);
            split_w_kernel<<<gw, 256>>>(
                (const float4*)d_in[9],  (__nv_bfloat162*)woh, (__nv_bfloat162*)wol, nD4,
                (const float4*)d_in[11], (__nv_bfloat162*)w1h, (__nv_bfloat162*)w1l, nF4,
                (const float4*)d_in[13], (__nv_bfloat162*)w2h, (__nv_bfloat162*)w2l, nF4);
        }
        flash_attn<<<gA, 128, ATT_SMEM16>>>(q16h, q16l, k16, v16, ah, al);
        mm_gemm_pk<<<gPK, 256, GSMEM16>>>(ah, al, woh + wD, wol + wD,
                                          bo + l * DD, pp, DD, DD, DD / 3);
        ln_res_kernel<<<gLN, 256>>>(h, pp, ln2g + l * DD, ln2b + l * DD, ah, al);
        mm_gemm128<2><<<gF, 256, GSMEM16>>>(ah, al, w1h + (size_t)l * FF * DD,
                                            w1l + (size_t)l * FF * DD, b1 + l * FF,
                                            nullptr, fh, fl, FF, DD);
        mm_gemm_pk<<<gPK, 256, GSMEM16>>>(fh, fl, w2h + (size_t)l * DD * FF,
                                          w2l + (size_t)l * DD * FF, b2 + l * DD,
                                          pp, DD, FF, FF / 3);
    }

    // LM head
    {
        int n4 = VV * DD / 4;
        cvt16_kernel<<<(n4 + 255) / 256, 256>>>((const float4*)tok, (__half2*)t16, n4);
    }
    ln_res16_kernel<<<gLN, 256>>>(h, pp, lnfg, lnfb, e16h, e16l);
    lm_gemm<<<gV, 256, GSMEM_LM>>>(e16h, e16l, t16, out, VV, DD);
}

// round 12
// speedup vs baseline: 1.3625x; 1.1178x over previous
#include <cuda_runtime.h>
#include <cuda_bf16.h>
#include <cuda_fp16.h>
#include <cstdint>
#include <math.h>

#define BB 2
#define SS 1024
#define DD 768
#define HH 12
#define DK 64
#define FF 3072
#define LL 4
#define VV 32000
#define MTOK (BB*SS)   /* 2048 */

// ---------------- scratch ----------------------------------------------------
__device__ float g_h  [MTOK*DD];
__device__ float g_p  [3*MTOK*DD];        // split-K partials
__device__ __half g_t16 [VV*DD];          // tok_emb fp16 (LM head B)
__device__ __half g_e16h[MTOK*DD], g_e16l[MTOK*DD];   // LN outputs fp16 hi/lo
__device__ __half g_w16q[LL*DD*DD], g_w16k[LL*DD*DD], g_w16v[LL*DD*DD];
__device__ __half g_w16o[LL*DD*DD];
__device__ __half g_w16f1[LL*FF*DD], g_w16f2[LL*DD*FF];
__device__ __half g_q16h[MTOK*DD], g_q16l[MTOK*DD];
__device__ __half g_k16 [MTOK*DD], g_v16 [MTOK*DD];
__device__ __half g_a16h[MTOK*DD], g_a16l[MTOK*DD];   // attention ctx fp16 hi/lo
__device__ __half g_f16h[MTOK*FF], g_f16l[MTOK*FF];   // relu(ffn) fp16 hi/lo

// ---------------- helpers ----------------------------------------------------
__device__ __forceinline__ uint32_t smem_u32(const void* p) {
    uint32_t a;
    asm("{ .reg .u64 t; cvta.to.shared.u64 t, %1; cvt.u32.u64 %0, t; }" : "=r"(a) : "l"(p));
    return a;
}
__device__ __forceinline__ void cpasync16(uint32_t saddr, const void* gaddr) {
    asm volatile("cp.async.cg.shared.global [%0], [%1], 16;" :: "r"(saddr), "l"(gaddr));
}
#define CP_COMMIT() asm volatile("cp.async.commit_group;" ::: "memory")
#define CP_WAIT(N)  asm volatile("cp.async.wait_group %0;" :: "n"(N) : "memory")

__device__ __forceinline__ void ldsm4(uint32_t* r, uint32_t addr) {
    asm volatile("ldmatrix.sync.aligned.m8n8.x4.shared.b16 {%0,%1,%2,%3}, [%4];"
        : "=r"(r[0]), "=r"(r[1]), "=r"(r[2]), "=r"(r[3]) : "r"(addr));
}
__device__ __forceinline__ void ldsm4t(uint32_t* r, uint32_t addr) {
    asm volatile("ldmatrix.sync.aligned.m8n8.x4.trans.shared.b16 {%0,%1,%2,%3}, [%4];"
        : "=r"(r[0]), "=r"(r[1]), "=r"(r[2]), "=r"(r[3]) : "r"(addr));
}
__device__ __forceinline__ void mma16816h(float* c, const uint32_t* a, const uint32_t* b) {
    asm volatile(
        "mma.sync.aligned.m16n8k16.row.col.f32.f16.f16.f32 "
        "{%0,%1,%2,%3}, {%4,%5,%6,%7}, {%8,%9}, {%0,%1,%2,%3};"
        : "+f"(c[0]), "+f"(c[1]), "+f"(c[2]), "+f"(c[3])
        : "r"(a[0]), "r"(a[1]), "r"(a[2]), "r"(a[3]), "r"(b[0]), "r"(b[1]));
}
__device__ __forceinline__ void split1h(float v, __half& h, __half& l) {
    h = __float2half(v);
    l = __float2half(v - __half2float(h));
}
__device__ __forceinline__ uint32_t packh(float v0, float v1) {
    __half2 p(__float2half(v0), __float2half(v1));
    return *(uint32_t*)&p;
}

// ---------------- embed ------------------------------------------------------
__global__ void embedcvt_kernel(const long long* __restrict__ x64,
                                const float* __restrict__ tok,
                                const float* __restrict__ pos) {
    __shared__ int is64s;
    if (threadIdx.x == 0) {
        int ok = 1;
        for (int i = 0; i < 16; i++) { long long t = x64[i]; if (t < 0 || t >= VV) ok = 0; }
        is64s = ok;
    }
    __syncthreads();
    int idx = blockIdx.x * blockDim.x + threadIdx.x;
    if (idx < MTOK * DD) {
        int d = idx % DD, t = idx / DD, s = t % SS;
        int tokid = is64s ? (int)x64[t] : ((const int*)x64)[t];
        g_h[idx] = tok[tokid * DD + d] + pos[s * DD + d];
    }
}

// ---------------- warp-per-row layernorms -> fp16 hi/lo ----------------------
__global__ __launch_bounds__(256)
void ln16_kernel(const float* __restrict__ in, const float* __restrict__ g,
                 const float* __restrict__ b,
                 __half* __restrict__ ohi, __half* __restrict__ olo) {
    const int wid = threadIdx.x >> 5, lane = threadIdx.x & 31;
    const int row = blockIdx.x * 8 + wid;
    const float4* xr = (const float4*)(in + (size_t)row * DD);
    float4 v[6];
    float s1 = 0.f, s2 = 0.f;
#pragma unroll
    for (int i = 0; i < 6; i++) {
        v[i] = xr[lane + 32 * i];
        s1 += v[i].x + v[i].y + v[i].z + v[i].w;
        s2 += v[i].x*v[i].x + v[i].y*v[i].y + v[i].z*v[i].z + v[i].w*v[i].w;
    }
#pragma unroll
    for (int o = 16; o > 0; o >>= 1) {
        s1 += __shfl_xor_sync(0xffffffffu, s1, o);
        s2 += __shfl_xor_sync(0xffffffffu, s2, o);
    }
    float mu = s1 * (1.0f / DD);
    float inv = rsqrtf(s2 * (1.0f / DD) - mu * mu + 1e-5f);
    const float4* gg = (const float4*)g;
    const float4* bb = (const float4*)b;
#pragma unroll
    for (int i = 0; i < 6; i++) {
        int e4 = lane + 32 * i;
        float4 gv = gg[e4], bv = bb[e4];
        float o0 = (v[i].x - mu) * inv * gv.x + bv.x;
        float o1 = (v[i].y - mu) * inv * gv.y + bv.y;
        float o2 = (v[i].z - mu) * inv * gv.z + bv.z;
        float o3 = (v[i].w - mu) * inv * gv.w + bv.w;
        __half h0,l0,h1,l1,h2,l2,h3,l3;
        split1h(o0,h0,l0); split1h(o1,h1,l1); split1h(o2,h2,l2); split1h(o3,h3,l3);
        size_t base = (size_t)row * DD + e4 * 4;
        *(__half2*)&ohi[base]     = __half2(h0, h1);
        *(__half2*)&ohi[base + 2] = __half2(h2, h3);
        *(__half2*)&olo[base]     = __half2(l0, l1);
        *(__half2*)&olo[base + 2] = __half2(l2, l3);
    }
}

// h += P0+P1+P2 (written back), then LN -> fp16 hi/lo
__global__ __launch_bounds__(256)
void ln_res16_kernel(float* __restrict__ h, const float* __restrict__ p,
                     const float* __restrict__ g, const float* __restrict__ b,
                     __half* __restrict__ ohi, __half* __restrict__ olo) {
    const int wid = threadIdx.x >> 5, lane = threadIdx.x & 31;
    const int row = blockIdx.x * 8 + wid;
    float4* hr = (float4*)(h + (size_t)row * DD);
    const float4* p0 = (const float4*)(p + (size_t)row * DD);
    const float4* p1 = (const float4*)(p + (size_t)MTOK * DD + (size_t)row * DD);
    const float4* p2 = (const float4*)(p + 2 * (size_t)MTOK * DD + (size_t)row * DD);
    float4 v[6];
    float s1 = 0.f, s2 = 0.f;
#pragma unroll
    for (int i = 0; i < 6; i++) {
        int e4 = lane + 32 * i;
        float4 hv = hr[e4], a0 = p0[e4], a1 = p1[e4], a2 = p2[e4];
        hv.x += a0.x + a1.x + a2.x;
        hv.y += a0.y + a1.y + a2.y;
        hv.z += a0.z + a1.z + a2.z;
        hv.w += a0.w + a1.w + a2.w;
        hr[e4] = hv;
        v[i] = hv;
        s1 += hv.x + hv.y + hv.z + hv.w;
        s2 += hv.x*hv.x + hv.y*hv.y + hv.z*hv.z + hv.w*hv.w;
    }
#pragma unroll
    for (int o = 16; o > 0; o >>= 1) {
        s1 += __shfl_xor_sync(0xffffffffu, s1, o);
        s2 += __shfl_xor_sync(0xffffffffu, s2, o);
    }
    float mu = s1 * (1.0f / DD);
    float inv = rsqrtf(s2 * (1.0f / DD) - mu * mu + 1e-5f);
    const float4* gg = (const float4*)g;
    const float4* bb = (const float4*)b;
#pragma unroll
    for (int i = 0; i < 6; i++) {
        int e4 = lane + 32 * i;
        float4 gv = gg[e4], bv = bb[e4];
        float o0 = (v[i].x - mu) * inv * gv.x + bv.x;
        float o1 = (v[i].y - mu) * inv * gv.y + bv.y;
        float o2 = (v[i].z - mu) * inv * gv.z + bv.z;
        float o3 = (v[i].w - mu) * inv * gv.w + bv.w;
        __half h0,l0,h1,l1,h2,l2,h3,l3;
        split1h(o0,h0,l0); split1h(o1,h1,l1); split1h(o2,h2,l2); split1h(o3,h3,l3);
        size_t base = (size_t)row * DD + e4 * 4;
        *(__half2*)&ohi[base]     = __half2(h0, h1);
        *(__half2*)&ohi[base + 2] = __half2(h2, h3);
        *(__half2*)&olo[base]     = __half2(l0, l1);
        *(__half2*)&olo[base + 2] = __half2(l2, l3);
    }
}

// ---------------- fp32 -> fp16 weight converts -------------------------------
__global__ void cvt16_kernel(const float4* __restrict__ x, __half2* __restrict__ o, int n4) {
    int i = blockIdx.x * blockDim.x + threadIdx.x;
    if (i < n4) {
        float4 v = x[i];
        o[2*i]   = __floats2half2_rn(v.x, v.y);
        o[2*i+1] = __floats2half2_rn(v.z, v.w);
    }
}

// all 6 layer weights -> fp16 (grid.y selects)
__global__ void cvtw6_kernel(const float4* s0, __half2* o0, int n0,
                             const float4* s1, __half2* o1, int n1,
                             const float4* s2, __half2* o2, int n2,
                             const float4* s3, __half2* o3, int n3,
                             const float4* s4, __half2* o4, int n4_,
                             const float4* s5, __half2* o5, int n5) {
    const float4* s; __half2* o; int n;
    switch (blockIdx.y) {
        case 0: s = s0; o = o0; n = n0; break;
        case 1: s = s1; o = o1; n = n1; break;
        case 2: s = s2; o = o2; n = n2; break;
        case 3: s = s3; o = o3; n = n3; break;
        case 4: s = s4; o = o4; n = n4_; break;
        default: s = s5; o = o5; n = n5; break;
    }
    int i = blockIdx.x * blockDim.x + threadIdx.x;
    if (i < n) {
        float4 v = s[i];
        o[2*i]   = __floats2half2_rn(v.x, v.y);
        o[2*i+1] = __floats2half2_rn(v.z, v.w);
    }
}

// ---------------- fp16 2-pass GEMM core --------------------------------------
// C = (Ah+Al) @ Bh^T; 3 tiles/stage, 4 stages, single sync per stage.
#define RB     48
#define TILE16 (128*RB)                  /* 6144 B  */
#define NSTG   4
#define LSTG   (3*TILE16)                /* 18432 */
#define GSMEM_H (NSTG*LSTG)              /* 73728 */

// EPI: 0 f32 out (+opt bias), 5 fp16split+bias+scale (opt lo), 6 relu+bias+fp16split
template<int EPI>
__device__ __forceinline__ void hgemm_core(
        const __half* Ah, const __half* Al, const __half* Bh,
        const float* bias, float sc,
        float* C, __half* Chi, __half* Clo,
        int m0, int n0, int N, int K, int ldk, uint32_t sb) {
    const int tid = threadIdx.x;
    const int wid = tid >> 5, lane = tid & 31;
    const int wm = (wid >> 2) * 64;
    const int wn = (wid & 3) * 32;

    float Cf[4][4][4];
#pragma unroll
    for (int i = 0; i < 4; i++)
#pragma unroll
        for (int j = 0; j < 4; j++)
#pragma unroll
            for (int x = 0; x < 4; x++) Cf[i][j][x] = 0.f;

    const int NS = K >> 4;
    const int a_row = (lane & 15);
    const int a_cs = ((lane >> 4) * 8) * 2;
    const int b_row = (lane & 7) + ((lane >> 4) & 1) * 8;
    const int b_cs = (((lane >> 3) & 1) * 8) * 2;
    const int lr = tid >> 1;
    const int lc = tid & 1;

#define LOAD_H(S_)                                                              \
    do {                                                                        \
        const int k0_ = (S_) << 4;                                              \
        uint32_t tb = sb + ((S_) & (NSTG - 1)) * LSTG + lr * RB + lc * 16;      \
        const int ac_ = k0_ + lc * 8;                                           \
        cpasync16(tb,              Ah + (size_t)(m0 + lr) * ldk + ac_);         \
        cpasync16(tb + TILE16,     Al + (size_t)(m0 + lr) * ldk + ac_);         \
        cpasync16(tb + 2 * TILE16, Bh + (size_t)(n0 + lr) * ldk + ac_);         \
    } while (0)

#pragma unroll
    for (int s = 0; s < NSTG - 1; s++) { LOAD_H(s); CP_COMMIT(); }

    for (int s = 0; s < NS; s++) {
        CP_WAIT(NSTG - 2);
        __syncthreads();

        const uint32_t st = sb + (s & (NSTG - 1)) * LSTG;
        uint32_t Af[4][4], Bf[2][4];
#pragma unroll
        for (int mf = 0; mf < 4; mf++)
            ldsm4(Af[mf], st + (wm + mf * 16 + a_row) * RB + a_cs);
#pragma unroll
        for (int p = 0; p < 2; p++)
            ldsm4(Bf[p], st + 2 * TILE16 + (wn + p * 16 + b_row) * RB + b_cs);
#pragma unroll
        for (int mf = 0; mf < 4; mf++)
#pragma unroll
            for (int nf = 0; nf < 4; nf++)
                mma16816h(Cf[mf][nf], Af[mf], &Bf[nf >> 1][(nf & 1) * 2]);
#pragma unroll
        for (int mf = 0; mf < 4; mf++)
            ldsm4(Af[mf], st + TILE16 + (wm + mf * 16 + a_row) * RB + a_cs);
#pragma unroll
        for (int mf = 0; mf < 4; mf++)
#pragma unroll
            for (int nf = 0; nf < 4; nf++)
                mma16816h(Cf[mf][nf], Af[mf], &Bf[nf >> 1][(nf & 1) * 2]);

        if (s + NSTG - 1 < NS) LOAD_H(s + NSTG - 1);
        CP_COMMIT();
    }
#undef LOAD_H

    const int g = lane >> 2, t2 = (lane & 3) * 2;
#pragma unroll
    for (int mf = 0; mf < 4; mf++) {
#pragma unroll
        for (int nf = 0; nf < 4; nf++) {
            int n = n0 + wn + nf * 8 + t2;
#pragma unroll
            for (int hrow = 0; hrow < 2; hrow++) {
                int m = m0 + wm + mf * 16 + g + hrow * 8;
                float v0 = Cf[mf][nf][hrow * 2 + 0];
                float v1 = Cf[mf][nf][hrow * 2 + 1];
                if (EPI == 0) {
                    if (bias) { v0 += bias[n]; v1 += bias[n + 1]; }
                    *(float2*)&C[(size_t)m * N + n] = make_float2(v0, v1);
                } else if (EPI == 5) {
                    v0 = (v0 + bias[n]) * sc;
                    v1 = (v1 + bias[n + 1]) * sc;
                    __half h0, l0, h1, l1;
                    split1h(v0, h0, l0); split1h(v1, h1, l1);
                    *(__half2*)&Chi[(size_t)m * N + n] = __half2(h0, h1);
                    if (Clo)
                        *(__half2*)&Clo[(size_t)m * N + n] = __half2(l0, l1);
                } else {
                    v0 = fmaxf(v0 + bias[n], 0.f);
                    v1 = fmaxf(v1 + bias[n + 1], 0.f);
                    __half h0, l0, h1, l1;
                    split1h(v0, h0, l0); split1h(v1, h1, l1);
                    *(__half2*)&Chi[(size_t)m * N + n] = __half2(h0, h1);
                    *(__half2*)&Clo[(size_t)m * N + n] = __half2(l0, l1);
                }
            }
        }
    }
}

__global__ __launch_bounds__(256, 2)
void lm_gemm(const __half* __restrict__ Ah, const __half* __restrict__ Al,
             const __half* __restrict__ Bh, float* __restrict__ C, int N, int K) {
    extern __shared__ char smem_raw[];
    hgemm_core<0>(Ah, Al, Bh, nullptr, 1.0f, C, nullptr, nullptr,
                  blockIdx.y * 128, blockIdx.x * 128, N, K, K, smem_u32(smem_raw));
}

// W1: relu + fp16 split out
__global__ __launch_bounds__(256, 2)
void ffn1_gemm(const __half* __restrict__ Ah, const __half* __restrict__ Al,
               const __half* __restrict__ Bh, const float* __restrict__ bias,
               __half* __restrict__ Chi, __half* __restrict__ Clo, int N, int K) {
    extern __shared__ char smem_raw[];
    hgemm_core<6>(Ah, Al, Bh, bias, 1.0f, nullptr, Chi, Clo,
                  blockIdx.y * 128, blockIdx.x * 128, N, K, K, smem_u32(smem_raw));
}

// split-K partial GEMM (O-proj, W2): grid.z = K-split; fp32 partials; bias at z==0
__global__ __launch_bounds__(256, 2)
void hgemm_pk(const __half* __restrict__ Ah, const __half* __restrict__ Al,
              const __half* __restrict__ Bh, const float* __restrict__ bias,
              float* __restrict__ P, int N, int Kfull, int Ks) {
    extern __shared__ char smem_raw[];
    const int z = blockIdx.z;
    const int k0 = z * Ks;
    hgemm_core<0>(Ah + k0, Al + k0, Bh + k0,
                  z == 0 ? bias : nullptr, 1.0f,
                  P + (size_t)z * MTOK * N, nullptr, nullptr,
                  blockIdx.y * 128, blockIdx.x * 128, N, Ks, Kfull, smem_u32(smem_raw));
}

__global__ __launch_bounds__(256, 2)
void qkv16_gemm(const __half* __restrict__ Ah, const __half* __restrict__ Al,
                const __half* __restrict__ wq, const __half* __restrict__ wk,
                const __half* __restrict__ wv,
                const float* __restrict__ bq, const float* __restrict__ bk,
                const float* __restrict__ bv,
                __half* __restrict__ qh, __half* __restrict__ ql,
                __half* __restrict__ k16, __half* __restrict__ v16) {
    extern __shared__ char smem_raw[];
    const int which = blockIdx.x / 6, nb = blockIdx.x % 6;
    const __half* B = (which == 0) ? wq : (which == 1) ? wk : wv;
    const float* bias = (which == 0) ? bq : (which == 1) ? bk : bv;
    __half* Ch = (which == 0) ? qh : (which == 1) ? k16 : v16;
    __half* Cl = (which == 0) ? ql : nullptr;
    float sc = (which == 0) ? 0.125f : 1.0f;
    hgemm_core<5>(Ah, Al, B, bias, sc, nullptr, Ch, Cl,
                  blockIdx.y * 128, nb * 128, DD, DD, DD, smem_u32(smem_raw));
}

// ---------------- fp16 2-pass MMA flash attention ----------------------------
#define AST 144
#define ATILE (64*AST)
#define ATT_SMEM16 (2*ATILE + 2*2*ATILE)   /* 55296 */

__device__ __forceinline__ void att_load4(uint32_t dst, const void* src,
                                          size_t grow0, int hcol, int tid) {
    int r = tid >> 1, c0 = (tid & 1) * 4;
    const char* p = (const char*)src + ((grow0 + r) * DD + hcol + c0 * 8) * 2;
    uint32_t d = dst + r * AST + c0 * 16;
#pragma unroll
    for (int i = 0; i < 4; i++) cpasync16(d + i * 16, p + i * 16);
}

__global__ __launch_bounds__(128)
void flash_attn(const __half* __restrict__ qh, const __half* __restrict__ ql,
                const __half* __restrict__ k16, const __half* __restrict__ v16,
                __half* __restrict__ chi, __half* __restrict__ clo) {
    const int qt = gridDim.x - 1 - blockIdx.x;
    const int hd = blockIdx.y, b = blockIdx.z;
    extern __shared__ char smc[];
    const uint32_t sb = smem_u32(smc);
    const uint32_t Qh_s = sb, Ql_s = sb + ATILE;
    const uint32_t KV = sb + 2 * ATILE;

    const int tid = threadIdx.x, wid = tid >> 5, lane = tid & 31;
    const size_t qrow0 = (size_t)(b * SS + qt * 64);
    const int hcol = hd * DK;

    att_load4(Qh_s, qh, qrow0, hcol, tid);
    att_load4(Ql_s, ql, qrow0, hcol, tid);
    {
        size_t kr = (size_t)(b * SS);
        att_load4(KV,         k16, kr, hcol, tid);
        att_load4(KV + ATILE, v16, kr, hcol, tid);
    }
    CP_COMMIT();

    float O[8][4];
    float mrow[2] = { -1e30f, -1e30f };
    float lrow[2] = { 0.f, 0.f };
#pragma unroll
    for (int nt = 0; nt < 8; nt++)
#pragma unroll
        for (int x = 0; x < 4; x++) O[nt][x] = 0.f;

    const int g = lane >> 2, t2q = (lane & 3) * 2;
    const int a_row = wid * 16 + (lane & 15);
    const uint32_t a_cs = ((lane >> 4) << 3) * 2;
    const int b_row = (lane & 7) + (((lane >> 4) & 1) << 3);
    const uint32_t b_cs = (((lane >> 3) & 1) << 3) * 2;
    const int v_row = (lane & 15);
    const uint32_t v_cs = ((lane >> 4) << 3) * 2;

    for (int jt = 0; jt <= qt; jt++) {
        if (jt < qt) {
            size_t kr = (size_t)(b * SS + (jt + 1) * 64);
            uint32_t nb = KV + ((jt + 1) & 1) * (2 * ATILE);
            att_load4(nb,         k16, kr, hcol, tid);
            att_load4(nb + ATILE, v16, kr, hcol, tid);
            CP_COMMIT();
            CP_WAIT(1);
        } else {
            CP_WAIT(0);
        }
        __syncthreads();

        const uint32_t Kh_s = KV + (jt & 1) * (2 * ATILE);
        const uint32_t Vh_s = Kh_s + ATILE;

        float S[8][4];
#pragma unroll
        for (int nt = 0; nt < 8; nt++)
#pragma unroll
            for (int x = 0; x < 4; x++) S[nt][x] = 0.f;

#pragma unroll
        for (int ks = 0; ks < 4; ks++) {
            uint32_t Qhf[4], Qlf[4];
            ldsm4(Qhf, Qh_s + a_row * AST + ks * 32 + a_cs);
            ldsm4(Qlf, Ql_s + a_row * AST + ks * 32 + a_cs);
#pragma unroll
            for (int p = 0; p < 4; p++) {
                uint32_t Kf[4];
                ldsm4(Kf, Kh_s + (p * 16 + b_row) * AST + ks * 32 + b_cs);
#pragma unroll
                for (int q = 0; q < 2; q++) {
                    mma16816h(S[p * 2 + q], Qhf, &Kf[q * 2]);
                    mma16816h(S[p * 2 + q], Qlf, &Kf[q * 2]);
                }
            }
        }

        const bool diag = (jt == qt);
#pragma unroll
        for (int half = 0; half < 2; half++) {
            const int rloc = wid * 16 + g + half * 8;
            float mt = -1e30f;
#pragma unroll
            for (int nt = 0; nt < 8; nt++) {
                float s0 = S[nt][half * 2], s1 = S[nt][half * 2 + 1];
                if (diag) {
                    if (nt * 8 + t2q > rloc)     s0 = -1e30f;
                    if (nt * 8 + t2q + 1 > rloc) s1 = -1e30f;
                }
                S[nt][half * 2] = s0; S[nt][half * 2 + 1] = s1;
                mt = fmaxf(mt, fmaxf(s0, s1));
            }
            mt = fmaxf(mt, __shfl_xor_sync(0xffffffffu, mt, 1));
            mt = fmaxf(mt, __shfl_xor_sync(0xffffffffu, mt, 2));
            float mn = fmaxf(mrow[half], mt);
            float f = __expf(mrow[half] - mn);
            mrow[half] = mn;
            float rs = 0.f;
#pragma unroll
            for (int nt = 0; nt < 8; nt++) {
                float e0 = __expf(S[nt][half * 2] - mn);
                float e1 = __expf(S[nt][half * 2 + 1] - mn);
                S[nt][half * 2] = e0; S[nt][half * 2 + 1] = e1;
                rs += e0 + e1;
            }
            rs += __shfl_xor_sync(0xffffffffu, rs, 1);
            rs += __shfl_xor_sync(0xffffffffu, rs, 2);
            lrow[half] = lrow[half] * f + rs;
#pragma unroll
            for (int nt = 0; nt < 8; nt++) {
                O[nt][half * 2] *= f; O[nt][half * 2 + 1] *= f;
            }
        }

#pragma unroll
        for (int ks = 0; ks < 4; ks++) {
            uint32_t Ph[4], Pl[4];
#pragma unroll
            for (int q4 = 0; q4 < 4; q4++) {
                int tile = 2 * ks + (q4 >> 1);
                int o = (q4 & 1) * 2;
                float v0 = S[tile][o], v1 = S[tile][o + 1];
                __half h0 = __float2half(v0), h1 = __float2half(v1);
                __half2 hh(h0, h1);
                Ph[q4] = *(uint32_t*)&hh;
                Pl[q4] = packh(v0 - __half2float(h0), v1 - __half2float(h1));
            }
#pragma unroll
            for (int nt = 0; nt < 4; nt++) {
                uint32_t Vf[4];
                ldsm4t(Vf, Vh_s + (ks * 16 + v_row) * AST + nt * 32 + v_cs);
#pragma unroll
                for (int q = 0; q < 2; q++) {
                    mma16816h(O[nt * 2 + q], Ph, &Vf[q * 2]);
                    mma16816h(O[nt * 2 + q], Pl, &Vf[q * 2]);
                }
            }
        }
        __syncthreads();
    }

    float inv[2] = { 1.0f / lrow[0], 1.0f / lrow[1] };
#pragma unroll
    for (int nt = 0; nt < 8; nt++) {
#pragma unroll
        for (int half = 0; half < 2; half++) {
            size_t row = qrow0 + wid * 16 + g + half * 8;
            int col = hcol + nt * 8 + t2q;
            float v0 = O[nt][half * 2] * inv[half];
            float v1 = O[nt][half * 2 + 1] * inv[half];
            __half h0, l0, h1, l1;
            split1h(v0, h0, l0); split1h(v1, h1, l1);
            *(__half2*)&chi[row * DD + col] = __half2(h0, h1);
            *(__half2*)&clo[row * DD + col] = __half2(l0, l1);
        }
    }
}

// ---------------- driver -----------------------------------------------------
extern "C" void kernel_launch(void* const* d_in, const int* in_sizes, int n_in,
                              void* d_out, int out_size) {
    (void)in_sizes; (void)n_in; (void)out_size;
    const float* tok  = (const float*)d_in[1];
    const float* pos  = (const float*)d_in[2];
    const float* bq   = (const float*)d_in[4];
    const float* bk   = (const float*)d_in[6];
    const float* bv   = (const float*)d_in[8];
    const float* bo   = (const float*)d_in[10];
    const float* b1   = (const float*)d_in[12];
    const float* b2   = (const float*)d_in[14];
    const float* ln1g = (const float*)d_in[15];
    const float* ln1b = (const float*)d_in[16];
    const float* ln2g = (const float*)d_in[17];
    const float* ln2b = (const float*)d_in[18];
    const float* lnfg = (const float*)d_in[19];
    const float* lnfb = (const float*)d_in[20];
    float* out = (float*)d_out;

    float *h, *pp;
    cudaGetSymbolAddress((void**)&h,  g_h);
    cudaGetSymbolAddress((void**)&pp, g_p);

    __half *t16, *e16h, *e16l, *w16q, *w16k, *w16v, *w16o, *w16f1, *w16f2;
    __half *q16h, *q16l, *k16, *v16, *a16h, *a16l, *f16h, *f16l;
    cudaGetSymbolAddress((void**)&t16,   g_t16);
    cudaGetSymbolAddress((void**)&e16h,  g_e16h);
    cudaGetSymbolAddress((void**)&e16l,  g_e16l);
    cudaGetSymbolAddress((void**)&w16q,  g_w16q);
    cudaGetSymbolAddress((void**)&w16k,  g_w16k);
    cudaGetSymbolAddress((void**)&w16v,  g_w16v);
    cudaGetSymbolAddress((void**)&w16o,  g_w16o);
    cudaGetSymbolAddress((void**)&w16f1, g_w16f1);
    cudaGetSymbolAddress((void**)&w16f2, g_w16f2);
    cudaGetSymbolAddress((void**)&q16h,  g_q16h);
    cudaGetSymbolAddress((void**)&q16l,  g_q16l);
    cudaGetSymbolAddress((void**)&k16,   g_k16);
    cudaGetSymbolAddress((void**)&v16,   g_v16);
    cudaGetSymbolAddress((void**)&a16h,  g_a16h);
    cudaGetSymbolAddress((void**)&a16l,  g_a16l);
    cudaGetSymbolAddress((void**)&f16h,  g_f16h);
    cudaGetSymbolAddress((void**)&f16l,  g_f16l);

    cudaFuncSetAttribute(qkv16_gemm, cudaFuncAttributeMaxDynamicSharedMemorySize, GSMEM_H);
    cudaFuncSetAttribute(ffn1_gemm,  cudaFuncAttributeMaxDynamicSharedMemorySize, GSMEM_H);
    cudaFuncSetAttribute(hgemm_pk,   cudaFuncAttributeMaxDynamicSharedMemorySize, GSMEM_H);
    cudaFuncSetAttribute(lm_gemm,    cudaFuncAttributeMaxDynamicSharedMemorySize, GSMEM_H);
    cudaFuncSetAttribute(flash_attn, cudaFuncAttributeMaxDynamicSharedMemorySize, ATT_SMEM16);

    // launch 0: embed
    embedcvt_kernel<<<(MTOK * DD + 255) / 256, 256>>>((const long long*)d_in[0], tok, pos);
    // launch 1: all six layer weight tensors -> fp16
    {
        const int nD4 = LL * DD * DD / 4;
        const int nF4 = LL * FF * DD / 4;
        dim3 gw((nF4 + 255) / 256, 6);
        cvtw6_kernel<<<gw, 256>>>(
            (const float4*)d_in[3],  (__half2*)w16q,  nD4,
            (const float4*)d_in[5],  (__half2*)w16k,  nD4,
            (const float4*)d_in[7],  (__half2*)w16v,  nD4,
            (const float4*)d_in[9],  (__half2*)w16o,  nD4,
            (const float4*)d_in[11], (__half2*)w16f1, nF4,
            (const float4*)d_in[13], (__half2*)w16f2, nF4);
    }

    dim3 gQKV(18, MTOK / 128);           // (18, 16)
    dim3 gPK(DD / 128, MTOK / 128, 3);   // (6, 16, 3)
    dim3 gF(FF / 128, MTOK / 128);       // (24, 16)
    dim3 gV(VV / 128, MTOK / 128);       // (250, 16)
    dim3 gA(SS / 64, HH, BB);            // (16, 12, 2)
    const int gLN = MTOK / 8;

    for (int l = 0; l < LL; l++) {
        const size_t wD = (size_t)l * DD * DD;
        if (l == 0)
            ln16_kernel<<<gLN, 256>>>(h, ln1g, ln1b, e16h, e16l);          // launch 2
        else
            ln_res16_kernel<<<gLN, 256>>>(h, pp, ln1g + l * DD, ln1b + l * DD, e16h, e16l);
        qkv16_gemm<<<gQKV, 256, GSMEM_H>>>(e16h, e16l,                     // launch 3 (l=0) — profiled
                                           w16q + wD, w16k + wD, w16v + wD,
                                           bq + l * DD, bk + l * DD, bv + l * DD,
                                           q16h, q16l, k16, v16);
        flash_attn<<<gA, 128, ATT_SMEM16>>>(q16h, q16l, k16, v16, a16h, a16l);
        hgemm_pk<<<gPK, 256, GSMEM_H>>>(a16h, a16l, w16o + wD, bo + l * DD,
                                        pp, DD, DD, DD / 3);
        ln_res16_kernel<<<gLN, 256>>>(h, pp, ln2g + l * DD, ln2b + l * DD, e16h, e16l);
        ffn1_gemm<<<gF, 256, GSMEM_H>>>(e16h, e16l, w16f1 + (size_t)l * FF * DD,
                                        b1 + l * FF, f16h, f16l, FF, DD);
        hgemm_pk<<<gPK, 256, GSMEM_H>>>(f16h, f16l, w16f2 + (size_t)l * DD * FF,
                                        b2 + l * DD, pp, DD, FF, FF / 3);
    }

    // LM head
    {
        int n4 = VV * DD / 4;
        cvt16_kernel<<<(n4 + 255) / 256, 256>>>((const float4*)tok, (__half2*)t16, n4);
    }
    ln_res16_kernel<<<gLN, 256>>>(h, pp, lnfg, lnfb, e16h, e16l);
    lm_gemm<<<gV, 256, GSMEM_H>>>(e16h, e16l, t16, out, VV, DD);
}

// round 13
// speedup vs baseline: 1.5609x; 1.1456x over previous
#include <cuda_runtime.h>
#include <cuda_bf16.h>
#include <cuda_fp16.h>
#include <cstdint>
#include <math.h>

#define BB 2
#define SS 1024
#define DD 768
#define HH 12
#define DK 64
#define FF 3072
#define LL 4
#define VV 32000
#define MTOK (BB*SS)   /* 2048 */

// ---------------- scratch ----------------------------------------------------
__device__ float g_h  [MTOK*DD];
__device__ float g_p  [3*MTOK*DD];        // split-K partials
__device__ __half g_t16 [VV*DD];          // tok_emb fp16 (LM head B)
__device__ __half g_e16h[MTOK*DD], g_e16l[MTOK*DD];   // LN outputs fp16 hi/lo
__device__ __half g_w16q[LL*DD*DD], g_w16k[LL*DD*DD], g_w16v[LL*DD*DD];
__device__ __half g_w16o[LL*DD*DD];
__device__ __half g_w16f1[LL*FF*DD], g_w16f2[LL*DD*FF];
__device__ __half g_q16h[MTOK*DD], g_q16l[MTOK*DD];
__device__ __half g_k16 [MTOK*DD], g_v16 [MTOK*DD];
__device__ __half g_a16h[MTOK*DD], g_a16l[MTOK*DD];   // attention ctx fp16 hi/lo
__device__ __half g_f16h[MTOK*FF], g_f16l[MTOK*FF];   // relu(ffn) fp16 hi/lo

// ---------------- helpers ----------------------------------------------------
__device__ __forceinline__ uint32_t smem_u32(const void* p) {
    uint32_t a;
    asm("{ .reg .u64 t; cvta.to.shared.u64 t, %1; cvt.u32.u64 %0, t; }" : "=r"(a) : "l"(p));
    return a;
}
__device__ __forceinline__ void cpasync16(uint32_t saddr, const void* gaddr) {
    asm volatile("cp.async.cg.shared.global [%0], [%1], 16;" :: "r"(saddr), "l"(gaddr));
}
#define CP_COMMIT() asm volatile("cp.async.commit_group;" ::: "memory")
#define CP_WAIT(N)  asm volatile("cp.async.wait_group %0;" :: "n"(N) : "memory")

__device__ __forceinline__ void ldsm4(uint32_t* r, uint32_t addr) {
    asm volatile("ldmatrix.sync.aligned.m8n8.x4.shared.b16 {%0,%1,%2,%3}, [%4];"
        : "=r"(r[0]), "=r"(r[1]), "=r"(r[2]), "=r"(r[3]) : "r"(addr));
}
__device__ __forceinline__ void ldsm4t(uint32_t* r, uint32_t addr) {
    asm volatile("ldmatrix.sync.aligned.m8n8.x4.trans.shared.b16 {%0,%1,%2,%3}, [%4];"
        : "=r"(r[0]), "=r"(r[1]), "=r"(r[2]), "=r"(r[3]) : "r"(addr));
}
__device__ __forceinline__ void mma16816h(float* c, const uint32_t* a, const uint32_t* b) {
    asm volatile(
        "mma.sync.aligned.m16n8k16.row.col.f32.f16.f16.f32 "
        "{%0,%1,%2,%3}, {%4,%5,%6,%7}, {%8,%9}, {%0,%1,%2,%3};"
        : "+f"(c[0]), "+f"(c[1]), "+f"(c[2]), "+f"(c[3])
        : "r"(a[0]), "r"(a[1]), "r"(a[2]), "r"(a[3]), "r"(b[0]), "r"(b[1]));
}
__device__ __forceinline__ void split1h(float v, __half& h, __half& l) {
    h = __float2half(v);
    l = __float2half(v - __half2float(h));
}
__device__ __forceinline__ uint32_t packh(float v0, float v1) {
    __half2 p(__float2half(v0), __float2half(v1));
    return *(uint32_t*)&p;
}

// ---------------- embed ------------------------------------------------------
__global__ void embedcvt_kernel(const long long* __restrict__ x64,
                                const float* __restrict__ tok,
                                const float* __restrict__ pos) {
    __shared__ int is64s;
    if (threadIdx.x == 0) {
        int ok = 1;
        for (int i = 0; i < 16; i++) { long long t = x64[i]; if (t < 0 || t >= VV) ok = 0; }
        is64s = ok;
    }
    __syncthreads();
    int idx = blockIdx.x * blockDim.x + threadIdx.x;
    if (idx < MTOK * DD) {
        int d = idx % DD, t = idx / DD, s = t % SS;
        int tokid = is64s ? (int)x64[t] : ((const int*)x64)[t];
        g_h[idx] = tok[tokid * DD + d] + pos[s * DD + d];
    }
}

// ---------------- warp-per-row layernorms -> fp16 hi/lo ----------------------
__global__ __launch_bounds__(256)
void ln16_kernel(const float* __restrict__ in, const float* __restrict__ g,
                 const float* __restrict__ b,
                 __half* __restrict__ ohi, __half* __restrict__ olo) {
    const int wid = threadIdx.x >> 5, lane = threadIdx.x & 31;
    const int row = blockIdx.x * 8 + wid;
    const float4* xr = (const float4*)(in + (size_t)row * DD);
    float4 v[6];
    float s1 = 0.f, s2 = 0.f;
#pragma unroll
    for (int i = 0; i < 6; i++) {
        v[i] = xr[lane + 32 * i];
        s1 += v[i].x + v[i].y + v[i].z + v[i].w;
        s2 += v[i].x*v[i].x + v[i].y*v[i].y + v[i].z*v[i].z + v[i].w*v[i].w;
    }
#pragma unroll
    for (int o = 16; o > 0; o >>= 1) {
        s1 += __shfl_xor_sync(0xffffffffu, s1, o);
        s2 += __shfl_xor_sync(0xffffffffu, s2, o);
    }
    float mu = s1 * (1.0f / DD);
    float inv = rsqrtf(s2 * (1.0f / DD) - mu * mu + 1e-5f);
    const float4* gg = (const float4*)g;
    const float4* bb = (const float4*)b;
#pragma unroll
    for (int i = 0; i < 6; i++) {
        int e4 = lane + 32 * i;
        float4 gv = gg[e4], bv = bb[e4];
        float o0 = (v[i].x - mu) * inv * gv.x + bv.x;
        float o1 = (v[i].y - mu) * inv * gv.y + bv.y;
        float o2 = (v[i].z - mu) * inv * gv.z + bv.z;
        float o3 = (v[i].w - mu) * inv * gv.w + bv.w;
        __half h0,l0,h1,l1,h2,l2,h3,l3;
        split1h(o0,h0,l0); split1h(o1,h1,l1); split1h(o2,h2,l2); split1h(o3,h3,l3);
        size_t base = (size_t)row * DD + e4 * 4;
        *(__half2*)&ohi[base]     = __half2(h0, h1);
        *(__half2*)&ohi[base + 2] = __half2(h2, h3);
        *(__half2*)&olo[base]     = __half2(l0, l1);
        *(__half2*)&olo[base + 2] = __half2(l2, l3);
    }
}

// h += P0+P1+P2 (written back), then LN -> fp16 hi/lo
__global__ __launch_bounds__(256)
void ln_res16_kernel(float* __restrict__ h, const float* __restrict__ p,
                     const float* __restrict__ g, const float* __restrict__ b,
                     __half* __restrict__ ohi, __half* __restrict__ olo) {
    const int wid = threadIdx.x >> 5, lane = threadIdx.x & 31;
    const int row = blockIdx.x * 8 + wid;
    float4* hr = (float4*)(h + (size_t)row * DD);
    const float4* p0 = (const float4*)(p + (size_t)row * DD);
    const float4* p1 = (const float4*)(p + (size_t)MTOK * DD + (size_t)row * DD);
    const float4* p2 = (const float4*)(p + 2 * (size_t)MTOK * DD + (size_t)row * DD);
    float4 v[6];
    float s1 = 0.f, s2 = 0.f;
#pragma unroll
    for (int i = 0; i < 6; i++) {
        int e4 = lane + 32 * i;
        float4 hv = hr[e4], a0 = p0[e4], a1 = p1[e4], a2 = p2[e4];
        hv.x += a0.x + a1.x + a2.x;
        hv.y += a0.y + a1.y + a2.y;
        hv.z += a0.z + a1.z + a2.z;
        hv.w += a0.w + a1.w + a2.w;
        hr[e4] = hv;
        v[i] = hv;
        s1 += hv.x + hv.y + hv.z + hv.w;
        s2 += hv.x*hv.x + hv.y*hv.y + hv.z*hv.z + hv.w*hv.w;
    }
#pragma unroll
    for (int o = 16; o > 0; o >>= 1) {
        s1 += __shfl_xor_sync(0xffffffffu, s1, o);
        s2 += __shfl_xor_sync(0xffffffffu, s2, o);
    }
    float mu = s1 * (1.0f / DD);
    float inv = rsqrtf(s2 * (1.0f / DD) - mu * mu + 1e-5f);
    const float4* gg = (const float4*)g;
    const float4* bb = (const float4*)b;
#pragma unroll
    for (int i = 0; i < 6; i++) {
        int e4 = lane + 32 * i;
        float4 gv = gg[e4], bv = bb[e4];
        float o0 = (v[i].x - mu) * inv * gv.x + bv.x;
        float o1 = (v[i].y - mu) * inv * gv.y + bv.y;
        float o2 = (v[i].z - mu) * inv * gv.z + bv.z;
        float o3 = (v[i].w - mu) * inv * gv.w + bv.w;
        __half h0,l0,h1,l1,h2,l2,h3,l3;
        split1h(o0,h0,l0); split1h(o1,h1,l1); split1h(o2,h2,l2); split1h(o3,h3,l3);
        size_t base = (size_t)row * DD + e4 * 4;
        *(__half2*)&ohi[base]     = __half2(h0, h1);
        *(__half2*)&ohi[base + 2] = __half2(h2, h3);
        *(__half2*)&olo[base]     = __half2(l0, l1);
        *(__half2*)&olo[base + 2] = __half2(l2, l3);
    }
}

// ---------------- fp32 -> fp16 weight converts -------------------------------
__global__ void cvt16_kernel(const float4* __restrict__ x, __half2* __restrict__ o, int n4) {
    int i = blockIdx.x * blockDim.x + threadIdx.x;
    if (i < n4) {
        float4 v = x[i];
        o[2*i]   = __floats2half2_rn(v.x, v.y);
        o[2*i+1] = __floats2half2_rn(v.z, v.w);
    }
}

__global__ void cvtw6_kernel(const float4* s0, __half2* o0, int n0,
                             const float4* s1, __half2* o1, int n1,
                             const float4* s2, __half2* o2, int n2,
                             const float4* s3, __half2* o3, int n3,
                             const float4* s4, __half2* o4, int n4_,
                             const float4* s5, __half2* o5, int n5) {
    const float4* s; __half2* o; int n;
    switch (blockIdx.y) {
        case 0: s = s0; o = o0; n = n0; break;
        case 1: s = s1; o = o1; n = n1; break;
        case 2: s = s2; o = o2; n = n2; break;
        case 3: s = s3; o = o3; n = n3; break;
        case 4: s = s4; o = o4; n = n4_; break;
        default: s = s5; o = o5; n = n5; break;
    }
    int i = blockIdx.x * blockDim.x + threadIdx.x;
    if (i < n) {
        float4 v = s[i];
        o[2*i]   = __floats2half2_rn(v.x, v.y);
        o[2*i+1] = __floats2half2_rn(v.z, v.w);
    }
}

// ---------------- fp16 2-pass GEMM core --------------------------------------
#define RB     48
#define TILE16 (128*RB)                  /* 6144 B  */
#define NSTG   4
#define LSTG   (3*TILE16)                /* 18432 */
#define GSMEM_H (NSTG*LSTG)              /* 73728 */

// EPI: 0 f32 out (+opt bias), 5 fp16split+bias+scale (opt lo), 6 relu+bias+fp16split
template<int EPI>
__device__ __forceinline__ void hgemm_core(
        const __half* Ah, const __half* Al, const __half* Bh,
        const float* bias, float sc,
        float* C, __half* Chi, __half* Clo,
        int m0, int n0, int N, int K, int ldk, uint32_t sb) {
    const int tid = threadIdx.x;
    const int wid = tid >> 5, lane = tid & 31;
    const int wm = (wid >> 2) * 64;
    const int wn = (wid & 3) * 32;

    float Cf[4][4][4];
#pragma unroll
    for (int i = 0; i < 4; i++)
#pragma unroll
        for (int j = 0; j < 4; j++)
#pragma unroll
            for (int x = 0; x < 4; x++) Cf[i][j][x] = 0.f;

    const int NS = K >> 4;
    const int a_row = (lane & 15);
    const int a_cs = ((lane >> 4) * 8) * 2;
    const int b_row = (lane & 7) + ((lane >> 4) & 1) * 8;
    const int b_cs = (((lane >> 3) & 1) * 8) * 2;
    const int lr = tid >> 1;
    const int lc = tid & 1;

#define LOAD_H(S_)                                                              \
    do {                                                                        \
        const int k0_ = (S_) << 4;                                              \
        uint32_t tb = sb + ((S_) & (NSTG - 1)) * LSTG + lr * RB + lc * 16;      \
        const int ac_ = k0_ + lc * 8;                                           \
        cpasync16(tb,              Ah + (size_t)(m0 + lr) * ldk + ac_);         \
        cpasync16(tb + TILE16,     Al + (size_t)(m0 + lr) * ldk + ac_);         \
        cpasync16(tb + 2 * TILE16, Bh + (size_t)(n0 + lr) * ldk + ac_);         \
    } while (0)

#pragma unroll
    for (int s = 0; s < NSTG - 1; s++) { LOAD_H(s); CP_COMMIT(); }

    for (int s = 0; s < NS; s++) {
        CP_WAIT(NSTG - 2);
        __syncthreads();

        const uint32_t st = sb + (s & (NSTG - 1)) * LSTG;
        uint32_t Af[4][4], Bf[2][4];
#pragma unroll
        for (int mf = 0; mf < 4; mf++)
            ldsm4(Af[mf], st + (wm + mf * 16 + a_row) * RB + a_cs);
#pragma unroll
        for (int p = 0; p < 2; p++)
            ldsm4(Bf[p], st + 2 * TILE16 + (wn + p * 16 + b_row) * RB + b_cs);
#pragma unroll
        for (int mf = 0; mf < 4; mf++)
#pragma unroll
            for (int nf = 0; nf < 4; nf++)
                mma16816h(Cf[mf][nf], Af[mf], &Bf[nf >> 1][(nf & 1) * 2]);
#pragma unroll
        for (int mf = 0; mf < 4; mf++)
            ldsm4(Af[mf], st + TILE16 + (wm + mf * 16 + a_row) * RB + a_cs);
#pragma unroll
        for (int mf = 0; mf < 4; mf++)
#pragma unroll
            for (int nf = 0; nf < 4; nf++)
                mma16816h(Cf[mf][nf], Af[mf], &Bf[nf >> 1][(nf & 1) * 2]);

        if (s + NSTG - 1 < NS) LOAD_H(s + NSTG - 1);
        CP_COMMIT();
    }
#undef LOAD_H

    const int g = lane >> 2, t2 = (lane & 3) * 2;
#pragma unroll
    for (int mf = 0; mf < 4; mf++) {
#pragma unroll
        for (int nf = 0; nf < 4; nf++) {
            int n = n0 + wn + nf * 8 + t2;
#pragma unroll
            for (int hrow = 0; hrow < 2; hrow++) {
                int m = m0 + wm + mf * 16 + g + hrow * 8;
                float v0 = Cf[mf][nf][hrow * 2 + 0];
                float v1 = Cf[mf][nf][hrow * 2 + 1];
                if (EPI == 0) {
                    if (bias) { v0 += bias[n]; v1 += bias[n + 1]; }
                    *(float2*)&C[(size_t)m * N + n] = make_float2(v0, v1);
                } else if (EPI == 5) {
                    v0 = (v0 + bias[n]) * sc;
                    v1 = (v1 + bias[n + 1]) * sc;
                    __half h0, l0, h1, l1;
                    split1h(v0, h0, l0); split1h(v1, h1, l1);
                    *(__half2*)&Chi[(size_t)m * N + n] = __half2(h0, h1);
                    if (Clo)
                        *(__half2*)&Clo[(size_t)m * N + n] = __half2(l0, l1);
                } else {
                    v0 = fmaxf(v0 + bias[n], 0.f);
                    v1 = fmaxf(v1 + bias[n + 1], 0.f);
                    __half h0, l0, h1, l1;
                    split1h(v0, h0, l0); split1h(v1, h1, l1);
                    *(__half2*)&Chi[(size_t)m * N + n] = __half2(h0, h1);
                    *(__half2*)&Clo[(size_t)m * N + n] = __half2(l0, l1);
                }
            }
        }
    }
}

// ---------------- fp16 1-pass LM head GEMM (C = Ah @ Bh^T, fp32 out) ---------
#define L1STG   (2*TILE16)               /* 12288 */
#define GSMEM_L1 (NSTG*L1STG)            /* 49152 */

__global__ __launch_bounds__(256, 2)
void lm_gemm(const __half* __restrict__ Ah, const __half* __restrict__ Bh,
             float* __restrict__ C, int N, int K) {
    extern __shared__ char smem_raw[];
    const uint32_t sb = smem_u32(smem_raw);
    const int tid = threadIdx.x;
    const int wid = tid >> 5, lane = tid & 31;
    const int m0 = blockIdx.y * 128, n0 = blockIdx.x * 128;
    const int wm = (wid >> 2) * 64;
    const int wn = (wid & 3) * 32;

    float Cf[4][4][4];
#pragma unroll
    for (int i = 0; i < 4; i++)
#pragma unroll
        for (int j = 0; j < 4; j++)
#pragma unroll
            for (int x = 0; x < 4; x++) Cf[i][j][x] = 0.f;

    const int NS = K >> 4;
    const int a_row = (lane & 15);
    const int a_cs = ((lane >> 4) * 8) * 2;
    const int b_row = (lane & 7) + ((lane >> 4) & 1) * 8;
    const int b_cs = (((lane >> 3) & 1) * 8) * 2;
    const int lr = tid >> 1;
    const int lc = tid & 1;

#define LOAD_L1(S_)                                                             \
    do {                                                                        \
        const int k0_ = (S_) << 4;                                              \
        uint32_t tb = sb + ((S_) & (NSTG - 1)) * L1STG + lr * RB + lc * 16;     \
        const int ac_ = k0_ + lc * 8;                                           \
        cpasync16(tb,          Ah + (size_t)(m0 + lr) * K + ac_);               \
        cpasync16(tb + TILE16, Bh + (size_t)(n0 + lr) * K + ac_);               \
    } while (0)

#pragma unroll
    for (int s = 0; s < NSTG - 1; s++) { LOAD_L1(s); CP_COMMIT(); }

    for (int s = 0; s < NS; s++) {
        CP_WAIT(NSTG - 2);
        __syncthreads();

        const uint32_t st = sb + (s & (NSTG - 1)) * L1STG;
        uint32_t Af[4][4], Bf[2][4];
#pragma unroll
        for (int mf = 0; mf < 4; mf++)
            ldsm4(Af[mf], st + (wm + mf * 16 + a_row) * RB + a_cs);
#pragma unroll
        for (int p = 0; p < 2; p++)
            ldsm4(Bf[p], st + TILE16 + (wn + p * 16 + b_row) * RB + b_cs);
#pragma unroll
        for (int mf = 0; mf < 4; mf++)
#pragma unroll
            for (int nf = 0; nf < 4; nf++)
                mma16816h(Cf[mf][nf], Af[mf], &Bf[nf >> 1][(nf & 1) * 2]);

        if (s + NSTG - 1 < NS) LOAD_L1(s + NSTG - 1);
        CP_COMMIT();
    }
#undef LOAD_L1

    const int g = lane >> 2, t2 = (lane & 3) * 2;
#pragma unroll
    for (int mf = 0; mf < 4; mf++) {
#pragma unroll
        for (int nf = 0; nf < 4; nf++) {
            int n = n0 + wn + nf * 8 + t2;
#pragma unroll
            for (int hrow = 0; hrow < 2; hrow++) {
                int m = m0 + wm + mf * 16 + g + hrow * 8;
                *(float2*)&C[(size_t)m * N + n] =
                    make_float2(Cf[mf][nf][hrow * 2], Cf[mf][nf][hrow * 2 + 1]);
            }
        }
    }
}

// W1: relu + fp16 split out
__global__ __launch_bounds__(256, 2)
void ffn1_gemm(const __half* __restrict__ Ah, const __half* __restrict__ Al,
               const __half* __restrict__ Bh, const float* __restrict__ bias,
               __half* __restrict__ Chi, __half* __restrict__ Clo, int N, int K) {
    extern __shared__ char smem_raw[];
    hgemm_core<6>(Ah, Al, Bh, bias, 1.0f, nullptr, Chi, Clo,
                  blockIdx.y * 128, blockIdx.x * 128, N, K, K, smem_u32(smem_raw));
}

// split-K partial GEMM (O-proj, W2): grid.z = K-split; fp32 partials; bias at z==0
__global__ __launch_bounds__(256, 2)
void hgemm_pk(const __half* __restrict__ Ah, const __half* __restrict__ Al,
              const __half* __restrict__ Bh, const float* __restrict__ bias,
              float* __restrict__ P, int N, int Kfull, int Ks) {
    extern __shared__ char smem_raw[];
    const int z = blockIdx.z;
    const int k0 = z * Ks;
    hgemm_core<0>(Ah + k0, Al + k0, Bh + k0,
                  z == 0 ? bias : nullptr, 1.0f,
                  P + (size_t)z * MTOK * N, nullptr, nullptr,
                  blockIdx.y * 128, blockIdx.x * 128, N, Ks, Kfull, smem_u32(smem_raw));
}

__global__ __launch_bounds__(256, 2)
void qkv16_gemm(const __half* __restrict__ Ah, const __half* __restrict__ Al,
                const __half* __restrict__ wq, const __half* __restrict__ wk,
                const __half* __restrict__ wv,
                const float* __restrict__ bq, const float* __restrict__ bk,
                const float* __restrict__ bv,
                __half* __restrict__ qh, __half* __restrict__ ql,
                __half* __restrict__ k16, __half* __restrict__ v16) {
    extern __shared__ char smem_raw[];
    const int which = blockIdx.x / 6, nb = blockIdx.x % 6;
    const __half* B = (which == 0) ? wq : (which == 1) ? wk : wv;
    const float* bias = (which == 0) ? bq : (which == 1) ? bk : bv;
    __half* Ch = (which == 0) ? qh : (which == 1) ? k16 : v16;
    __half* Cl = (which == 0) ? ql : nullptr;
    float sc = (which == 0) ? 0.125f : 1.0f;
    hgemm_core<5>(Ah, Al, B, bias, sc, nullptr, Ch, Cl,
                  blockIdx.y * 128, nb * 128, DD, DD, DD, smem_u32(smem_raw));
}

// ---------------- fp16 2-pass MMA flash attention ----------------------------
#define AST 144
#define ATILE (64*AST)
#define ATT_SMEM16 (2*ATILE + 2*2*ATILE)   /* 55296 */

__device__ __forceinline__ void att_load4(uint32_t dst, const void* src,
                                          size_t grow0, int hcol, int tid) {
    int r = tid >> 1, c0 = (tid & 1) * 4;
    const char* p = (const char*)src + ((grow0 + r) * DD + hcol + c0 * 8) * 2;
    uint32_t d = dst + r * AST + c0 * 16;
#pragma unroll
    for (int i = 0; i < 4; i++) cpasync16(d + i * 16, p + i * 16);
}

__global__ __launch_bounds__(128)
void flash_attn(const __half* __restrict__ qh, const __half* __restrict__ ql,
                const __half* __restrict__ k16, const __half* __restrict__ v16,
                __half* __restrict__ chi, __half* __restrict__ clo) {
    const int qt = gridDim.x - 1 - blockIdx.x;
    const int hd = blockIdx.y, b = blockIdx.z;
    extern __shared__ char smc[];
    const uint32_t sb = smem_u32(smc);
    const uint32_t Qh_s = sb, Ql_s = sb + ATILE;
    const uint32_t KV = sb + 2 * ATILE;

    const int tid = threadIdx.x, wid = tid >> 5, lane = tid & 31;
    const size_t qrow0 = (size_t)(b * SS + qt * 64);
    const int hcol = hd * DK;

    att_load4(Qh_s, qh, qrow0, hcol, tid);
    att_load4(Ql_s, ql, qrow0, hcol, tid);
    {
        size_t kr = (size_t)(b * SS);
        att_load4(KV,         k16, kr, hcol, tid);
        att_load4(KV + ATILE, v16, kr, hcol, tid);
    }
    CP_COMMIT();

    float O[8][4];
    float mrow[2] = { -1e30f, -1e30f };
    float lrow[2] = { 0.f, 0.f };
#pragma unroll
    for (int nt = 0; nt < 8; nt++)
#pragma unroll
        for (int x = 0; x < 4; x++) O[nt][x] = 0.f;

    const int g = lane >> 2, t2q = (lane & 3) * 2;
    const int a_row = wid * 16 + (lane & 15);
    const uint32_t a_cs = ((lane >> 4) << 3) * 2;
    const int b_row = (lane & 7) + (((lane >> 4) & 1) << 3);
    const uint32_t b_cs = (((lane >> 3) & 1) << 3) * 2;
    const int v_row = (lane & 15);
    const uint32_t v_cs = ((lane >> 4) << 3) * 2;

    for (int jt = 0; jt <= qt; jt++) {
        if (jt < qt) {
            size_t kr = (size_t)(b * SS + (jt + 1) * 64);
            uint32_t nb = KV + ((jt + 1) & 1) * (2 * ATILE);
            att_load4(nb,         k16, kr, hcol, tid);
            att_load4(nb + ATILE, v16, kr, hcol, tid);
            CP_COMMIT();
            CP_WAIT(1);
        } else {
            CP_WAIT(0);
        }
        __syncthreads();

        const uint32_t Kh_s = KV + (jt & 1) * (2 * ATILE);
        const uint32_t Vh_s = Kh_s + ATILE;

        float S[8][4];
#pragma unroll
        for (int nt = 0; nt < 8; nt++)
#pragma unroll
            for (int x = 0; x < 4; x++) S[nt][x] = 0.f;

#pragma unroll
        for (int ks = 0; ks < 4; ks++) {
            uint32_t Qhf[4], Qlf[4];
            ldsm4(Qhf, Qh_s + a_row * AST + ks * 32 + a_cs);
            ldsm4(Qlf, Ql_s + a_row * AST + ks * 32 + a_cs);
#pragma unroll
            for (int p = 0; p < 4; p++) {
                uint32_t Kf[4];
                ldsm4(Kf, Kh_s + (p * 16 + b_row) * AST + ks * 32 + b_cs);
#pragma unroll
                for (int q = 0; q < 2; q++) {
                    mma16816h(S[p * 2 + q], Qhf, &Kf[q * 2]);
                    mma16816h(S[p * 2 + q], Qlf, &Kf[q * 2]);
                }
            }
        }

        const bool diag = (jt == qt);
#pragma unroll
        for (int half = 0; half < 2; half++) {
            const int rloc = wid * 16 + g + half * 8;
            float mt = -1e30f;
#pragma unroll
            for (int nt = 0; nt < 8; nt++) {
                float s0 = S[nt][half * 2], s1 = S[nt][half * 2 + 1];
                if (diag) {
                    if (nt * 8 + t2q > rloc)     s0 = -1e30f;
                    if (nt * 8 + t2q + 1 > rloc) s1 = -1e30f;
                }
                S[nt][half * 2] = s0; S[nt][half * 2 + 1] = s1;
                mt = fmaxf(mt, fmaxf(s0, s1));
            }
            mt = fmaxf(mt, __shfl_xor_sync(0xffffffffu, mt, 1));
            mt = fmaxf(mt, __shfl_xor_sync(0xffffffffu, mt, 2));
            float mn = fmaxf(mrow[half], mt);
            float f = __expf(mrow[half] - mn);
            mrow[half] = mn;
            float rs = 0.f;
#pragma unroll
            for (int nt = 0; nt < 8; nt++) {
                float e0 = __expf(S[nt][half * 2] - mn);
                float e1 = __expf(S[nt][half * 2 + 1] - mn);
                S[nt][half * 2] = e0; S[nt][half * 2 + 1] = e1;
                rs += e0 + e1;
            }
            rs += __shfl_xor_sync(0xffffffffu, rs, 1);
            rs += __shfl_xor_sync(0xffffffffu, rs, 2);
            lrow[half] = lrow[half] * f + rs;
#pragma unroll
            for (int nt = 0; nt < 8; nt++) {
                O[nt][half * 2] *= f; O[nt][half * 2 + 1] *= f;
            }
        }

#pragma unroll
        for (int ks = 0; ks < 4; ks++) {
            uint32_t Ph[4], Pl[4];
#pragma unroll
            for (int q4 = 0; q4 < 4; q4++) {
                int tile = 2 * ks + (q4 >> 1);
                int o = (q4 & 1) * 2;
                float v0 = S[tile][o], v1 = S[tile][o + 1];
                __half h0 = __float2half(v0), h1 = __float2half(v1);
                __half2 hh(h0, h1);
                Ph[q4] = *(uint32_t*)&hh;
                Pl[q4] = packh(v0 - __half2float(h0), v1 - __half2float(h1));
            }
#pragma unroll
            for (int nt = 0; nt < 4; nt++) {
                uint32_t Vf[4];
                ldsm4t(Vf, Vh_s + (ks * 16 + v_row) * AST + nt * 32 + v_cs);
#pragma unroll
                for (int q = 0; q < 2; q++) {
                    mma16816h(O[nt * 2 + q], Ph, &Vf[q * 2]);
                    mma16816h(O[nt * 2 + q], Pl, &Vf[q * 2]);
                }
            }
        }
        __syncthreads();
    }

    float inv[2] = { 1.0f / lrow[0], 1.0f / lrow[1] };
#pragma unroll
    for (int nt = 0; nt < 8; nt++) {
#pragma unroll
        for (int half = 0; half < 2; half++) {
            size_t row = qrow0 + wid * 16 + g + half * 8;
            int col = hcol + nt * 8 + t2q;
            float v0 = O[nt][half * 2] * inv[half];
            float v1 = O[nt][half * 2 + 1] * inv[half];
            __half h0, l0, h1, l1;
            split1h(v0, h0, l0); split1h(v1, h1, l1);
            *(__half2*)&chi[row * DD + col] = __half2(h0, h1);
            *(__half2*)&clo[row * DD + col] = __half2(l0, l1);
        }
    }
}

// ---------------- driver -----------------------------------------------------
extern "C" void kernel_launch(void* const* d_in, const int* in_sizes, int n_in,
                              void* d_out, int out_size) {
    (void)in_sizes; (void)n_in; (void)out_size;
    const float* tok  = (const float*)d_in[1];
    const float* pos  = (const float*)d_in[2];
    const float* bq   = (const float*)d_in[4];
    const float* bk   = (const float*)d_in[6];
    const float* bv   = (const float*)d_in[8];
    const float* bo   = (const float*)d_in[10];
    const float* b1   = (const float*)d_in[12];
    const float* b2   = (const float*)d_in[14];
    const float* ln1g = (const float*)d_in[15];
    const float* ln1b = (const float*)d_in[16];
    const float* ln2g = (const float*)d_in[17];
    const float* ln2b = (const float*)d_in[18];
    const float* lnfg = (const float*)d_in[19];
    const float* lnfb = (const float*)d_in[20];
    float* out = (float*)d_out;

    float *h, *pp;
    cudaGetSymbolAddress((void**)&h,  g_h);
    cudaGetSymbolAddress((void**)&pp, g_p);

    __half *t16, *e16h, *e16l, *w16q, *w16k, *w16v, *w16o, *w16f1, *w16f2;
    __half *q16h, *q16l, *k16, *v16, *a16h, *a16l, *f16h, *f16l;
    cudaGetSymbolAddress((void**)&t16,   g_t16);
    cudaGetSymbolAddress((void**)&e16h,  g_e16h);
    cudaGetSymbolAddress((void**)&e16l,  g_e16l);
    cudaGetSymbolAddress((void**)&w16q,  g_w16q);
    cudaGetSymbolAddress((void**)&w16k,  g_w16k);
    cudaGetSymbolAddress((void**)&w16v,  g_w16v);
    cudaGetSymbolAddress((void**)&w16o,  g_w16o);
    cudaGetSymbolAddress((void**)&w16f1, g_w16f1);
    cudaGetSymbolAddress((void**)&w16f2, g_w16f2);
    cudaGetSymbolAddress((void**)&q16h,  g_q16h);
    cudaGetSymbolAddress((void**)&q16l,  g_q16l);
    cudaGetSymbolAddress((void**)&k16,   g_k16);
    cudaGetSymbolAddress((void**)&v16,   g_v16);
    cudaGetSymbolAddress((void**)&a16h,  g_a16h);
    cudaGetSymbolAddress((void**)&a16l,  g_a16l);
    cudaGetSymbolAddress((void**)&f16h,  g_f16h);
    cudaGetSymbolAddress((void**)&f16l,  g_f16l);

    cudaFuncSetAttribute(qkv16_gemm, cudaFuncAttributeMaxDynamicSharedMemorySize, GSMEM_H);
    cudaFuncSetAttribute(ffn1_gemm,  cudaFuncAttributeMaxDynamicSharedMemorySize, GSMEM_H);
    cudaFuncSetAttribute(hgemm_pk,   cudaFuncAttributeMaxDynamicSharedMemorySize, GSMEM_H);
    cudaFuncSetAttribute(lm_gemm,    cudaFuncAttributeMaxDynamicSharedMemorySize, GSMEM_L1);
    cudaFuncSetAttribute(flash_attn, cudaFuncAttributeMaxDynamicSharedMemorySize, ATT_SMEM16);

    // launch 0: embed
    embedcvt_kernel<<<(MTOK * DD + 255) / 256, 256>>>((const long long*)d_in[0], tok, pos);
    // launch 1: all six layer weight tensors -> fp16
    {
        const int nD4 = LL * DD * DD / 4;
        const int nF4 = LL * FF * DD / 4;
        dim3 gw((nF4 + 255) / 256, 6);
        cvtw6_kernel<<<gw, 256>>>(
            (const float4*)d_in[3],  (__half2*)w16q,  nD4,
            (const float4*)d_in[5],  (__half2*)w16k,  nD4,
            (const float4*)d_in[7],  (__half2*)w16v,  nD4,
            (const float4*)d_in[9],  (__half2*)w16o,  nD4,
            (const float4*)d_in[11], (__half2*)w16f1, nF4,
            (const float4*)d_in[13], (__half2*)w16f2, nF4);
    }

    dim3 gQKV(18, MTOK / 128);           // (18, 16)
    dim3 gPK(DD / 128, MTOK / 128, 3);   // (6, 16, 3)
    dim3 gF(FF / 128, MTOK / 128);       // (24, 16)
    dim3 gV(VV / 128, MTOK / 128);       // (250, 16)
    dim3 gA(SS / 64, HH, BB);            // (16, 12, 2)
    const int gLN = MTOK / 8;

    for (int l = 0; l < LL; l++) {
        const size_t wD = (size_t)l * DD * DD;
        if (l == 0)
            ln16_kernel<<<gLN, 256>>>(h, ln1g, ln1b, e16h, e16l);          // launch 2
        else
            ln_res16_kernel<<<gLN, 256>>>(h, pp, ln1g + l * DD, ln1b + l * DD, e16h, e16l);
        qkv16_gemm<<<gQKV, 256, GSMEM_H>>>(e16h, e16l,                     // launch 3 (l=0) — profiled
                                           w16q + wD, w16k + wD, w16v + wD,
                                           bq + l * DD, bk + l * DD, bv + l * DD,
                                           q16h, q16l, k16, v16);
        flash_attn<<<gA, 128, ATT_SMEM16>>>(q16h, q16l, k16, v16, a16h, a16l);
        hgemm_pk<<<gPK, 256, GSMEM_H>>>(a16h, a16l, w16o + wD, bo + l * DD,
                                        pp, DD, DD, DD / 3);
        ln_res16_kernel<<<gLN, 256>>>(h, pp, ln2g + l * DD, ln2b + l * DD, e16h, e16l);
        ffn1_gemm<<<gF, 256, GSMEM_H>>>(e16h, e16l, w16f1 + (size_t)l * FF * DD,
                                        b1 + l * FF, f16h, f16l, FF, DD);
        hgemm_pk<<<gPK, 256, GSMEM_H>>>(f16h, f16l, w16f2 + (size_t)l * DD * FF,
                                        b2 + l * DD, pp, DD, FF, FF / 3);
    }

    // LM head (1-pass fp16)
    {
        int n4 = VV * DD / 4;
        cvt16_kernel<<<(n4 + 255) / 256, 256>>>((const float4*)tok, (__half2*)t16, n4);
    }
    ln_res16_kernel<<<gLN, 256>>>(h, pp, lnfg, lnfb, e16h, e16l);
    lm_gemm<<<gV, 256, GSMEM_L1>>>(e16h, t16, out, VV, DD);
}